// round 2
// baseline (speedup 1.0000x reference)
#include <cuda_runtime.h>
#include <math.h>

#define Bb 2
#define Ss 2048
#define Dd 1024
#define Hh 16
#define DHh 64
#define DQK 128
#define BQ 64
#define BKT 64
#define QSTR 129
#define PSTR 65
#define INV_SCALE 0.08838834764831845f  // 1/sqrt(128)

// scratch (no cudaMalloc allowed)
__device__ float g_pos_kq[Ss * 2 * Dd];        // [S, 2D]
__device__ float g_tok[Bb * Ss * 3 * Dd];      // [B*S, 3D]
__device__ float g_bias_delta[Hh * 4096];      // [H, delta+2047]

// ---------------------------------------------------------------------------
// T5 relative-position bias, collapsed to a per-head function of delta = k - q
// ---------------------------------------------------------------------------
__global__ void bias_kernel(const float* __restrict__ bias_table) {
    int idx = blockIdx.x * blockDim.x + threadIdx.x;
    if (idx >= Hh * 4096) return;
    int h = idx >> 12;
    int dd = idx & 4095;
    int delta = dd - 2047;         // k - q
    int n = -delta;                // q - k
    int ret = 0;
    if (n < 0) { ret = 16; n = -n; }   // bidirectional: half-buckets = 16
    int bucket;
    if (n < 8) {
        bucket = n;
    } else {
        float v = logf((float)n / 8.0f) / logf(16.0f) * 8.0f;
        int vi = 8 + (int)v;
        bucket = vi < 15 ? vi : 15;
    }
    bucket += ret;
    g_bias_delta[idx] = bias_table[(bucket + 2048) * Hh + h];
}

// ---------------------------------------------------------------------------
// fp32 SGEMM: C[M,N] = A[M,K] @ B[K,N]; M,N % 128 == 0, K % 16 == 0
// 256 threads, 128x128 block tile, 8x8 per-thread microtile
// ---------------------------------------------------------------------------
__global__ void __launch_bounds__(256) sgemm_kernel(
    const float* __restrict__ A, const float* __restrict__ Bm,
    float* __restrict__ C, int M, int N, int K)
{
    __shared__ float As[16][128];   // transposed A tile
    __shared__ float Bs[16][128];
    const int tid = threadIdx.x;
    const int row0 = blockIdx.y * 128;
    const int col0 = blockIdx.x * 128;
    const int ty = tid >> 4, tx = tid & 15;
    float acc[8][8] = {};

    for (int k0 = 0; k0 < K; k0 += 16) {
#pragma unroll
        for (int t = 0; t < 2; t++) {
            int idx = tid + t * 256;
            int r = idx >> 2, c4 = (idx & 3) << 2;
            float4 av = *(const float4*)&A[(size_t)(row0 + r) * K + k0 + c4];
            As[c4 + 0][r] = av.x; As[c4 + 1][r] = av.y;
            As[c4 + 2][r] = av.z; As[c4 + 3][r] = av.w;
            int rb = idx >> 5, cb4 = (idx & 31) << 2;
            *(float4*)&Bs[rb][cb4] =
                *(const float4*)&Bm[(size_t)(k0 + rb) * N + col0 + cb4];
        }
        __syncthreads();
#pragma unroll
        for (int kk = 0; kk < 16; kk++) {
            float a[8], b[8];
            *(float4*)&a[0] = *(const float4*)&As[kk][ty * 8];
            *(float4*)&a[4] = *(const float4*)&As[kk][ty * 8 + 4];
            *(float4*)&b[0] = *(const float4*)&Bs[kk][tx * 8];
            *(float4*)&b[4] = *(const float4*)&Bs[kk][tx * 8 + 4];
#pragma unroll
            for (int i = 0; i < 8; i++)
#pragma unroll
                for (int j = 0; j < 8; j++)
                    acc[i][j] += a[i] * b[j];
        }
        __syncthreads();
    }
#pragma unroll
    for (int i = 0; i < 8; i++) {
        float* cp = &C[(size_t)(row0 + ty * 8 + i) * N + col0 + tx * 8];
        *(float4*)cp       = make_float4(acc[i][0], acc[i][1], acc[i][2], acc[i][3]);
        *(float4*)(cp + 4) = make_float4(acc[i][4], acc[i][5], acc[i][6], acc[i][7]);
    }
}

// ---------------------------------------------------------------------------
// Flash attention: combined 128-dim QK (tok||pos), 64-dim V, online softmax.
// One block per (q-tile 64, head, batch). 256 threads = 16x16 grid, 4x4 tiles.
// ---------------------------------------------------------------------------
constexpr int SM_K = BQ * QSTR;
constexpr int SM_V = SM_K + BKT * QSTR;
constexpr int SM_P = SM_V + BKT * DHh;
constexpr int SMEM_FLOATS = SM_P + BKT * PSTR;
constexpr int SMEM_BYTES = SMEM_FLOATS * 4;

__global__ void __launch_bounds__(256) attn_kernel(
    const float* __restrict__ tok, const float* __restrict__ pos,
    const float* __restrict__ biasd, float* __restrict__ out)
{
    extern __shared__ float sm[];
    float* Qs = sm;           // [BQ][QSTR]
    float* Ks = sm + SM_K;    // [BKT][QSTR]
    float* Vs = sm + SM_V;    // [BKT][64]
    float* Ps = sm + SM_P;    // [BKT][PSTR] transposed P

    const int b = blockIdx.z, h = blockIdx.y;
    const int q0 = blockIdx.x * BQ;
    const int tid = threadIdx.x;
    const int ty = tid >> 4, tx = tid & 15;
    const float* bd = biasd + h * 4096;

    // Load Q tile: dims 0..63 = tok_query, 64..127 = pos_query
#pragma unroll
    for (int t = 0; t < 8; t++) {
        int idx = tid + t * 256;
        int r = idx >> 5, part = idx & 31;
        const float* src = (part < 16)
            ? &tok[(size_t)(b * Ss + q0 + r) * 3072 + 1024 + h * 64 + part * 4]
            : &pos[(size_t)(q0 + r) * 2048 + 1024 + h * 64 + (part - 16) * 4];
        float4 v = *(const float4*)src;
        float* dst = &Qs[r * QSTR + part * 4];
        dst[0] = v.x; dst[1] = v.y; dst[2] = v.z; dst[3] = v.w;
    }

    float m_i[4], l_i[4] = {0.f, 0.f, 0.f, 0.f};
    float o[4][4] = {};
    m_i[0] = m_i[1] = m_i[2] = m_i[3] = -INFINITY;

    for (int k0 = 0; k0 < Ss; k0 += BKT) {
        __syncthreads();
        // Load K tile (tok_key || pos_key)
#pragma unroll
        for (int t = 0; t < 8; t++) {
            int idx = tid + t * 256;
            int r = idx >> 5, part = idx & 31;
            const float* src = (part < 16)
                ? &tok[(size_t)(b * Ss + k0 + r) * 3072 + h * 64 + part * 4]
                : &pos[(size_t)(k0 + r) * 2048 + h * 64 + (part - 16) * 4];
            float4 v = *(const float4*)src;
            float* dst = &Ks[r * QSTR + part * 4];
            dst[0] = v.x; dst[1] = v.y; dst[2] = v.z; dst[3] = v.w;
        }
        // Load V tile
#pragma unroll
        for (int t = 0; t < 4; t++) {
            int idx = tid + t * 256;
            int r = idx >> 4, part = idx & 15;
            *(float4*)&Vs[r * 64 + part * 4] =
                *(const float4*)&tok[(size_t)(b * Ss + k0 + r) * 3072 + 2048 + h * 64 + part * 4];
        }
        __syncthreads();

        // S = Qc Kc^T over 128 dims
        float s[4][4] = {};
#pragma unroll 4
        for (int d = 0; d < DQK; d++) {
            float qr[4], kr[4];
#pragma unroll
            for (int i = 0; i < 4; i++) qr[i] = Qs[(ty * 4 + i) * QSTR + d];
#pragma unroll
            for (int j = 0; j < 4; j++) kr[j] = Ks[(tx * 4 + j) * QSTR + d];
#pragma unroll
            for (int i = 0; i < 4; i++)
#pragma unroll
                for (int j = 0; j < 4; j++)
                    s[i][j] += qr[i] * kr[j];
        }

        // scale + relative-position bias
        const int dbase = (k0 - q0) + 2047 + tx * 4 - ty * 4;
#pragma unroll
        for (int i = 0; i < 4; i++)
#pragma unroll
            for (int j = 0; j < 4; j++)
                s[i][j] = s[i][j] * INV_SCALE + bd[dbase + j - i];

        // online softmax (row reduce over 16 lanes of tx)
#pragma unroll
        for (int i = 0; i < 4; i++) {
            float mt = fmaxf(fmaxf(s[i][0], s[i][1]), fmaxf(s[i][2], s[i][3]));
#pragma unroll
            for (int off = 8; off; off >>= 1)
                mt = fmaxf(mt, __shfl_xor_sync(0xffffffffu, mt, off));
            float mnew = fmaxf(m_i[i], mt);
            float corr = expf(m_i[i] - mnew);
            float rs = 0.f;
#pragma unroll
            for (int j = 0; j < 4; j++) {
                float p = expf(s[i][j] - mnew);
                s[i][j] = p;
                rs += p;
            }
#pragma unroll
            for (int off = 8; off; off >>= 1)
                rs += __shfl_xor_sync(0xffffffffu, rs, off);
            l_i[i] = l_i[i] * corr + rs;
            m_i[i] = mnew;
#pragma unroll
            for (int j = 0; j < 4; j++) o[i][j] *= corr;
#pragma unroll
            for (int j = 0; j < 4; j++)
                Ps[(tx * 4 + j) * PSTR + ty * 4 + i] = s[i][j];
        }
        __syncthreads();

        // O += P @ V
#pragma unroll 2
        for (int kk = 0; kk < BKT; kk++) {
            float4 v = *(const float4*)&Vs[kk * 64 + tx * 4];
#pragma unroll
            for (int i = 0; i < 4; i++) {
                float p = Ps[kk * PSTR + ty * 4 + i];
                o[i][0] += p * v.x; o[i][1] += p * v.y;
                o[i][2] += p * v.z; o[i][3] += p * v.w;
            }
        }
    }

    // normalize + store: out[b, q, h*64 + dh]
#pragma unroll
    for (int i = 0; i < 4; i++) {
        float inv = 1.0f / l_i[i];
        float4 r = make_float4(o[i][0] * inv, o[i][1] * inv, o[i][2] * inv, o[i][3] * inv);
        *(float4*)&out[(size_t)(b * Ss + q0 + ty * 4 + i) * 1024 + h * 64 + tx * 4] = r;
    }
}

// ---------------------------------------------------------------------------
extern "C" void kernel_launch(void* const* d_in, const int* in_sizes, int n_in,
                              void* d_out, int out_size)
{
    const float* x          = (const float*)d_in[0];
    const float* pos_embed  = (const float*)d_in[1];
    const float* W_pos_kq   = (const float*)d_in[2];
    const float* W_tok_kqv  = (const float*)d_in[3];
    const float* bias_table = (const float*)d_in[4];
    float* out = (float*)d_out;

    float *pos_kq, *tok, *biasd;
    cudaGetSymbolAddress((void**)&pos_kq, g_pos_kq);
    cudaGetSymbolAddress((void**)&tok, g_tok);
    cudaGetSymbolAddress((void**)&biasd, g_bias_delta);

    cudaFuncSetAttribute(attn_kernel,
                         cudaFuncAttributeMaxDynamicSharedMemorySize, SMEM_BYTES);

    bias_kernel<<<(Hh * 4096) / 256, 256>>>(bias_table);
    // pos_kq = pos_embed[2048,1024] @ W_pos_kq[1024,2048]
    sgemm_kernel<<<dim3(2048 / 128, 2048 / 128), 256>>>(pos_embed, W_pos_kq, pos_kq,
                                                        2048, 2048, 1024);
    // tok = x[4096,1024] @ W_tok_kqv[1024,3072]
    sgemm_kernel<<<dim3(3072 / 128, 4096 / 128), 256>>>(x, W_tok_kqv, tok,
                                                        4096, 3072, 1024);
    attn_kernel<<<dim3(Ss / BQ, Hh, Bb), 256, SMEM_BYTES>>>(tok, pos_kq, biasd, out);
}

// round 3
// speedup vs baseline: 2.5942x; 2.5942x over previous
#include <cuda_runtime.h>
#include <cuda_fp16.h>
#include <math.h>
#include <stdint.h>

#define INV_SCALE 0.08838834764831845f  // 1/sqrt(128)

// ------------------------- static scratch (no cudaMalloc) -------------------
__device__ float  g_bias[16 * 4096];
__device__ float  g_tok[4096UL * 3072];     // [B*S][3D]
__device__ float  g_pos[2048UL * 2048];     // [S][2D]
__device__ __half g_xh[4096UL * 1024],  g_xl[4096UL * 1024];
__device__ __half g_peh[2048UL * 1024], g_pel[2048UL * 1024];
__device__ __half g_wth[3072UL * 1024], g_wtl[3072UL * 1024];  // W_tok^T
__device__ __half g_wph[2048UL * 1024], g_wpl[2048UL * 1024];  // W_pos^T
__device__ __half g_qh[32UL * 2048 * 128], g_ql[32UL * 2048 * 128];
__device__ __half g_kh[32UL * 2048 * 128], g_kl[32UL * 2048 * 128];
__device__ __half g_vh[32UL * 64 * 2048],  g_vl[32UL * 64 * 2048]; // V^T per z

// ---------------------------------------------------------------------------
__device__ __forceinline__ void mma16816(float c[4], const uint32_t a[4],
                                         const uint32_t b[2]) {
    asm volatile(
        "mma.sync.aligned.m16n8k16.row.col.f32.f16.f16.f32 "
        "{%0,%1,%2,%3}, {%4,%5,%6,%7}, {%8,%9}, {%0,%1,%2,%3};\n"
        : "+f"(c[0]), "+f"(c[1]), "+f"(c[2]), "+f"(c[3])
        : "r"(a[0]), "r"(a[1]), "r"(a[2]), "r"(a[3]), "r"(b[0]), "r"(b[1]));
}
// A fragment, row-major m16k16 tile at s (row stride = str halves)
__device__ __forceinline__ void ldA(uint32_t a[4], const __half* s, int str) {
    int l = threadIdx.x & 31, r = l >> 2, c = (l & 3) * 2;
    a[0] = *(const uint32_t*)(s + r * str + c);
    a[1] = *(const uint32_t*)(s + (r + 8) * str + c);
    a[2] = *(const uint32_t*)(s + r * str + c + 8);
    a[3] = *(const uint32_t*)(s + (r + 8) * str + c + 8);
}
// B fragment, n8k16 from [n][k] layout (k contiguous)
__device__ __forceinline__ void ldB(uint32_t b[2], const __half* s, int str) {
    int l = threadIdx.x & 31, n = l >> 2, c = (l & 3) * 2;
    b[0] = *(const uint32_t*)(s + n * str + c);
    b[1] = *(const uint32_t*)(s + n * str + c + 8);
}
__device__ __forceinline__ void split1(float v, __half& h, __half& l) {
    h = __float2half_rn(v);
    l = __float2half_rn(v - __half2float(h));
}

// ---------------------------------------------------------------------------
// T5 bias LUT: g_bias[h][delta + 2047], delta = k - q
// ---------------------------------------------------------------------------
__global__ void bias_kernel(const float* __restrict__ bias_table) {
    int idx = blockIdx.x * blockDim.x + threadIdx.x;
    if (idx >= 16 * 4096) return;
    int h = idx >> 12, dd = idx & 4095;
    int n = -(dd - 2047);
    int ret = 0;
    if (n < 0) { ret = 16; n = -n; }
    int bucket;
    if (n < 8) bucket = n;
    else {
        float v = logf((float)n / 8.0f) / logf(16.0f) * 8.0f;
        int vi = 8 + (int)v;
        bucket = vi < 15 ? vi : 15;
    }
    g_bias[idx] = bias_table[(bucket + ret + 2048) * 16 + h];
}

// ---------------------------------------------------------------------------
// pack fp32 -> (hi, lo) fp16, elementwise, float4-vectorized
// ---------------------------------------------------------------------------
__global__ void pack_split4(const float* __restrict__ src, __half* __restrict__ hi,
                            __half* __restrict__ lo, int n4) {
    int i = blockIdx.x * blockDim.x + threadIdx.x;
    if (i >= n4) return;
    float4 v = ((const float4*)src)[i];
    __half h0, h1, h2, h3, l0, l1, l2, l3;
    split1(v.x, h0, l0); split1(v.y, h1, l1);
    split1(v.z, h2, l2); split1(v.w, h3, l3);
    ((__half2*)hi)[2 * i]     = __halves2half2(h0, h1);
    ((__half2*)hi)[2 * i + 1] = __halves2half2(h2, h3);
    ((__half2*)lo)[2 * i]     = __halves2half2(l0, l1);
    ((__half2*)lo)[2 * i + 1] = __halves2half2(l2, l3);
}
// pack + transpose: src [K=1024][N] -> dst [N][1024]
__global__ void pack_splitT(const float* __restrict__ src, __half* __restrict__ hi,
                            __half* __restrict__ lo, int N) {
    int i = blockIdx.x * blockDim.x + threadIdx.x;  // i = n*1024 + k
    if (i >= N * 1024) return;
    int n = i >> 10, k = i & 1023;
    __half h, l;
    split1(src[(size_t)k * N + n], h, l);
    hi[i] = h; lo[i] = l;
}

// ---------------------------------------------------------------------------
// build Q/K (tok||pos, 128-dim) and V^T, split fp16
// ---------------------------------------------------------------------------
__global__ void pack_qk(const float* __restrict__ tok, const float* __restrict__ pos) {
    int i = blockIdx.x * blockDim.x + threadIdx.x;  // z*2048*32 + s*32 + d4
    if (i >= 32 * 2048 * 32) return;
    int d = (i & 31) * 4, s = (i >> 5) & 2047, z = i >> 16;
    int b = z >> 4, h = z & 15;
    const float* qsrc;
    const float* ksrc;
    if (d < 64) {
        qsrc = &tok[(size_t)(b * 2048 + s) * 3072 + 1024 + h * 64 + d];
        ksrc = &tok[(size_t)(b * 2048 + s) * 3072 + h * 64 + d];
    } else {
        qsrc = &pos[(size_t)s * 2048 + 1024 + h * 64 + (d - 64)];
        ksrc = &pos[(size_t)s * 2048 + h * 64 + (d - 64)];
    }
    float4 qv = *(const float4*)qsrc;
    float4 kv = *(const float4*)ksrc;
    size_t o = ((size_t)z * 2048 + s) * 128 + d;
    __half h0, h1, h2, h3, l0, l1, l2, l3;
    split1(qv.x, h0, l0); split1(qv.y, h1, l1); split1(qv.z, h2, l2); split1(qv.w, h3, l3);
    *(__half2*)&g_qh[o] = __halves2half2(h0, h1); *(__half2*)&g_qh[o + 2] = __halves2half2(h2, h3);
    *(__half2*)&g_ql[o] = __halves2half2(l0, l1); *(__half2*)&g_ql[o + 2] = __halves2half2(l2, l3);
    split1(kv.x, h0, l0); split1(kv.y, h1, l1); split1(kv.z, h2, l2); split1(kv.w, h3, l3);
    *(__half2*)&g_kh[o] = __halves2half2(h0, h1); *(__half2*)&g_kh[o + 2] = __halves2half2(h2, h3);
    *(__half2*)&g_kl[o] = __halves2half2(l0, l1); *(__half2*)&g_kl[o + 2] = __halves2half2(l2, l3);
}
__global__ void pack_v(const float* __restrict__ tok) {
    int i = blockIdx.x * blockDim.x + threadIdx.x;  // z*64*512 + dh*512 + s4
    if (i >= 32 * 64 * 512) return;
    int s = (i & 511) * 4, dh = (i >> 9) & 63, z = i >> 15;
    int b = z >> 4, h = z & 15;
    size_t o = ((size_t)z * 64 + dh) * 2048 + s;
#pragma unroll
    for (int t = 0; t < 4; t++) {
        float v = tok[(size_t)(b * 2048 + s + t) * 3072 + 2048 + h * 64 + dh];
        __half hv, lv;
        split1(v, hv, lv);
        g_vh[o + t] = hv; g_vl[o + t] = lv;
    }
}

// ---------------------------------------------------------------------------
// split-fp16 GEMM: C[M][N] = A[M][K] @ B[K][N], operands pre-split,
// B pre-transposed to [N][K]. 128x128 tile, 8 warps (2x4), warp 64x32.
// ---------------------------------------------------------------------------
__global__ void __launch_bounds__(256) hgemm_split(
    const __half* __restrict__ Ah, const __half* __restrict__ Al,
    const __half* __restrict__ Bh, const __half* __restrict__ Bl,
    float* __restrict__ C, int M, int N, int K)
{
    __shared__ __half sAh[128][24], sAl[128][24], sBh[128][24], sBl[128][24];
    const int tid = threadIdx.x, wid = tid >> 5, lane = tid & 31;
    const int wm = wid & 1, wn = wid >> 1;
    const int bm = blockIdx.y * 128, bn = blockIdx.x * 128;
    const int lr = tid >> 1, lc = (tid & 1) * 8;
    const __half* pAh = Ah + (size_t)(bm + lr) * K + lc;
    const __half* pAl = Al + (size_t)(bm + lr) * K + lc;
    const __half* pBh = Bh + (size_t)(bn + lr) * K + lc;
    const __half* pBl = Bl + (size_t)(bn + lr) * K + lc;
    float acc[4][4][4] = {};
    uint4 rah = *(const uint4*)pAh, ral = *(const uint4*)pAl;
    uint4 rbh = *(const uint4*)pBh, rbl = *(const uint4*)pBl;
    for (int k0 = 0; k0 < K; k0 += 16) {
        *(uint4*)&sAh[lr][lc] = rah; *(uint4*)&sAl[lr][lc] = ral;
        *(uint4*)&sBh[lr][lc] = rbh; *(uint4*)&sBl[lr][lc] = rbl;
        __syncthreads();
        if (k0 + 16 < K) {
            rah = *(const uint4*)(pAh + k0 + 16); ral = *(const uint4*)(pAl + k0 + 16);
            rbh = *(const uint4*)(pBh + k0 + 16); rbl = *(const uint4*)(pBl + k0 + 16);
        }
        uint32_t afh[4][4], afl[4][4], bfh[4][2], bfl[4][2];
#pragma unroll
        for (int i = 0; i < 4; i++) {
            ldA(afh[i], &sAh[wm * 64 + i * 16][0], 24);
            ldA(afl[i], &sAl[wm * 64 + i * 16][0], 24);
        }
#pragma unroll
        for (int j = 0; j < 4; j++) {
            ldB(bfh[j], &sBh[wn * 32 + j * 8][0], 24);
            ldB(bfl[j], &sBl[wn * 32 + j * 8][0], 24);
        }
#pragma unroll
        for (int i = 0; i < 4; i++)
#pragma unroll
            for (int j = 0; j < 4; j++) {
                mma16816(acc[i][j], afh[i], bfh[j]);
                mma16816(acc[i][j], afh[i], bfl[j]);
                mma16816(acc[i][j], afl[i], bfh[j]);
            }
        __syncthreads();
    }
#pragma unroll
    for (int i = 0; i < 4; i++)
#pragma unroll
        for (int j = 0; j < 4; j++) {
            int r = bm + wm * 64 + i * 16 + (lane >> 2);
            int c = bn + wn * 32 + j * 8 + (lane & 3) * 2;
            *(float2*)&C[(size_t)r * N + c] = make_float2(acc[i][j][0], acc[i][j][1]);
            *(float2*)&C[(size_t)(r + 8) * N + c] = make_float2(acc[i][j][2], acc[i][j][3]);
        }
}

// ---------------------------------------------------------------------------
// fused flash attention, tensor cores, split precision
// block = (q-tile 128, z), 8 warps; warp owns 16 q-rows x all 64 keys/iter
// ---------------------------------------------------------------------------
#define QSTR 136
#define VSTR 72
constexpr int SM_QH = 0;
constexpr int SM_QL = SM_QH + 128 * QSTR;
constexpr int SM_KH = SM_QL + 128 * QSTR;
constexpr int SM_KL = SM_KH + 64 * QSTR;
constexpr int SM_VH = SM_KL + 64 * QSTR;
constexpr int SM_VL = SM_VH + 64 * VSTR;
constexpr int ATT_SMEM = (SM_VL + 64 * VSTR) * 2;  // bytes = 122880

__global__ void __launch_bounds__(256) attn_kernel(
    const __half* __restrict__ qh, const __half* __restrict__ ql,
    const __half* __restrict__ kh, const __half* __restrict__ kl,
    const __half* __restrict__ vh, const __half* __restrict__ vl,
    const float* __restrict__ biasd, float* __restrict__ out)
{
    extern __shared__ __half sm[];
    __half* sQh = sm + SM_QH; __half* sQl = sm + SM_QL;
    __half* sKh = sm + SM_KH; __half* sKl = sm + SM_KL;
    __half* sVh = sm + SM_VH; __half* sVl = sm + SM_VL;
    const int z = blockIdx.y, b = z >> 4, h = z & 15;
    const int q0 = blockIdx.x * 128;
    const int tid = threadIdx.x, wid = tid >> 5, lane = tid & 31;
    const int lr4 = lane >> 2, lc2 = (lane & 3) * 2;
    const float* bd = biasd + h * 4096;
    const size_t zq = (size_t)z * 2048 * 128;
    const size_t zv = (size_t)z * 64 * 2048;
    const int mrow = wid * 16;

#pragma unroll
    for (int t = 0; t < 8; t++) {
        int i = tid + t * 256, r = i >> 4, c8 = (i & 15) * 8;
        *(uint4*)&sQh[r * QSTR + c8] = *(const uint4*)&qh[zq + (size_t)(q0 + r) * 128 + c8];
        *(uint4*)&sQl[r * QSTR + c8] = *(const uint4*)&ql[zq + (size_t)(q0 + r) * 128 + c8];
    }

    float m0 = -INFINITY, m1 = -INFINITY, L0 = 0.f, L1 = 0.f;
    float of[8][4] = {};

    for (int k0 = 0; k0 < 2048; k0 += 64) {
        __syncthreads();
#pragma unroll
        for (int t = 0; t < 4; t++) {
            int i = tid + t * 256, r = i >> 4, c8 = (i & 15) * 8;
            *(uint4*)&sKh[r * QSTR + c8] = *(const uint4*)&kh[zq + (size_t)(k0 + r) * 128 + c8];
            *(uint4*)&sKl[r * QSTR + c8] = *(const uint4*)&kl[zq + (size_t)(k0 + r) * 128 + c8];
        }
#pragma unroll
        for (int t = 0; t < 2; t++) {
            int i = tid + t * 256, d = i >> 3, c8 = (i & 7) * 8;
            *(uint4*)&sVh[d * VSTR + c8] = *(const uint4*)&vh[zv + (size_t)d * 2048 + k0 + c8];
            *(uint4*)&sVl[d * VSTR + c8] = *(const uint4*)&vl[zv + (size_t)d * 2048 + k0 + c8];
        }
        __syncthreads();

        // S = Q K^T (128-dim, 3-term split)
        float sf[8][4] = {};
#pragma unroll
        for (int kd = 0; kd < 8; kd++) {
            uint32_t ah[4], al[4];
            ldA(ah, sQh + mrow * QSTR + kd * 16, QSTR);
            ldA(al, sQl + mrow * QSTR + kd * 16, QSTR);
#pragma unroll
            for (int nf = 0; nf < 8; nf++) {
                uint32_t bh2[2], bl2[2];
                ldB(bh2, sKh + (nf * 8) * QSTR + kd * 16, QSTR);
                ldB(bl2, sKl + (nf * 8) * QSTR + kd * 16, QSTR);
                mma16816(sf[nf], ah, bh2);
                mma16816(sf[nf], ah, bl2);
                mma16816(sf[nf], al, bh2);
            }
        }

        // scale + bias + online softmax
        const int r0 = q0 + mrow + lr4;
        float lm0 = -INFINITY, lm1 = -INFINITY;
#pragma unroll
        for (int nf = 0; nf < 8; nf++) {
            int c = k0 + nf * 8 + lc2;
            sf[nf][0] = sf[nf][0] * INV_SCALE + bd[c - r0 + 2047];
            sf[nf][1] = sf[nf][1] * INV_SCALE + bd[c + 1 - r0 + 2047];
            sf[nf][2] = sf[nf][2] * INV_SCALE + bd[c - (r0 + 8) + 2047];
            sf[nf][3] = sf[nf][3] * INV_SCALE + bd[c + 1 - (r0 + 8) + 2047];
            lm0 = fmaxf(lm0, fmaxf(sf[nf][0], sf[nf][1]));
            lm1 = fmaxf(lm1, fmaxf(sf[nf][2], sf[nf][3]));
        }
        lm0 = fmaxf(lm0, __shfl_xor_sync(0xffffffffu, lm0, 1));
        lm0 = fmaxf(lm0, __shfl_xor_sync(0xffffffffu, lm0, 2));
        lm1 = fmaxf(lm1, __shfl_xor_sync(0xffffffffu, lm1, 1));
        lm1 = fmaxf(lm1, __shfl_xor_sync(0xffffffffu, lm1, 2));
        float mn0 = fmaxf(m0, lm0), mn1 = fmaxf(m1, lm1);
        float corr0 = __expf(m0 - mn0), corr1 = __expf(m1 - mn1);
        float rs0 = 0.f, rs1 = 0.f;
        uint32_t ap[4][4];
#pragma unroll
        for (int nf = 0; nf < 8; nf++) {
            float p0 = __expf(sf[nf][0] - mn0), p1 = __expf(sf[nf][1] - mn0);
            float p2 = __expf(sf[nf][2] - mn1), p3 = __expf(sf[nf][3] - mn1);
            rs0 += p0 + p1; rs1 += p2 + p3;
            __half2 h01 = __floats2half2_rn(p0, p1);
            __half2 h23 = __floats2half2_rn(p2, p3);
            int kf = nf >> 1, off = (nf & 1) * 2;
            ap[kf][off] = *(uint32_t*)&h01;
            ap[kf][off + 1] = *(uint32_t*)&h23;
        }
        rs0 += __shfl_xor_sync(0xffffffffu, rs0, 1);
        rs0 += __shfl_xor_sync(0xffffffffu, rs0, 2);
        rs1 += __shfl_xor_sync(0xffffffffu, rs1, 1);
        rs1 += __shfl_xor_sync(0xffffffffu, rs1, 2);
        L0 = L0 * corr0 + rs0;
        L1 = L1 * corr1 + rs1;
        m0 = mn0; m1 = mn1;
#pragma unroll
        for (int nf = 0; nf < 8; nf++) {
            of[nf][0] *= corr0; of[nf][1] *= corr0;
            of[nf][2] *= corr1; of[nf][3] *= corr1;
        }
        // O += P V (2-term split on V)
#pragma unroll
        for (int kf = 0; kf < 4; kf++)
#pragma unroll
            for (int nf = 0; nf < 8; nf++) {
                uint32_t bh2[2], bl2[2];
                ldB(bh2, sVh + (nf * 8) * VSTR + kf * 16, VSTR);
                ldB(bl2, sVl + (nf * 8) * VSTR + kf * 16, VSTR);
                mma16816(of[nf], ap[kf], bh2);
                mma16816(of[nf], ap[kf], bl2);
            }
    }

    float inv0 = 1.f / L0, inv1 = 1.f / L1;
    const int r0 = q0 + mrow + lr4;
    const size_t ob = (size_t)b * 2048 * 1024 + h * 64;
#pragma unroll
    for (int nf = 0; nf < 8; nf++) {
        int c = nf * 8 + lc2;
        *(float2*)&out[ob + (size_t)r0 * 1024 + c] =
            make_float2(of[nf][0] * inv0, of[nf][1] * inv0);
        *(float2*)&out[ob + (size_t)(r0 + 8) * 1024 + c] =
            make_float2(of[nf][2] * inv1, of[nf][3] * inv1);
    }
}

// ---------------------------------------------------------------------------
extern "C" void kernel_launch(void* const* d_in, const int* in_sizes, int n_in,
                              void* d_out, int out_size)
{
    const float* x          = (const float*)d_in[0];
    const float* pos_embed  = (const float*)d_in[1];
    const float* W_pos_kq   = (const float*)d_in[2];
    const float* W_tok_kqv  = (const float*)d_in[3];
    const float* bias_table = (const float*)d_in[4];
    float* out = (float*)d_out;

    float *tok, *pos, *biasd;
    __half *xh, *xl, *peh, *pel, *wth, *wtl, *wph, *wpl;
    __half *qh, *ql, *kh, *kl, *vh, *vl;
    cudaGetSymbolAddress((void**)&tok, g_tok);
    cudaGetSymbolAddress((void**)&pos, g_pos);
    cudaGetSymbolAddress((void**)&biasd, g_bias);
    cudaGetSymbolAddress((void**)&xh, g_xh);   cudaGetSymbolAddress((void**)&xl, g_xl);
    cudaGetSymbolAddress((void**)&peh, g_peh); cudaGetSymbolAddress((void**)&pel, g_pel);
    cudaGetSymbolAddress((void**)&wth, g_wth); cudaGetSymbolAddress((void**)&wtl, g_wtl);
    cudaGetSymbolAddress((void**)&wph, g_wph); cudaGetSymbolAddress((void**)&wpl, g_wpl);
    cudaGetSymbolAddress((void**)&qh, g_qh);   cudaGetSymbolAddress((void**)&ql, g_ql);
    cudaGetSymbolAddress((void**)&kh, g_kh);   cudaGetSymbolAddress((void**)&kl, g_kl);
    cudaGetSymbolAddress((void**)&vh, g_vh);   cudaGetSymbolAddress((void**)&vl, g_vl);

    cudaFuncSetAttribute(attn_kernel,
                         cudaFuncAttributeMaxDynamicSharedMemorySize, ATT_SMEM);

    bias_kernel<<<256, 256>>>(bias_table);
    pack_split4<<<(4096 * 1024 / 4 + 255) / 256, 256>>>(x, xh, xl, 4096 * 1024 / 4);
    pack_split4<<<(2048 * 1024 / 4 + 255) / 256, 256>>>(pos_embed, peh, pel, 2048 * 1024 / 4);
    pack_splitT<<<(3072 * 1024 + 255) / 256, 256>>>(W_tok_kqv, wth, wtl, 3072);
    pack_splitT<<<(2048 * 1024 + 255) / 256, 256>>>(W_pos_kq, wph, wpl, 2048);

    hgemm_split<<<dim3(3072 / 128, 4096 / 128), 256>>>(xh, xl, wth, wtl, tok,
                                                       4096, 3072, 1024);
    hgemm_split<<<dim3(2048 / 128, 2048 / 128), 256>>>(peh, pel, wph, wpl, pos,
                                                       2048, 2048, 1024);

    pack_qk<<<(32 * 2048 * 32 + 255) / 256, 256>>>(tok, pos);
    pack_v<<<(32 * 64 * 512 + 255) / 256, 256>>>(tok);

    attn_kernel<<<dim3(16, 32), 256, ATT_SMEM>>>(qh, ql, kh, kl, vh, vl, biasd, out);
}

// round 4
// speedup vs baseline: 2.7736x; 1.0692x over previous
#include <cuda_runtime.h>
#include <cuda_fp16.h>
#include <math.h>
#include <stdint.h>

#define INV_SCALE 0.08838834764831845f  // 1/sqrt(128)

// ------------------------- static scratch (no cudaMalloc) -------------------
__device__ float  g_bias[16 * 4096];
__device__ float  g_tok[4096UL * 3072];     // [B*S][3D]
__device__ float  g_pos[2048UL * 2048];     // [S][2D]
__device__ __half g_xh[4096UL * 1024],  g_xl[4096UL * 1024];
__device__ __half g_peh[2048UL * 1024], g_pel[2048UL * 1024];
__device__ __half g_wth[3072UL * 1024], g_wtl[3072UL * 1024];  // W_tok^T
__device__ __half g_wph[2048UL * 1024], g_wpl[2048UL * 1024];  // W_pos^T
__device__ __half g_qh[32UL * 2048 * 128], g_ql[32UL * 2048 * 128];
__device__ __half g_kh[32UL * 2048 * 128], g_kl[32UL * 2048 * 128];
__device__ __half g_vh[32UL * 64 * 2048],  g_vl[32UL * 64 * 2048]; // V^T per z

// ---------------------------------------------------------------------------
__device__ __forceinline__ void mma16816(float c[4], const uint32_t a[4],
                                         const uint32_t b[2]) {
    asm volatile(
        "mma.sync.aligned.m16n8k16.row.col.f32.f16.f16.f32 "
        "{%0,%1,%2,%3}, {%4,%5,%6,%7}, {%8,%9}, {%0,%1,%2,%3};\n"
        : "+f"(c[0]), "+f"(c[1]), "+f"(c[2]), "+f"(c[3])
        : "r"(a[0]), "r"(a[1]), "r"(a[2]), "r"(a[3]), "r"(b[0]), "r"(b[1]));
}
__device__ __forceinline__ uint32_t sptr(const void* p) {
    return (uint32_t)__cvta_generic_to_shared(p);
}
__device__ __forceinline__ void ldsm4(uint32_t r[4], const __half* p) {
    asm volatile("ldmatrix.sync.aligned.m8n8.x4.shared.b16 {%0,%1,%2,%3}, [%4];\n"
                 : "=r"(r[0]), "=r"(r[1]), "=r"(r[2]), "=r"(r[3]) : "r"(sptr(p)));
}
__device__ __forceinline__ void cpa16(__half* dst, const __half* src) {
    asm volatile("cp.async.cg.shared.global [%0], [%1], 16;\n"
                 :: "r"(sptr(dst)), "l"(src));
}
#define CP_COMMIT() asm volatile("cp.async.commit_group;\n")
__device__ __forceinline__ void split1(float v, __half& h, __half& l) {
    h = __float2half_rn(v);
    l = __float2half_rn(v - __half2float(h));
}

// ---------------------------------------------------------------------------
// T5 bias LUT: g_bias[h][delta + 2047], delta = k - q
// ---------------------------------------------------------------------------
__global__ void bias_kernel(const float* __restrict__ bias_table) {
    int idx = blockIdx.x * blockDim.x + threadIdx.x;
    if (idx >= 16 * 4096) return;
    int h = idx >> 12, dd = idx & 4095;
    int n = -(dd - 2047);
    int ret = 0;
    if (n < 0) { ret = 16; n = -n; }
    int bucket;
    if (n < 8) bucket = n;
    else {
        float v = logf((float)n / 8.0f) / logf(16.0f) * 8.0f;
        int vi = 8 + (int)v;
        bucket = vi < 15 ? vi : 15;
    }
    g_bias[idx] = bias_table[(bucket + ret + 2048) * 16 + h];
}

// ---------------------------------------------------------------------------
// pack fp32 -> (hi, lo) fp16, elementwise, float4-vectorized
// ---------------------------------------------------------------------------
__global__ void pack_split4(const float* __restrict__ src, __half* __restrict__ hi,
                            __half* __restrict__ lo, int n4) {
    int i = blockIdx.x * blockDim.x + threadIdx.x;
    if (i >= n4) return;
    float4 v = ((const float4*)src)[i];
    __half h0, h1, h2, h3, l0, l1, l2, l3;
    split1(v.x, h0, l0); split1(v.y, h1, l1);
    split1(v.z, h2, l2); split1(v.w, h3, l3);
    ((__half2*)hi)[2 * i]     = __halves2half2(h0, h1);
    ((__half2*)hi)[2 * i + 1] = __halves2half2(h2, h3);
    ((__half2*)lo)[2 * i]     = __halves2half2(l0, l1);
    ((__half2*)lo)[2 * i + 1] = __halves2half2(l2, l3);
}
// pack + transpose via 32x32 smem tile: src [1024][N] -> dst [N][1024]
__global__ void __launch_bounds__(256) pack_splitT(
    const float* __restrict__ src, __half* __restrict__ hi,
    __half* __restrict__ lo, int N) {
    __shared__ float tile[32][33];
    int n0 = blockIdx.x * 32, k0 = blockIdx.y * 32;
    int tx = threadIdx.x, ty = threadIdx.y;
#pragma unroll
    for (int t = 0; t < 4; t++)
        tile[ty + t * 8][tx] = src[(size_t)(k0 + ty + t * 8) * N + n0 + tx];
    __syncthreads();
#pragma unroll
    for (int t = 0; t < 4; t++) {
        int n = n0 + ty + t * 8;
        float v = tile[tx][ty + t * 8];
        __half h, l;
        split1(v, h, l);
        hi[(size_t)n * 1024 + k0 + tx] = h;
        lo[(size_t)n * 1024 + k0 + tx] = l;
    }
}

// ---------------------------------------------------------------------------
// build Q/K (tok||pos, 128-dim) and V^T, split fp16
// ---------------------------------------------------------------------------
__global__ void pack_qk(const float* __restrict__ tok, const float* __restrict__ pos) {
    int i = blockIdx.x * blockDim.x + threadIdx.x;
    if (i >= 32 * 2048 * 32) return;
    int d = (i & 31) * 4, s = (i >> 5) & 2047, z = i >> 16;
    int b = z >> 4, h = z & 15;
    const float* qsrc;
    const float* ksrc;
    if (d < 64) {
        qsrc = &tok[(size_t)(b * 2048 + s) * 3072 + 1024 + h * 64 + d];
        ksrc = &tok[(size_t)(b * 2048 + s) * 3072 + h * 64 + d];
    } else {
        qsrc = &pos[(size_t)s * 2048 + 1024 + h * 64 + (d - 64)];
        ksrc = &pos[(size_t)s * 2048 + h * 64 + (d - 64)];
    }
    float4 qv = *(const float4*)qsrc;
    float4 kv = *(const float4*)ksrc;
    size_t o = ((size_t)z * 2048 + s) * 128 + d;
    __half h0, h1, h2, h3, l0, l1, l2, l3;
    split1(qv.x, h0, l0); split1(qv.y, h1, l1); split1(qv.z, h2, l2); split1(qv.w, h3, l3);
    *(__half2*)&g_qh[o] = __halves2half2(h0, h1); *(__half2*)&g_qh[o + 2] = __halves2half2(h2, h3);
    *(__half2*)&g_ql[o] = __halves2half2(l0, l1); *(__half2*)&g_ql[o + 2] = __halves2half2(l2, l3);
    split1(kv.x, h0, l0); split1(kv.y, h1, l1); split1(kv.z, h2, l2); split1(kv.w, h3, l3);
    *(__half2*)&g_kh[o] = __halves2half2(h0, h1); *(__half2*)&g_kh[o + 2] = __halves2half2(h2, h3);
    *(__half2*)&g_kl[o] = __halves2half2(l0, l1); *(__half2*)&g_kl[o + 2] = __halves2half2(l2, l3);
}
__global__ void pack_v(const float* __restrict__ tok) {
    int i = blockIdx.x * blockDim.x + threadIdx.x;
    if (i >= 32 * 64 * 512) return;
    int s = (i & 511) * 4, dh = (i >> 9) & 63, z = i >> 15;
    int b = z >> 4, h = z & 15;
    size_t o = ((size_t)z * 64 + dh) * 2048 + s;
#pragma unroll
    for (int t = 0; t < 4; t++) {
        float v = tok[(size_t)(b * 2048 + s + t) * 3072 + 2048 + h * 64 + dh];
        __half hv, lv;
        split1(v, hv, lv);
        g_vh[o + t] = hv; g_vl[o + t] = lv;
    }
}

// ---------------------------------------------------------------------------
// split-fp16 GEMM: C[M][N] = A[M][K] @ B^T (B given as [N][K]).
// 128x128 tile, 8 warps (2x4), warp 64x32, k-step 16, ldmatrix fragments.
// ---------------------------------------------------------------------------
__global__ void __launch_bounds__(256) hgemm_split(
    const __half* __restrict__ Ah, const __half* __restrict__ Al,
    const __half* __restrict__ Bh, const __half* __restrict__ Bl,
    float* __restrict__ C, int M, int N, int K)
{
    __shared__ __half sAh[128][24], sAl[128][24], sBh[128][24], sBl[128][24];
    const int tid = threadIdx.x, wid = tid >> 5, lane = tid & 31;
    const int wm = wid & 1, wn = wid >> 1;
    const int bm = blockIdx.y * 128, bn = blockIdx.x * 128;
    const int lr = tid >> 1, lc = (tid & 1) * 8;
    const __half* pAh = Ah + (size_t)(bm + lr) * K + lc;
    const __half* pAl = Al + (size_t)(bm + lr) * K + lc;
    const __half* pBh = Bh + (size_t)(bn + lr) * K + lc;
    const __half* pBl = Bl + (size_t)(bn + lr) * K + lc;
    const int aoff = (lane & 15) * 24 + (lane >> 4) * 8;
    const int boff = ((lane & 7) + ((lane >> 4) << 3)) * 24 + ((lane >> 3) & 1) * 8;
    float acc[4][4][4] = {};
    uint4 rah = *(const uint4*)pAh, ral = *(const uint4*)pAl;
    uint4 rbh = *(const uint4*)pBh, rbl = *(const uint4*)pBl;
    for (int k0 = 0; k0 < K; k0 += 16) {
        *(uint4*)&sAh[lr][lc] = rah; *(uint4*)&sAl[lr][lc] = ral;
        *(uint4*)&sBh[lr][lc] = rbh; *(uint4*)&sBl[lr][lc] = rbl;
        __syncthreads();
        if (k0 + 16 < K) {
            rah = *(const uint4*)(pAh + k0 + 16); ral = *(const uint4*)(pAl + k0 + 16);
            rbh = *(const uint4*)(pBh + k0 + 16); rbl = *(const uint4*)(pBl + k0 + 16);
        }
        uint32_t afh[4][4], afl[4][4], bfh[4][2], bfl[4][2];
#pragma unroll
        for (int i = 0; i < 4; i++) {
            ldsm4(afh[i], &sAh[wm * 64 + i * 16][0] + aoff);
            ldsm4(afl[i], &sAl[wm * 64 + i * 16][0] + aoff);
        }
#pragma unroll
        for (int j2 = 0; j2 < 2; j2++) {
            uint32_t t4[4];
            ldsm4(t4, &sBh[wn * 32 + j2 * 16][0] + boff);
            bfh[2 * j2][0] = t4[0]; bfh[2 * j2][1] = t4[1];
            bfh[2 * j2 + 1][0] = t4[2]; bfh[2 * j2 + 1][1] = t4[3];
            ldsm4(t4, &sBl[wn * 32 + j2 * 16][0] + boff);
            bfl[2 * j2][0] = t4[0]; bfl[2 * j2][1] = t4[1];
            bfl[2 * j2 + 1][0] = t4[2]; bfl[2 * j2 + 1][1] = t4[3];
        }
#pragma unroll
        for (int i = 0; i < 4; i++)
#pragma unroll
            for (int j = 0; j < 4; j++) {
                mma16816(acc[i][j], afh[i], bfh[j]);
                mma16816(acc[i][j], afh[i], bfl[j]);
                mma16816(acc[i][j], afl[i], bfh[j]);
            }
        __syncthreads();
    }
#pragma unroll
    for (int i = 0; i < 4; i++)
#pragma unroll
        for (int j = 0; j < 4; j++) {
            int r = bm + wm * 64 + i * 16 + (lane >> 2);
            int c = bn + wn * 32 + j * 8 + (lane & 3) * 2;
            *(float2*)&C[(size_t)r * N + c] = make_float2(acc[i][j][0], acc[i][j][1]);
            *(float2*)&C[(size_t)(r + 8) * N + c] = make_float2(acc[i][j][2], acc[i][j][3]);
        }
}

// ---------------------------------------------------------------------------
// fused flash attention: ldmatrix fragments + cp.async double-buffered K/V
// block = (q-tile 128, z), 8 warps; warp owns 16 q-rows x 64 keys/iter
// ---------------------------------------------------------------------------
#define QSTR 136
#define VSTR 72
constexpr int O_QH = 0;
constexpr int O_QL = 128 * QSTR;            // 17408
constexpr int O_K  = 2 * 128 * QSTR;        // 34816
constexpr int KHL  = 64 * QSTR;             // 8704
constexpr int KBUF = 2 * KHL;               // 17408
constexpr int O_V  = O_K + 2 * KBUF;        // 69632
constexpr int VHL  = 64 * VSTR;             // 4608
constexpr int VBUF = 2 * VHL;               // 9216
constexpr int ATT_SMEM = (O_V + 2 * VBUF) * 2;  // 176128 bytes

__global__ void __launch_bounds__(256) attn_kernel(
    const __half* __restrict__ qh, const __half* __restrict__ ql,
    const __half* __restrict__ kh, const __half* __restrict__ kl,
    const __half* __restrict__ vh, const __half* __restrict__ vl,
    const float* __restrict__ biasd, float* __restrict__ out)
{
    extern __shared__ __half smh[];
    const int z = blockIdx.y, b = z >> 4, h = z & 15;
    const int q0 = blockIdx.x * 128;
    const int tid = threadIdx.x, wid = tid >> 5, lane = tid & 31;
    const int lr4 = lane >> 2, lc2 = (lane & 3) * 2;
    const float* bd = biasd + h * 4096;
    const size_t zq = (size_t)z * 2048 * 128;
    const size_t zv = (size_t)z * 64 * 2048;
    const int mrow = wid * 16;
    const int aoffQ = (lane & 15) * QSTR + (lane >> 4) * 8;
    const int boffK = ((lane & 7) + ((lane >> 4) << 3)) * QSTR + ((lane >> 3) & 1) * 8;
    const int boffV = ((lane & 7) + ((lane >> 4) << 3)) * VSTR + ((lane >> 3) & 1) * 8;

    // Q via cp.async (part of group 0)
#pragma unroll
    for (int t = 0; t < 8; t++) {
        int i = tid + t * 256, r = i >> 4, c = (i & 15) * 8;
        cpa16(smh + O_QH + r * QSTR + c, qh + zq + (size_t)(q0 + r) * 128 + c);
        cpa16(smh + O_QL + r * QSTR + c, ql + zq + (size_t)(q0 + r) * 128 + c);
    }
    // K/V tile 0 into buf 0 (same group)
    {
        __half* bKh = smh + O_K; __half* bKl = bKh + KHL;
        __half* bVh = smh + O_V; __half* bVl = bVh + VHL;
#pragma unroll
        for (int t = 0; t < 4; t++) {
            int i = tid + t * 256, r = i >> 4, c = (i & 15) * 8;
            cpa16(bKh + r * QSTR + c, kh + zq + (size_t)r * 128 + c);
            cpa16(bKl + r * QSTR + c, kl + zq + (size_t)r * 128 + c);
        }
#pragma unroll
        for (int t = 0; t < 2; t++) {
            int i = tid + t * 256, d = i >> 3, c = (i & 7) * 8;
            cpa16(bVh + d * VSTR + c, vh + zv + (size_t)d * 2048 + c);
            cpa16(bVl + d * VSTR + c, vl + zv + (size_t)d * 2048 + c);
        }
    }
    CP_COMMIT();

    float m0 = -INFINITY, m1 = -INFINITY, L0 = 0.f, L1 = 0.f;
    float of[8][4] = {};

    for (int it = 0; it < 32; it++) {
        const int k0 = it * 64, buf = it & 1;
        if (it + 1 < 32) {
            // prefetch next tile into the other buffer
            __half* nKh = smh + O_K + (buf ^ 1) * KBUF; __half* nKl = nKh + KHL;
            __half* nVh = smh + O_V + (buf ^ 1) * VBUF; __half* nVl = nVh + VHL;
            const int nk0 = k0 + 64;
#pragma unroll
            for (int t = 0; t < 4; t++) {
                int i = tid + t * 256, r = i >> 4, c = (i & 15) * 8;
                cpa16(nKh + r * QSTR + c, kh + zq + (size_t)(nk0 + r) * 128 + c);
                cpa16(nKl + r * QSTR + c, kl + zq + (size_t)(nk0 + r) * 128 + c);
            }
#pragma unroll
            for (int t = 0; t < 2; t++) {
                int i = tid + t * 256, d = i >> 3, c = (i & 7) * 8;
                cpa16(nVh + d * VSTR + c, vh + zv + (size_t)d * 2048 + nk0 + c);
                cpa16(nVl + d * VSTR + c, vl + zv + (size_t)d * 2048 + nk0 + c);
            }
            CP_COMMIT();
            asm volatile("cp.async.wait_group 1;\n");
        } else {
            asm volatile("cp.async.wait_group 0;\n");
        }
        __syncthreads();

        __half* bKh = smh + O_K + buf * KBUF; __half* bKl = bKh + KHL;
        __half* bVh = smh + O_V + buf * VBUF; __half* bVl = bVh + VHL;

        // S = Q K^T (128-dim, 3-term split)
        float sf[8][4] = {};
#pragma unroll
        for (int kd = 0; kd < 8; kd++) {
            uint32_t ah[4], al[4];
            ldsm4(ah, smh + O_QH + mrow * QSTR + kd * 16 + aoffQ);
            ldsm4(al, smh + O_QL + mrow * QSTR + kd * 16 + aoffQ);
#pragma unroll
            for (int np = 0; np < 4; np++) {
                uint32_t b4h[4], b4l[4];
                ldsm4(b4h, bKh + (np * 16) * QSTR + kd * 16 + boffK);
                ldsm4(b4l, bKl + (np * 16) * QSTR + kd * 16 + boffK);
                mma16816(sf[2 * np],     ah, b4h);
                mma16816(sf[2 * np],     ah, b4l);
                mma16816(sf[2 * np],     al, b4h);
                mma16816(sf[2 * np + 1], ah, b4h + 2);
                mma16816(sf[2 * np + 1], ah, b4l + 2);
                mma16816(sf[2 * np + 1], al, b4h + 2);
            }
        }

        // scale + bias + online softmax
        const int r0 = q0 + mrow + lr4;
        float lm0 = -INFINITY, lm1 = -INFINITY;
#pragma unroll
        for (int nf = 0; nf < 8; nf++) {
            int c = k0 + nf * 8 + lc2;
            sf[nf][0] = sf[nf][0] * INV_SCALE + bd[c - r0 + 2047];
            sf[nf][1] = sf[nf][1] * INV_SCALE + bd[c + 1 - r0 + 2047];
            sf[nf][2] = sf[nf][2] * INV_SCALE + bd[c - (r0 + 8) + 2047];
            sf[nf][3] = sf[nf][3] * INV_SCALE + bd[c + 1 - (r0 + 8) + 2047];
            lm0 = fmaxf(lm0, fmaxf(sf[nf][0], sf[nf][1]));
            lm1 = fmaxf(lm1, fmaxf(sf[nf][2], sf[nf][3]));
        }
        lm0 = fmaxf(lm0, __shfl_xor_sync(0xffffffffu, lm0, 1));
        lm0 = fmaxf(lm0, __shfl_xor_sync(0xffffffffu, lm0, 2));
        lm1 = fmaxf(lm1, __shfl_xor_sync(0xffffffffu, lm1, 1));
        lm1 = fmaxf(lm1, __shfl_xor_sync(0xffffffffu, lm1, 2));
        float mn0 = fmaxf(m0, lm0), mn1 = fmaxf(m1, lm1);
        float corr0 = __expf(m0 - mn0), corr1 = __expf(m1 - mn1);
        float rs0 = 0.f, rs1 = 0.f;
        uint32_t ap[4][4];
#pragma unroll
        for (int nf = 0; nf < 8; nf++) {
            float p0 = __expf(sf[nf][0] - mn0), p1 = __expf(sf[nf][1] - mn0);
            float p2 = __expf(sf[nf][2] - mn1), p3 = __expf(sf[nf][3] - mn1);
            rs0 += p0 + p1; rs1 += p2 + p3;
            __half2 h01 = __floats2half2_rn(p0, p1);
            __half2 h23 = __floats2half2_rn(p2, p3);
            int kf = nf >> 1, off = (nf & 1) * 2;
            ap[kf][off] = *(uint32_t*)&h01;
            ap[kf][off + 1] = *(uint32_t*)&h23;
        }
        rs0 += __shfl_xor_sync(0xffffffffu, rs0, 1);
        rs0 += __shfl_xor_sync(0xffffffffu, rs0, 2);
        rs1 += __shfl_xor_sync(0xffffffffu, rs1, 1);
        rs1 += __shfl_xor_sync(0xffffffffu, rs1, 2);
        L0 = L0 * corr0 + rs0;
        L1 = L1 * corr1 + rs1;
        m0 = mn0; m1 = mn1;
#pragma unroll
        for (int nf = 0; nf < 8; nf++) {
            of[nf][0] *= corr0; of[nf][1] *= corr0;
            of[nf][2] *= corr1; of[nf][3] *= corr1;
        }
        // O += P V (2-term split on V)
#pragma unroll
        for (int kf = 0; kf < 4; kf++)
#pragma unroll
            for (int np = 0; np < 4; np++) {
                uint32_t b4h[4], b4l[4];
                ldsm4(b4h, bVh + (np * 16) * VSTR + kf * 16 + boffV);
                ldsm4(b4l, bVl + (np * 16) * VSTR + kf * 16 + boffV);
                mma16816(of[2 * np],     ap[kf], b4h);
                mma16816(of[2 * np],     ap[kf], b4l);
                mma16816(of[2 * np + 1], ap[kf], b4h + 2);
                mma16816(of[2 * np + 1], ap[kf], b4l + 2);
            }
        __syncthreads();   // buffer reuse fence for next iteration's prefetch
    }

    float inv0 = 1.f / L0, inv1 = 1.f / L1;
    const int r0 = q0 + mrow + lr4;
    const size_t ob = (size_t)b * 2048 * 1024 + h * 64;
#pragma unroll
    for (int nf = 0; nf < 8; nf++) {
        int c = nf * 8 + lc2;
        *(float2*)&out[ob + (size_t)r0 * 1024 + c] =
            make_float2(of[nf][0] * inv0, of[nf][1] * inv0);
        *(float2*)&out[ob + (size_t)(r0 + 8) * 1024 + c] =
            make_float2(of[nf][2] * inv1, of[nf][3] * inv1);
    }
}

// ---------------------------------------------------------------------------
extern "C" void kernel_launch(void* const* d_in, const int* in_sizes, int n_in,
                              void* d_out, int out_size)
{
    const float* x          = (const float*)d_in[0];
    const float* pos_embed  = (const float*)d_in[1];
    const float* W_pos_kq   = (const float*)d_in[2];
    const float* W_tok_kqv  = (const float*)d_in[3];
    const float* bias_table = (const float*)d_in[4];
    float* out = (float*)d_out;

    float *tok, *pos, *biasd;
    __half *xh, *xl, *peh, *pel, *wth, *wtl, *wph, *wpl;
    __half *qh, *ql, *kh, *kl, *vh, *vl;
    cudaGetSymbolAddress((void**)&tok, g_tok);
    cudaGetSymbolAddress((void**)&pos, g_pos);
    cudaGetSymbolAddress((void**)&biasd, g_bias);
    cudaGetSymbolAddress((void**)&xh, g_xh);   cudaGetSymbolAddress((void**)&xl, g_xl);
    cudaGetSymbolAddress((void**)&peh, g_peh); cudaGetSymbolAddress((void**)&pel, g_pel);
    cudaGetSymbolAddress((void**)&wth, g_wth); cudaGetSymbolAddress((void**)&wtl, g_wtl);
    cudaGetSymbolAddress((void**)&wph, g_wph); cudaGetSymbolAddress((void**)&wpl, g_wpl);
    cudaGetSymbolAddress((void**)&qh, g_qh);   cudaGetSymbolAddress((void**)&ql, g_ql);
    cudaGetSymbolAddress((void**)&kh, g_kh);   cudaGetSymbolAddress((void**)&kl, g_kl);
    cudaGetSymbolAddress((void**)&vh, g_vh);   cudaGetSymbolAddress((void**)&vl, g_vl);

    cudaFuncSetAttribute(attn_kernel,
                         cudaFuncAttributeMaxDynamicSharedMemorySize, ATT_SMEM);

    bias_kernel<<<256, 256>>>(bias_table);
    pack_split4<<<(4096 * 1024 / 4 + 255) / 256, 256>>>(x, xh, xl, 4096 * 1024 / 4);
    pack_split4<<<(2048 * 1024 / 4 + 255) / 256, 256>>>(pos_embed, peh, pel, 2048 * 1024 / 4);
    pack_splitT<<<dim3(3072 / 32, 1024 / 32), dim3(32, 8)>>>(W_tok_kqv, wth, wtl, 3072);
    pack_splitT<<<dim3(2048 / 32, 1024 / 32), dim3(32, 8)>>>(W_pos_kq, wph, wpl, 2048);

    hgemm_split<<<dim3(3072 / 128, 4096 / 128), 256>>>(xh, xl, wth, wtl, tok,
                                                       4096, 3072, 1024);
    hgemm_split<<<dim3(2048 / 128, 2048 / 128), 256>>>(peh, pel, wph, wpl, pos,
                                                       2048, 2048, 1024);

    pack_qk<<<(32 * 2048 * 32 + 255) / 256, 256>>>(tok, pos);
    pack_v<<<(32 * 64 * 512 + 255) / 256, 256>>>(tok);

    attn_kernel<<<dim3(16, 32), 256, ATT_SMEM>>>(qh, ql, kh, kl, vh, vl, biasd, out);
}

// round 5
// speedup vs baseline: 3.6564x; 1.3183x over previous
#include <cuda_runtime.h>
#include <cuda_fp16.h>
#include <math.h>
#include <stdint.h>

#define INV_SCALE 0.08838834764831845f  // 1/sqrt(128)

// ------------------------- static scratch (no cudaMalloc) -------------------
__device__ float  g_bias[16 * 4096];
__device__ float  g_tok[4096UL * 3072];     // [B*S][3D]
__device__ float  g_pos[2048UL * 2048];     // [S][2D]
__device__ __half g_xh[4096UL * 1024],  g_xl[4096UL * 1024];
__device__ __half g_peh[2048UL * 1024], g_pel[2048UL * 1024];
__device__ __half g_wth[3072UL * 1024], g_wtl[3072UL * 1024];  // W_tok^T
__device__ __half g_wph[2048UL * 1024], g_wpl[2048UL * 1024];  // W_pos^T
__device__ __half g_qh[32UL * 2048 * 128], g_ql[32UL * 2048 * 128];
__device__ __half g_kh[32UL * 2048 * 128];
__device__ __half g_vh[32UL * 64 * 2048],  g_vl[32UL * 64 * 2048]; // V^T per z

// ---------------------------------------------------------------------------
__device__ __forceinline__ void mma16816(float c[4], const uint32_t a[4],
                                         const uint32_t b[2]) {
    asm volatile(
        "mma.sync.aligned.m16n8k16.row.col.f32.f16.f16.f32 "
        "{%0,%1,%2,%3}, {%4,%5,%6,%7}, {%8,%9}, {%0,%1,%2,%3};\n"
        : "+f"(c[0]), "+f"(c[1]), "+f"(c[2]), "+f"(c[3])
        : "r"(a[0]), "r"(a[1]), "r"(a[2]), "r"(a[3]), "r"(b[0]), "r"(b[1]));
}
__device__ __forceinline__ uint32_t sptr(const void* p) {
    return (uint32_t)__cvta_generic_to_shared(p);
}
__device__ __forceinline__ void ldsm4(uint32_t r[4], const __half* p) {
    asm volatile("ldmatrix.sync.aligned.m8n8.x4.shared.b16 {%0,%1,%2,%3}, [%4];\n"
                 : "=r"(r[0]), "=r"(r[1]), "=r"(r[2]), "=r"(r[3]) : "r"(sptr(p)));
}
__device__ __forceinline__ void cpa16(__half* dst, const __half* src) {
    asm volatile("cp.async.cg.shared.global [%0], [%1], 16;\n"
                 :: "r"(sptr(dst)), "l"(src));
}
#define CP_COMMIT() asm volatile("cp.async.commit_group;\n")
#define CP_WAIT1() asm volatile("cp.async.wait_group 1;\n")
#define CP_WAIT0() asm volatile("cp.async.wait_group 0;\n")
__device__ __forceinline__ void split1(float v, __half& h, __half& l) {
    h = __float2half_rn(v);
    l = __float2half_rn(v - __half2float(h));
}

// ---------------------------------------------------------------------------
// T5 bias LUT: g_bias[h][delta + 2047], delta = k - q
// ---------------------------------------------------------------------------
__global__ void bias_kernel(const float* __restrict__ bias_table) {
    int idx = blockIdx.x * blockDim.x + threadIdx.x;
    if (idx >= 16 * 4096) return;
    int h = idx >> 12, dd = idx & 4095;
    int n = -(dd - 2047);
    int ret = 0;
    if (n < 0) { ret = 16; n = -n; }
    int bucket;
    if (n < 8) bucket = n;
    else {
        float v = logf((float)n / 8.0f) / logf(16.0f) * 8.0f;
        int vi = 8 + (int)v;
        bucket = vi < 15 ? vi : 15;
    }
    g_bias[idx] = bias_table[(bucket + ret + 2048) * 16 + h];
}

// ---------------------------------------------------------------------------
// pack fp32 -> (hi, lo) fp16, elementwise, float4-vectorized
// ---------------------------------------------------------------------------
__global__ void pack_split4(const float* __restrict__ src, __half* __restrict__ hi,
                            __half* __restrict__ lo, int n4) {
    int i = blockIdx.x * blockDim.x + threadIdx.x;
    if (i >= n4) return;
    float4 v = ((const float4*)src)[i];
    __half h0, h1, h2, h3, l0, l1, l2, l3;
    split1(v.x, h0, l0); split1(v.y, h1, l1);
    split1(v.z, h2, l2); split1(v.w, h3, l3);
    ((__half2*)hi)[2 * i]     = __halves2half2(h0, h1);
    ((__half2*)hi)[2 * i + 1] = __halves2half2(h2, h3);
    ((__half2*)lo)[2 * i]     = __halves2half2(l0, l1);
    ((__half2*)lo)[2 * i + 1] = __halves2half2(l2, l3);
}
// pack + transpose via 32x32 smem tile: src [1024][N] -> dst [N][1024]
__global__ void __launch_bounds__(256) pack_splitT(
    const float* __restrict__ src, __half* __restrict__ hi,
    __half* __restrict__ lo, int N) {
    __shared__ float tile[32][33];
    int n0 = blockIdx.x * 32, k0 = blockIdx.y * 32;
    int tx = threadIdx.x, ty = threadIdx.y;
#pragma unroll
    for (int t = 0; t < 4; t++)
        tile[ty + t * 8][tx] = src[(size_t)(k0 + ty + t * 8) * N + n0 + tx];
    __syncthreads();
#pragma unroll
    for (int t = 0; t < 4; t++) {
        int n = n0 + ty + t * 8;
        float v = tile[tx][ty + t * 8];
        __half h, l;
        split1(v, h, l);
        hi[(size_t)n * 1024 + k0 + tx] = h;
        lo[(size_t)n * 1024 + k0 + tx] = l;
    }
}

// ---------------------------------------------------------------------------
// build Q (split) / K (hi only) 128-dim and V^T (split)
// ---------------------------------------------------------------------------
__global__ void pack_qk(const float* __restrict__ tok, const float* __restrict__ pos) {
    int i = blockIdx.x * blockDim.x + threadIdx.x;
    if (i >= 32 * 2048 * 32) return;
    int d = (i & 31) * 4, s = (i >> 5) & 2047, z = i >> 16;
    int b = z >> 4, h = z & 15;
    const float* qsrc;
    const float* ksrc;
    if (d < 64) {
        qsrc = &tok[(size_t)(b * 2048 + s) * 3072 + 1024 + h * 64 + d];
        ksrc = &tok[(size_t)(b * 2048 + s) * 3072 + h * 64 + d];
    } else {
        qsrc = &pos[(size_t)s * 2048 + 1024 + h * 64 + (d - 64)];
        ksrc = &pos[(size_t)s * 2048 + h * 64 + (d - 64)];
    }
    float4 qv = *(const float4*)qsrc;
    float4 kv = *(const float4*)ksrc;
    size_t o = ((size_t)z * 2048 + s) * 128 + d;
    __half h0, h1, h2, h3, l0, l1, l2, l3;
    split1(qv.x, h0, l0); split1(qv.y, h1, l1); split1(qv.z, h2, l2); split1(qv.w, h3, l3);
    *(__half2*)&g_qh[o] = __halves2half2(h0, h1); *(__half2*)&g_qh[o + 2] = __halves2half2(h2, h3);
    *(__half2*)&g_ql[o] = __halves2half2(l0, l1); *(__half2*)&g_ql[o + 2] = __halves2half2(l2, l3);
    *(__half2*)&g_kh[o]     = __floats2half2_rn(kv.x, kv.y);
    *(__half2*)&g_kh[o + 2] = __floats2half2_rn(kv.z, kv.w);
}
__global__ void pack_v(const float* __restrict__ tok) {
    int i = blockIdx.x * blockDim.x + threadIdx.x;
    if (i >= 32 * 64 * 512) return;
    int s = (i & 511) * 4, dh = (i >> 9) & 63, z = i >> 15;
    int b = z >> 4, h = z & 15;
    size_t o = ((size_t)z * 64 + dh) * 2048 + s;
#pragma unroll
    for (int t = 0; t < 4; t++) {
        float v = tok[(size_t)(b * 2048 + s + t) * 3072 + 2048 + h * 64 + dh];
        __half hv, lv;
        split1(v, hv, lv);
        g_vh[o + t] = hv; g_vl[o + t] = lv;
    }
}

// ---------------------------------------------------------------------------
// split-fp16 GEMM: C[M][N] = A[M][K] @ B^T (B given as [N][K]).
// 128x128 tile, 8 warps, 3-stage cp.async pipeline, 1 sync per k-step.
// ---------------------------------------------------------------------------
constexpr int HG_STG = 128 * 24;            // halves per array per stage
constexpr int HG_STAGE = 4 * HG_STG;        // Ah, Al, Bh, Bl
constexpr int HG_SMEM = 3 * HG_STAGE * 2;   // bytes = 73728

__global__ void __launch_bounds__(256) hgemm_split(
    const __half* __restrict__ Ah, const __half* __restrict__ Al,
    const __half* __restrict__ Bh, const __half* __restrict__ Bl,
    float* __restrict__ C, int M, int N, int K)
{
    extern __shared__ __half smg[];
    const int tid = threadIdx.x, wid = tid >> 5, lane = tid & 31;
    const int wm = wid & 1, wn = wid >> 1;
    const int bm = blockIdx.y * 128, bn = blockIdx.x * 128;
    const int lr = tid >> 1, lc = (tid & 1) * 8;
    const __half* pAh = Ah + (size_t)(bm + lr) * K + lc;
    const __half* pAl = Al + (size_t)(bm + lr) * K + lc;
    const __half* pBh = Bh + (size_t)(bn + lr) * K + lc;
    const __half* pBl = Bl + (size_t)(bn + lr) * K + lc;
    const int soff = lr * 24 + lc;
    const int aoff = (lane & 15) * 24 + (lane >> 4) * 8;
    const int boff = ((lane & 7) + ((lane >> 4) << 3)) * 24 + ((lane >> 3) & 1) * 8;
    const int NK = K / 16;
    float acc[4][4][4] = {};

#pragma unroll
    for (int s = 0; s < 2; s++) {
        __half* st = smg + s * HG_STAGE;
        cpa16(st + soff, pAh + s * 16);
        cpa16(st + HG_STG + soff, pAl + s * 16);
        cpa16(st + 2 * HG_STG + soff, pBh + s * 16);
        cpa16(st + 3 * HG_STG + soff, pBl + s * 16);
        CP_COMMIT();
    }
    CP_WAIT1();
    __syncthreads();

    for (int kt = 0; kt < NK; kt++) {
        const __half* st = smg + (kt % 3) * HG_STAGE;
        uint32_t afh[4][4], afl[4][4], bfh[4][2], bfl[4][2];
#pragma unroll
        for (int i = 0; i < 4; i++) {
            ldsm4(afh[i], st + (wm * 64 + i * 16) * 24 + aoff);
            ldsm4(afl[i], st + HG_STG + (wm * 64 + i * 16) * 24 + aoff);
        }
#pragma unroll
        for (int j2 = 0; j2 < 2; j2++) {
            uint32_t t4[4];
            ldsm4(t4, st + 2 * HG_STG + (wn * 32 + j2 * 16) * 24 + boff);
            bfh[2 * j2][0] = t4[0]; bfh[2 * j2][1] = t4[1];
            bfh[2 * j2 + 1][0] = t4[2]; bfh[2 * j2 + 1][1] = t4[3];
            ldsm4(t4, st + 3 * HG_STG + (wn * 32 + j2 * 16) * 24 + boff);
            bfl[2 * j2][0] = t4[0]; bfl[2 * j2][1] = t4[1];
            bfl[2 * j2 + 1][0] = t4[2]; bfl[2 * j2 + 1][1] = t4[3];
        }
#pragma unroll
        for (int i = 0; i < 4; i++)
#pragma unroll
            for (int j = 0; j < 4; j++) {
                mma16816(acc[i][j], afh[i], bfh[j]);
                mma16816(acc[i][j], afh[i], bfl[j]);
                mma16816(acc[i][j], afl[i], bfh[j]);
            }
        if (kt + 2 < NK) {
            __half* nt = smg + ((kt + 2) % 3) * HG_STAGE;
            int ko = (kt + 2) * 16;
            cpa16(nt + soff, pAh + ko);
            cpa16(nt + HG_STG + soff, pAl + ko);
            cpa16(nt + 2 * HG_STG + soff, pBh + ko);
            cpa16(nt + 3 * HG_STG + soff, pBl + ko);
            CP_COMMIT();
            CP_WAIT1();
        } else {
            CP_WAIT0();
        }
        __syncthreads();
    }
#pragma unroll
    for (int i = 0; i < 4; i++)
#pragma unroll
        for (int j = 0; j < 4; j++) {
            int r = bm + wm * 64 + i * 16 + (lane >> 2);
            int c = bn + wn * 32 + j * 8 + (lane & 3) * 2;
            *(float2*)&C[(size_t)r * N + c] = make_float2(acc[i][j][0], acc[i][j][1]);
            *(float2*)&C[(size_t)(r + 8) * N + c] = make_float2(acc[i][j][2], acc[i][j][3]);
        }
}

// ---------------------------------------------------------------------------
// fused flash attention: 2-term QK (Qhi+Qlo vs Khi), split-V PV,
// Q fragments hoisted to registers, 3-stage cp.async K/V, 1 sync/iter.
// block = (q-tile 128, z), 8 warps.
// ---------------------------------------------------------------------------
#define QSTR 136
#define VSTR 72
constexpr int O_QH = 0;
constexpr int O_QL = 128 * QSTR;                 // 17408
constexpr int O_K  = 2 * 128 * QSTR;             // 34816
constexpr int KHL  = 64 * QSTR;                  // 8704 (hi only)
constexpr int O_V  = O_K + 3 * KHL;              // 60928
constexpr int VHL  = 64 * VSTR;                  // 4608
constexpr int VSTG = 2 * VHL;                    // 9216 (hi+lo)
constexpr int ATT_SMEM = (O_V + 3 * VSTG) * 2;   // 177152 bytes

__global__ void __launch_bounds__(256) attn_kernel(
    const __half* __restrict__ qh, const __half* __restrict__ ql,
    const __half* __restrict__ kh,
    const __half* __restrict__ vh, const __half* __restrict__ vl,
    const float* __restrict__ biasd, float* __restrict__ out)
{
    extern __shared__ __half smh[];
    const int z = blockIdx.y, b = z >> 4, h = z & 15;
    const int q0 = blockIdx.x * 128;
    const int tid = threadIdx.x, wid = tid >> 5, lane = tid & 31;
    const int lr4 = lane >> 2, lc2 = (lane & 3) * 2;
    const float* bd = biasd + h * 4096;
    const size_t zq = (size_t)z * 2048 * 128;
    const size_t zv = (size_t)z * 64 * 2048;
    const int mrow = wid * 16;
    const int aoffQ = (lane & 15) * QSTR + (lane >> 4) * 8;
    const int boffK = ((lane & 7) + ((lane >> 4) << 3)) * QSTR + ((lane >> 3) & 1) * 8;
    const int boffV = ((lane & 7) + ((lane >> 4) << 3)) * VSTR + ((lane >> 3) & 1) * 8;

    // group 0: Q (hi+lo) + K tile0 + V tile0
#pragma unroll
    for (int t = 0; t < 8; t++) {
        int i = tid + t * 256, r = i >> 4, c = (i & 15) * 8;
        cpa16(smh + O_QH + r * QSTR + c, qh + zq + (size_t)(q0 + r) * 128 + c);
        cpa16(smh + O_QL + r * QSTR + c, ql + zq + (size_t)(q0 + r) * 128 + c);
    }
#pragma unroll
    for (int s = 0; s < 2; s++) {
        __half* bK = smh + O_K + s * KHL;
        __half* bVh = smh + O_V + s * VSTG;
        __half* bVl = bVh + VHL;
        const int k0 = s * 64;
#pragma unroll
        for (int t = 0; t < 4; t++) {
            int i = tid + t * 256, r = i >> 4, c = (i & 15) * 8;
            cpa16(bK + r * QSTR + c, kh + zq + (size_t)(k0 + r) * 128 + c);
        }
#pragma unroll
        for (int t = 0; t < 2; t++) {
            int i = tid + t * 256, d = i >> 3, c = (i & 7) * 8;
            cpa16(bVh + d * VSTR + c, vh + zv + (size_t)d * 2048 + k0 + c);
            cpa16(bVl + d * VSTR + c, vl + zv + (size_t)d * 2048 + k0 + c);
        }
        CP_COMMIT();
    }
    CP_WAIT1();
    __syncthreads();

    // hoist Q fragments (tile-invariant)
    uint32_t qfh[8][4], qfl[8][4];
#pragma unroll
    for (int kd = 0; kd < 8; kd++) {
        ldsm4(qfh[kd], smh + O_QH + mrow * QSTR + kd * 16 + aoffQ);
        ldsm4(qfl[kd], smh + O_QL + mrow * QSTR + kd * 16 + aoffQ);
    }

    float m0 = -INFINITY, m1 = -INFINITY, L0 = 0.f, L1 = 0.f;
    float of[8][4] = {};

    for (int it = 0; it < 32; it++) {
        const int k0 = it * 64, stg = it % 3;
        const __half* bK = smh + O_K + stg * KHL;
        const __half* bVh = smh + O_V + stg * VSTG;
        const __half* bVl = bVh + VHL;

        // S = (Qhi + Qlo) Khi^T
        float sf[8][4] = {};
#pragma unroll
        for (int kd = 0; kd < 8; kd++) {
#pragma unroll
            for (int np = 0; np < 4; np++) {
                uint32_t b4[4];
                ldsm4(b4, bK + (np * 16) * QSTR + kd * 16 + boffK);
                mma16816(sf[2 * np],     qfh[kd], b4);
                mma16816(sf[2 * np],     qfl[kd], b4);
                mma16816(sf[2 * np + 1], qfh[kd], b4 + 2);
                mma16816(sf[2 * np + 1], qfl[kd], b4 + 2);
            }
        }

        // scale + bias + online softmax
        const int r0 = q0 + mrow + lr4;
        float lm0 = -INFINITY, lm1 = -INFINITY;
#pragma unroll
        for (int nf = 0; nf < 8; nf++) {
            int c = k0 + nf * 8 + lc2;
            sf[nf][0] = sf[nf][0] * INV_SCALE + bd[c - r0 + 2047];
            sf[nf][1] = sf[nf][1] * INV_SCALE + bd[c + 1 - r0 + 2047];
            sf[nf][2] = sf[nf][2] * INV_SCALE + bd[c - (r0 + 8) + 2047];
            sf[nf][3] = sf[nf][3] * INV_SCALE + bd[c + 1 - (r0 + 8) + 2047];
            lm0 = fmaxf(lm0, fmaxf(sf[nf][0], sf[nf][1]));
            lm1 = fmaxf(lm1, fmaxf(sf[nf][2], sf[nf][3]));
        }
        lm0 = fmaxf(lm0, __shfl_xor_sync(0xffffffffu, lm0, 1));
        lm0 = fmaxf(lm0, __shfl_xor_sync(0xffffffffu, lm0, 2));
        lm1 = fmaxf(lm1, __shfl_xor_sync(0xffffffffu, lm1, 1));
        lm1 = fmaxf(lm1, __shfl_xor_sync(0xffffffffu, lm1, 2));
        float mn0 = fmaxf(m0, lm0), mn1 = fmaxf(m1, lm1);
        float corr0 = __expf(m0 - mn0), corr1 = __expf(m1 - mn1);
        float rs0 = 0.f, rs1 = 0.f;
        uint32_t ap[4][4];
#pragma unroll
        for (int nf = 0; nf < 8; nf++) {
            float p0 = __expf(sf[nf][0] - mn0), p1 = __expf(sf[nf][1] - mn0);
            float p2 = __expf(sf[nf][2] - mn1), p3 = __expf(sf[nf][3] - mn1);
            rs0 += p0 + p1; rs1 += p2 + p3;
            __half2 h01 = __floats2half2_rn(p0, p1);
            __half2 h23 = __floats2half2_rn(p2, p3);
            int kf = nf >> 1, off = (nf & 1) * 2;
            ap[kf][off] = *(uint32_t*)&h01;
            ap[kf][off + 1] = *(uint32_t*)&h23;
        }
        rs0 += __shfl_xor_sync(0xffffffffu, rs0, 1);
        rs0 += __shfl_xor_sync(0xffffffffu, rs0, 2);
        rs1 += __shfl_xor_sync(0xffffffffu, rs1, 1);
        rs1 += __shfl_xor_sync(0xffffffffu, rs1, 2);
        L0 = L0 * corr0 + rs0;
        L1 = L1 * corr1 + rs1;
        m0 = mn0; m1 = mn1;
#pragma unroll
        for (int nf = 0; nf < 8; nf++) {
            of[nf][0] *= corr0; of[nf][1] *= corr0;
            of[nf][2] *= corr1; of[nf][3] *= corr1;
        }
        // O += P V (2-term split on V)
#pragma unroll
        for (int kf = 0; kf < 4; kf++)
#pragma unroll
            for (int np = 0; np < 4; np++) {
                uint32_t b4h[4], b4l[4];
                ldsm4(b4h, bVh + (np * 16) * VSTR + kf * 16 + boffV);
                ldsm4(b4l, bVl + (np * 16) * VSTR + kf * 16 + boffV);
                mma16816(of[2 * np],     ap[kf], b4h);
                mma16816(of[2 * np],     ap[kf], b4l);
                mma16816(of[2 * np + 1], ap[kf], b4h + 2);
                mma16816(of[2 * np + 1], ap[kf], b4l + 2);
            }

        // prefetch tile it+2 then single sync
        if (it + 2 < 32) {
            const int nstg = (it + 2) % 3, nk0 = (it + 2) * 64;
            __half* nK = smh + O_K + nstg * KHL;
            __half* nVh = smh + O_V + nstg * VSTG;
            __half* nVl = nVh + VHL;
#pragma unroll
            for (int t = 0; t < 4; t++) {
                int i = tid + t * 256, r = i >> 4, c = (i & 15) * 8;
                cpa16(nK + r * QSTR + c, kh + zq + (size_t)(nk0 + r) * 128 + c);
            }
#pragma unroll
            for (int t = 0; t < 2; t++) {
                int i = tid + t * 256, d = i >> 3, c = (i & 7) * 8;
                cpa16(nVh + d * VSTR + c, vh + zv + (size_t)d * 2048 + nk0 + c);
                cpa16(nVl + d * VSTR + c, vl + zv + (size_t)d * 2048 + nk0 + c);
            }
            CP_COMMIT();
            CP_WAIT1();
        } else {
            CP_WAIT0();
        }
        __syncthreads();
    }

    float inv0 = 1.f / L0, inv1 = 1.f / L1;
    const int r0 = q0 + mrow + lr4;
    const size_t ob = (size_t)b * 2048 * 1024 + h * 64;
#pragma unroll
    for (int nf = 0; nf < 8; nf++) {
        int c = nf * 8 + lc2;
        *(float2*)&out[ob + (size_t)r0 * 1024 + c] =
            make_float2(of[nf][0] * inv0, of[nf][1] * inv0);
        *(float2*)&out[ob + (size_t)(r0 + 8) * 1024 + c] =
            make_float2(of[nf][2] * inv1, of[nf][3] * inv1);
    }
}

// ---------------------------------------------------------------------------
extern "C" void kernel_launch(void* const* d_in, const int* in_sizes, int n_in,
                              void* d_out, int out_size)
{
    const float* x          = (const float*)d_in[0];
    const float* pos_embed  = (const float*)d_in[1];
    const float* W_pos_kq   = (const float*)d_in[2];
    const float* W_tok_kqv  = (const float*)d_in[3];
    const float* bias_table = (const float*)d_in[4];
    float* out = (float*)d_out;

    float *tok, *pos, *biasd;
    __half *xh, *xl, *peh, *pel, *wth, *wtl, *wph, *wpl;
    __half *qh, *ql, *kh, *vh, *vl;
    cudaGetSymbolAddress((void**)&tok, g_tok);
    cudaGetSymbolAddress((void**)&pos, g_pos);
    cudaGetSymbolAddress((void**)&biasd, g_bias);
    cudaGetSymbolAddress((void**)&xh, g_xh);   cudaGetSymbolAddress((void**)&xl, g_xl);
    cudaGetSymbolAddress((void**)&peh, g_peh); cudaGetSymbolAddress((void**)&pel, g_pel);
    cudaGetSymbolAddress((void**)&wth, g_wth); cudaGetSymbolAddress((void**)&wtl, g_wtl);
    cudaGetSymbolAddress((void**)&wph, g_wph); cudaGetSymbolAddress((void**)&wpl, g_wpl);
    cudaGetSymbolAddress((void**)&qh, g_qh);   cudaGetSymbolAddress((void**)&ql, g_ql);
    cudaGetSymbolAddress((void**)&kh, g_kh);
    cudaGetSymbolAddress((void**)&vh, g_vh);   cudaGetSymbolAddress((void**)&vl, g_vl);

    cudaFuncSetAttribute(attn_kernel,
                         cudaFuncAttributeMaxDynamicSharedMemorySize, ATT_SMEM);
    cudaFuncSetAttribute(hgemm_split,
                         cudaFuncAttributeMaxDynamicSharedMemorySize, HG_SMEM);

    bias_kernel<<<256, 256>>>(bias_table);
    pack_split4<<<(4096 * 1024 / 4 + 255) / 256, 256>>>(x, xh, xl, 4096 * 1024 / 4);
    pack_split4<<<(2048 * 1024 / 4 + 255) / 256, 256>>>(pos_embed, peh, pel, 2048 * 1024 / 4);
    pack_splitT<<<dim3(3072 / 32, 1024 / 32), dim3(32, 8)>>>(W_tok_kqv, wth, wtl, 3072);
    pack_splitT<<<dim3(2048 / 32, 1024 / 32), dim3(32, 8)>>>(W_pos_kq, wph, wpl, 2048);

    hgemm_split<<<dim3(3072 / 128, 4096 / 128), 256, HG_SMEM>>>(
        xh, xl, wth, wtl, tok, 4096, 3072, 1024);
    hgemm_split<<<dim3(2048 / 128, 2048 / 128), 256, HG_SMEM>>>(
        peh, pel, wph, wpl, pos, 2048, 2048, 1024);

    pack_qk<<<(32 * 2048 * 32 + 255) / 256, 256>>>(tok, pos);
    pack_v<<<(32 * 64 * 512 + 255) / 256, 256>>>(tok);

    attn_kernel<<<dim3(16, 32), 256, ATT_SMEM>>>(qh, ql, kh, vh, vl, biasd, out);
}

// round 6
// speedup vs baseline: 4.3281x; 1.1837x over previous
#include <cuda_runtime.h>
#include <cuda_fp16.h>
#include <math.h>
#include <stdint.h>

#define INV_SCALE 0.08838834764831845f  // 1/sqrt(128)

// ------------------------- static scratch (no cudaMalloc) -------------------
__device__ float  g_bias[16 * 4096];
__device__ float  g_tok[4096UL * 3072];     // [B*S][3D]
__device__ float  g_pos[2048UL * 2048];     // [S][2D]
__device__ __half g_xh[4096UL * 1024];
__device__ __half g_peh[2048UL * 1024];
__device__ __half g_wth[3072UL * 1024], g_wtl[3072UL * 1024];  // W_tok^T
__device__ __half g_wph[2048UL * 1024], g_wpl[2048UL * 1024];  // W_pos^T
__device__ __half g_qh[32UL * 2048 * 128], g_ql[32UL * 2048 * 128];
__device__ __half g_kh[32UL * 2048 * 128];
__device__ __half g_vh[32UL * 64 * 2048],  g_vl[32UL * 64 * 2048]; // V^T per z

// ---------------------------------------------------------------------------
__device__ __forceinline__ void mma16816(float c[4], const uint32_t a[4],
                                         const uint32_t b[2]) {
    asm volatile(
        "mma.sync.aligned.m16n8k16.row.col.f32.f16.f16.f32 "
        "{%0,%1,%2,%3}, {%4,%5,%6,%7}, {%8,%9}, {%0,%1,%2,%3};\n"
        : "+f"(c[0]), "+f"(c[1]), "+f"(c[2]), "+f"(c[3])
        : "r"(a[0]), "r"(a[1]), "r"(a[2]), "r"(a[3]), "r"(b[0]), "r"(b[1]));
}
__device__ __forceinline__ uint32_t sptr(const void* p) {
    return (uint32_t)__cvta_generic_to_shared(p);
}
__device__ __forceinline__ void ldsm4(uint32_t r[4], const __half* p) {
    asm volatile("ldmatrix.sync.aligned.m8n8.x4.shared.b16 {%0,%1,%2,%3}, [%4];\n"
                 : "=r"(r[0]), "=r"(r[1]), "=r"(r[2]), "=r"(r[3]) : "r"(sptr(p)));
}
__device__ __forceinline__ void cpa16(__half* dst, const __half* src) {
    asm volatile("cp.async.cg.shared.global [%0], [%1], 16;\n"
                 :: "r"(sptr(dst)), "l"(src));
}
#define CP_COMMIT() asm volatile("cp.async.commit_group;\n")
#define CP_WAIT1() asm volatile("cp.async.wait_group 1;\n")
#define CP_WAIT0() asm volatile("cp.async.wait_group 0;\n")
__device__ __forceinline__ void split1(float v, __half& h, __half& l) {
    h = __float2half_rn(v);
    l = __float2half_rn(v - __half2float(h));
}

// ---------------------------------------------------------------------------
// T5 bias LUT: g_bias[h][delta + 2047], delta = k - q
// ---------------------------------------------------------------------------
__global__ void bias_kernel(const float* __restrict__ bias_table) {
    int idx = blockIdx.x * blockDim.x + threadIdx.x;
    if (idx >= 16 * 4096) return;
    int h = idx >> 12, dd = idx & 4095;
    int n = -(dd - 2047);
    int ret = 0;
    if (n < 0) { ret = 16; n = -n; }
    int bucket;
    if (n < 8) bucket = n;
    else {
        float v = logf((float)n / 8.0f) / logf(16.0f) * 8.0f;
        int vi = 8 + (int)v;
        bucket = vi < 15 ? vi : 15;
    }
    g_bias[idx] = bias_table[(bucket + ret + 2048) * 16 + h];
}

// ---------------------------------------------------------------------------
// pack fp32 -> fp16 (hi only), float4-vectorized
// ---------------------------------------------------------------------------
__global__ void pack_h4(const float* __restrict__ src, __half* __restrict__ hi, int n4) {
    int i = blockIdx.x * blockDim.x + threadIdx.x;
    if (i >= n4) return;
    float4 v = ((const float4*)src)[i];
    ((__half2*)hi)[2 * i]     = __floats2half2_rn(v.x, v.y);
    ((__half2*)hi)[2 * i + 1] = __floats2half2_rn(v.z, v.w);
}
// pack + transpose via 32x32 smem tile: src [1024][N] -> dst [N][1024], split
__global__ void __launch_bounds__(256) pack_splitT(
    const float* __restrict__ src, __half* __restrict__ hi,
    __half* __restrict__ lo, int N) {
    __shared__ float tile[32][33];
    int n0 = blockIdx.x * 32, k0 = blockIdx.y * 32;
    int tx = threadIdx.x, ty = threadIdx.y;
#pragma unroll
    for (int t = 0; t < 4; t++)
        tile[ty + t * 8][tx] = src[(size_t)(k0 + ty + t * 8) * N + n0 + tx];
    __syncthreads();
#pragma unroll
    for (int t = 0; t < 4; t++) {
        int n = n0 + ty + t * 8;
        float v = tile[tx][ty + t * 8];
        __half h, l;
        split1(v, h, l);
        hi[(size_t)n * 1024 + k0 + tx] = h;
        lo[(size_t)n * 1024 + k0 + tx] = l;
    }
}

// ---------------------------------------------------------------------------
// build Q (split) / K (hi only) 128-dim and V^T (split)
// ---------------------------------------------------------------------------
__global__ void pack_qk(const float* __restrict__ tok, const float* __restrict__ pos) {
    int i = blockIdx.x * blockDim.x + threadIdx.x;
    if (i >= 32 * 2048 * 32) return;
    int d = (i & 31) * 4, s = (i >> 5) & 2047, z = i >> 16;
    int b = z >> 4, h = z & 15;
    const float* qsrc;
    const float* ksrc;
    if (d < 64) {
        qsrc = &tok[(size_t)(b * 2048 + s) * 3072 + 1024 + h * 64 + d];
        ksrc = &tok[(size_t)(b * 2048 + s) * 3072 + h * 64 + d];
    } else {
        qsrc = &pos[(size_t)s * 2048 + 1024 + h * 64 + (d - 64)];
        ksrc = &pos[(size_t)s * 2048 + h * 64 + (d - 64)];
    }
    float4 qv = *(const float4*)qsrc;
    float4 kv = *(const float4*)ksrc;
    size_t o = ((size_t)z * 2048 + s) * 128 + d;
    __half h0, h1, h2, h3, l0, l1, l2, l3;
    split1(qv.x, h0, l0); split1(qv.y, h1, l1); split1(qv.z, h2, l2); split1(qv.w, h3, l3);
    *(__half2*)&g_qh[o] = __halves2half2(h0, h1); *(__half2*)&g_qh[o + 2] = __halves2half2(h2, h3);
    *(__half2*)&g_ql[o] = __halves2half2(l0, l1); *(__half2*)&g_ql[o + 2] = __halves2half2(l2, l3);
    *(__half2*)&g_kh[o]     = __floats2half2_rn(kv.x, kv.y);
    *(__half2*)&g_kh[o + 2] = __floats2half2_rn(kv.z, kv.w);
}
__global__ void pack_v(const float* __restrict__ tok) {
    int i = blockIdx.x * blockDim.x + threadIdx.x;
    if (i >= 32 * 64 * 512) return;
    int s = (i & 511) * 4, dh = (i >> 9) & 63, z = i >> 15;
    int b = z >> 4, h = z & 15;
    size_t o = ((size_t)z * 64 + dh) * 2048 + s;
#pragma unroll
    for (int t = 0; t < 4; t++) {
        float v = tok[(size_t)(b * 2048 + s + t) * 3072 + 2048 + h * 64 + dh];
        __half hv, lv;
        split1(v, hv, lv);
        g_vh[o + t] = hv; g_vl[o + t] = lv;
    }
}

// ---------------------------------------------------------------------------
// 2-term GEMM: C[M][N] = Ah[M][K] @ (Bh + Bl)^T  (B given as [N][K] split).
// 128x128 tile, 8 warps, 3-stage cp.async pipeline, 1 sync per k-step.
// ---------------------------------------------------------------------------
constexpr int HG_STG = 128 * 24;            // halves per array per stage
constexpr int HG_STAGE = 3 * HG_STG;        // Ah, Bh, Bl
constexpr int HG_SMEM = 3 * HG_STAGE * 2;   // bytes = 55296

__global__ void __launch_bounds__(256) hgemm_split(
    const __half* __restrict__ Ah,
    const __half* __restrict__ Bh, const __half* __restrict__ Bl,
    float* __restrict__ C, int M, int N, int K)
{
    extern __shared__ __half smg[];
    const int tid = threadIdx.x, wid = tid >> 5, lane = tid & 31;
    const int wm = wid & 1, wn = wid >> 1;
    const int bm = blockIdx.y * 128, bn = blockIdx.x * 128;
    const int lr = tid >> 1, lc = (tid & 1) * 8;
    const __half* pAh = Ah + (size_t)(bm + lr) * K + lc;
    const __half* pBh = Bh + (size_t)(bn + lr) * K + lc;
    const __half* pBl = Bl + (size_t)(bn + lr) * K + lc;
    const int soff = lr * 24 + lc;
    const int aoff = (lane & 15) * 24 + (lane >> 4) * 8;
    const int boff = ((lane & 7) + ((lane >> 4) << 3)) * 24 + ((lane >> 3) & 1) * 8;
    const int NK = K / 16;
    float acc[4][4][4] = {};

#pragma unroll
    for (int s = 0; s < 2; s++) {
        __half* st = smg + s * HG_STAGE;
        cpa16(st + soff, pAh + s * 16);
        cpa16(st + HG_STG + soff, pBh + s * 16);
        cpa16(st + 2 * HG_STG + soff, pBl + s * 16);
        CP_COMMIT();
    }
    CP_WAIT1();
    __syncthreads();

    for (int kt = 0; kt < NK; kt++) {
        const __half* st = smg + (kt % 3) * HG_STAGE;
        uint32_t afh[4][4], bfh[4][2], bfl[4][2];
#pragma unroll
        for (int i = 0; i < 4; i++)
            ldsm4(afh[i], st + (wm * 64 + i * 16) * 24 + aoff);
#pragma unroll
        for (int j2 = 0; j2 < 2; j2++) {
            uint32_t t4[4];
            ldsm4(t4, st + HG_STG + (wn * 32 + j2 * 16) * 24 + boff);
            bfh[2 * j2][0] = t4[0]; bfh[2 * j2][1] = t4[1];
            bfh[2 * j2 + 1][0] = t4[2]; bfh[2 * j2 + 1][1] = t4[3];
            ldsm4(t4, st + 2 * HG_STG + (wn * 32 + j2 * 16) * 24 + boff);
            bfl[2 * j2][0] = t4[0]; bfl[2 * j2][1] = t4[1];
            bfl[2 * j2 + 1][0] = t4[2]; bfl[2 * j2 + 1][1] = t4[3];
        }
#pragma unroll
        for (int i = 0; i < 4; i++)
#pragma unroll
            for (int j = 0; j < 4; j++) {
                mma16816(acc[i][j], afh[i], bfh[j]);
                mma16816(acc[i][j], afh[i], bfl[j]);
            }
        if (kt + 2 < NK) {
            __half* nt = smg + ((kt + 2) % 3) * HG_STAGE;
            int ko = (kt + 2) * 16;
            cpa16(nt + soff, pAh + ko);
            cpa16(nt + HG_STG + soff, pBh + ko);
            cpa16(nt + 2 * HG_STG + soff, pBl + ko);
            CP_COMMIT();
            CP_WAIT1();
        } else {
            CP_WAIT0();
        }
        __syncthreads();
    }
#pragma unroll
    for (int i = 0; i < 4; i++)
#pragma unroll
        for (int j = 0; j < 4; j++) {
            int r = bm + wm * 64 + i * 16 + (lane >> 2);
            int c = bn + wn * 32 + j * 8 + (lane & 3) * 2;
            *(float2*)&C[(size_t)r * N + c] = make_float2(acc[i][j][0], acc[i][j][1]);
            *(float2*)&C[(size_t)(r + 8) * N + c] = make_float2(acc[i][j][2], acc[i][j][3]);
        }
}

// ---------------------------------------------------------------------------
// fused flash attention: QK(it+1) issued BEFORE softmax(it) to keep the tensor
// pipe busy during exp/reduce. 4-stage cp.async K/V pipeline (distance 3).
// block = (q-tile 128, z), 8 warps.
// ---------------------------------------------------------------------------
#define QSTR 136
#define VSTR 72
constexpr int O_QH = 0;
constexpr int O_QL = 128 * QSTR;                 // 17408
constexpr int O_K  = 2 * 128 * QSTR;             // 34816
constexpr int KHL  = 64 * QSTR;                  // 8704 (hi only)
constexpr int O_V  = O_K + 4 * KHL;              // 69632
constexpr int VHL  = 64 * VSTR;                  // 4608
constexpr int VSTG = 2 * VHL;                    // 9216 (hi+lo)
constexpr int ATT_SMEM = (O_V + 4 * VSTG) * 2;   // 212992 bytes

__global__ void __launch_bounds__(256) attn_kernel(
    const __half* __restrict__ qh, const __half* __restrict__ ql,
    const __half* __restrict__ kh,
    const __half* __restrict__ vh, const __half* __restrict__ vl,
    const float* __restrict__ biasd, float* __restrict__ out)
{
    extern __shared__ __half smh[];
    const int z = blockIdx.y, b = z >> 4, h = z & 15;
    const int q0 = blockIdx.x * 128;
    const int tid = threadIdx.x, wid = tid >> 5, lane = tid & 31;
    const int lr4 = lane >> 2, lc2 = (lane & 3) * 2;
    const float* bd = biasd + h * 4096;
    const size_t zq = (size_t)z * 2048 * 128;
    const size_t zv = (size_t)z * 64 * 2048;
    const int mrow = wid * 16;
    const int aoffQ = (lane & 15) * QSTR + (lane >> 4) * 8;
    const int boffK = ((lane & 7) + ((lane >> 4) << 3)) * QSTR + ((lane >> 3) & 1) * 8;
    const int boffV = ((lane & 7) + ((lane >> 4) << 3)) * VSTR + ((lane >> 3) & 1) * 8;

    auto PREFETCH = [&](int t) {
        __half* bK = smh + O_K + (t & 3) * KHL;
        __half* bVh = smh + O_V + (t & 3) * VSTG;
        __half* bVl = bVh + VHL;
        const int k0 = t * 64;
#pragma unroll
        for (int tt = 0; tt < 4; tt++) {
            int i = tid + tt * 256, r = i >> 4, c = (i & 15) * 8;
            cpa16(bK + r * QSTR + c, kh + zq + (size_t)(k0 + r) * 128 + c);
        }
#pragma unroll
        for (int tt = 0; tt < 2; tt++) {
            int i = tid + tt * 256, d = i >> 3, c = (i & 7) * 8;
            cpa16(bVh + d * VSTR + c, vh + zv + (size_t)d * 2048 + k0 + c);
            cpa16(bVl + d * VSTR + c, vl + zv + (size_t)d * 2048 + k0 + c);
        }
        CP_COMMIT();
    };

    // group 0: Q + K/V tile0 ; group 1: tile1 ; group 2: tile2
#pragma unroll
    for (int t = 0; t < 8; t++) {
        int i = tid + t * 256, r = i >> 4, c = (i & 15) * 8;
        cpa16(smh + O_QH + r * QSTR + c, qh + zq + (size_t)(q0 + r) * 128 + c);
        cpa16(smh + O_QL + r * QSTR + c, ql + zq + (size_t)(q0 + r) * 128 + c);
    }
    {
        __half* bK = smh + O_K;
        __half* bVh = smh + O_V;
        __half* bVl = bVh + VHL;
#pragma unroll
        for (int tt = 0; tt < 4; tt++) {
            int i = tid + tt * 256, r = i >> 4, c = (i & 15) * 8;
            cpa16(bK + r * QSTR + c, kh + zq + (size_t)r * 128 + c);
        }
#pragma unroll
        for (int tt = 0; tt < 2; tt++) {
            int i = tid + tt * 256, d = i >> 3, c = (i & 7) * 8;
            cpa16(bVh + d * VSTR + c, vh + zv + (size_t)d * 2048 + c);
            cpa16(bVl + d * VSTR + c, vl + zv + (size_t)d * 2048 + c);
        }
        CP_COMMIT();
    }
    PREFETCH(1);
    PREFETCH(2);
    CP_WAIT1();          // Q + tiles 0,1 arrived
    __syncthreads();

    // hoist Q fragments (tile-invariant)
    uint32_t qfh[8][4], qfl[8][4];
#pragma unroll
    for (int kd = 0; kd < 8; kd++) {
        ldsm4(qfh[kd], smh + O_QH + mrow * QSTR + kd * 16 + aoffQ);
        ldsm4(qfl[kd], smh + O_QL + mrow * QSTR + kd * 16 + aoffQ);
    }

    float m0 = -INFINITY, m1 = -INFINITY, L0 = 0.f, L1 = 0.f;
    float of[8][4] = {};
    float sfA[8][4], sfB[8][4];

    auto QK = [&](int t, float (&sf)[8][4]) {
        const __half* bK = smh + O_K + (t & 3) * KHL;
#pragma unroll
        for (int nf = 0; nf < 8; nf++)
#pragma unroll
            for (int c = 0; c < 4; c++) sf[nf][c] = 0.f;
#pragma unroll
        for (int kd = 0; kd < 8; kd++) {
#pragma unroll
            for (int np = 0; np < 4; np++) {
                uint32_t b4[4];
                ldsm4(b4, bK + (np * 16) * QSTR + kd * 16 + boffK);
                mma16816(sf[2 * np],     qfh[kd], b4);
                mma16816(sf[2 * np],     qfl[kd], b4);
                mma16816(sf[2 * np + 1], qfh[kd], b4 + 2);
                mma16816(sf[2 * np + 1], qfl[kd], b4 + 2);
            }
        }
    };

    auto SOFTPV = [&](int it, float (&sf)[8][4]) {
        const int k0 = it * 64;
        const __half* bVh = smh + O_V + (it & 3) * VSTG;
        const __half* bVl = bVh + VHL;
        const int r0 = q0 + mrow + lr4;
        float lm0 = -INFINITY, lm1 = -INFINITY;
#pragma unroll
        for (int nf = 0; nf < 8; nf++) {
            int c = k0 + nf * 8 + lc2;
            sf[nf][0] = sf[nf][0] * INV_SCALE + bd[c - r0 + 2047];
            sf[nf][1] = sf[nf][1] * INV_SCALE + bd[c + 1 - r0 + 2047];
            sf[nf][2] = sf[nf][2] * INV_SCALE + bd[c - (r0 + 8) + 2047];
            sf[nf][3] = sf[nf][3] * INV_SCALE + bd[c + 1 - (r0 + 8) + 2047];
            lm0 = fmaxf(lm0, fmaxf(sf[nf][0], sf[nf][1]));
            lm1 = fmaxf(lm1, fmaxf(sf[nf][2], sf[nf][3]));
        }
        lm0 = fmaxf(lm0, __shfl_xor_sync(0xffffffffu, lm0, 1));
        lm0 = fmaxf(lm0, __shfl_xor_sync(0xffffffffu, lm0, 2));
        lm1 = fmaxf(lm1, __shfl_xor_sync(0xffffffffu, lm1, 1));
        lm1 = fmaxf(lm1, __shfl_xor_sync(0xffffffffu, lm1, 2));
        float mn0 = fmaxf(m0, lm0), mn1 = fmaxf(m1, lm1);
        float corr0 = __expf(m0 - mn0), corr1 = __expf(m1 - mn1);
        float rs0 = 0.f, rs1 = 0.f;
        uint32_t ap[4][4];
#pragma unroll
        for (int nf = 0; nf < 8; nf++) {
            float p0 = __expf(sf[nf][0] - mn0), p1 = __expf(sf[nf][1] - mn0);
            float p2 = __expf(sf[nf][2] - mn1), p3 = __expf(sf[nf][3] - mn1);
            rs0 += p0 + p1; rs1 += p2 + p3;
            __half2 h01 = __floats2half2_rn(p0, p1);
            __half2 h23 = __floats2half2_rn(p2, p3);
            int kf = nf >> 1, off = (nf & 1) * 2;
            ap[kf][off] = *(uint32_t*)&h01;
            ap[kf][off + 1] = *(uint32_t*)&h23;
        }
        rs0 += __shfl_xor_sync(0xffffffffu, rs0, 1);
        rs0 += __shfl_xor_sync(0xffffffffu, rs0, 2);
        rs1 += __shfl_xor_sync(0xffffffffu, rs1, 1);
        rs1 += __shfl_xor_sync(0xffffffffu, rs1, 2);
        L0 = L0 * corr0 + rs0;
        L1 = L1 * corr1 + rs1;
        m0 = mn0; m1 = mn1;
#pragma unroll
        for (int nf = 0; nf < 8; nf++) {
            of[nf][0] *= corr0; of[nf][1] *= corr0;
            of[nf][2] *= corr1; of[nf][3] *= corr1;
        }
#pragma unroll
        for (int kf = 0; kf < 4; kf++)
#pragma unroll
            for (int np = 0; np < 4; np++) {
                uint32_t b4h[4], b4l[4];
                ldsm4(b4h, bVh + (np * 16) * VSTR + kf * 16 + boffV);
                ldsm4(b4l, bVl + (np * 16) * VSTR + kf * 16 + boffV);
                mma16816(of[2 * np],     ap[kf], b4h);
                mma16816(of[2 * np],     ap[kf], b4l);
                mma16816(of[2 * np + 1], ap[kf], b4h + 2);
                mma16816(of[2 * np + 1], ap[kf], b4l + 2);
            }
    };

    auto PIPE = [&](int it) {
        if (it + 3 < 32) {
            PREFETCH(it + 3);
            CP_WAIT1();      // tile it+2 arrived
        } else {
            CP_WAIT0();
        }
        __syncthreads();
    };

    QK(0, sfA);
    for (int it = 0; it < 32; it += 2) {
        // even iter: consume sfA, build sfB
        if (it + 1 < 32) QK(it + 1, sfB);
        SOFTPV(it, sfA);
        PIPE(it);
        // odd iter: consume sfB, build sfA
        if (it + 2 < 32) QK(it + 2, sfA);
        SOFTPV(it + 1, sfB);
        PIPE(it + 1);
    }

    float inv0 = 1.f / L0, inv1 = 1.f / L1;
    const int r0 = q0 + mrow + lr4;
    const size_t ob = (size_t)b * 2048 * 1024 + h * 64;
#pragma unroll
    for (int nf = 0; nf < 8; nf++) {
        int c = nf * 8 + lc2;
        *(float2*)&out[ob + (size_t)r0 * 1024 + c] =
            make_float2(of[nf][0] * inv0, of[nf][1] * inv0);
        *(float2*)&out[ob + (size_t)(r0 + 8) * 1024 + c] =
            make_float2(of[nf][2] * inv1, of[nf][3] * inv1);
    }
}

// ---------------------------------------------------------------------------
extern "C" void kernel_launch(void* const* d_in, const int* in_sizes, int n_in,
                              void* d_out, int out_size)
{
    const float* x          = (const float*)d_in[0];
    const float* pos_embed  = (const float*)d_in[1];
    const float* W_pos_kq   = (const float*)d_in[2];
    const float* W_tok_kqv  = (const float*)d_in[3];
    const float* bias_table = (const float*)d_in[4];
    float* out = (float*)d_out;

    float *tok, *pos, *biasd;
    __half *xh, *peh, *wth, *wtl, *wph, *wpl;
    __half *qh, *ql, *kh, *vh, *vl;
    cudaGetSymbolAddress((void**)&tok, g_tok);
    cudaGetSymbolAddress((void**)&pos, g_pos);
    cudaGetSymbolAddress((void**)&biasd, g_bias);
    cudaGetSymbolAddress((void**)&xh, g_xh);
    cudaGetSymbolAddress((void**)&peh, g_peh);
    cudaGetSymbolAddress((void**)&wth, g_wth); cudaGetSymbolAddress((void**)&wtl, g_wtl);
    cudaGetSymbolAddress((void**)&wph, g_wph); cudaGetSymbolAddress((void**)&wpl, g_wpl);
    cudaGetSymbolAddress((void**)&qh, g_qh);   cudaGetSymbolAddress((void**)&ql, g_ql);
    cudaGetSymbolAddress((void**)&kh, g_kh);
    cudaGetSymbolAddress((void**)&vh, g_vh);   cudaGetSymbolAddress((void**)&vl, g_vl);

    cudaFuncSetAttribute(attn_kernel,
                         cudaFuncAttributeMaxDynamicSharedMemorySize, ATT_SMEM);
    cudaFuncSetAttribute(hgemm_split,
                         cudaFuncAttributeMaxDynamicSharedMemorySize, HG_SMEM);

    bias_kernel<<<256, 256>>>(bias_table);
    pack_h4<<<(4096 * 1024 / 4 + 255) / 256, 256>>>(x, xh, 4096 * 1024 / 4);
    pack_h4<<<(2048 * 1024 / 4 + 255) / 256, 256>>>(pos_embed, peh, 2048 * 1024 / 4);
    pack_splitT<<<dim3(3072 / 32, 1024 / 32), dim3(32, 8)>>>(W_tok_kqv, wth, wtl, 3072);
    pack_splitT<<<dim3(2048 / 32, 1024 / 32), dim3(32, 8)>>>(W_pos_kq, wph, wpl, 2048);

    hgemm_split<<<dim3(3072 / 128, 4096 / 128), 256, HG_SMEM>>>(
        xh, wth, wtl, tok, 4096, 3072, 1024);
    hgemm_split<<<dim3(2048 / 128, 2048 / 128), 256, HG_SMEM>>>(
        peh, wph, wpl, pos, 2048, 2048, 1024);

    pack_qk<<<(32 * 2048 * 32 + 255) / 256, 256>>>(tok, pos);
    pack_v<<<(32 * 64 * 512 + 255) / 256, 256>>>(tok);

    attn_kernel<<<dim3(16, 32), 256, ATT_SMEM>>>(qh, ql, kh, vh, vl, biasd, out);
}

// round 7
// speedup vs baseline: 4.7158x; 1.0896x over previous
#include <cuda_runtime.h>
#include <cuda_fp16.h>
#include <math.h>
#include <stdint.h>

#define INV_SCALE 0.08838834764831845f  // 1/sqrt(128)

// ------------------------- static scratch (no cudaMalloc) -------------------
__device__ float  g_bias[16 * 4096];
__device__ float  g_tok[4096UL * 3072];     // [B*S][3D]
__device__ float  g_pos[2048UL * 2048];     // [S][2D]
__device__ __half g_xh[4096UL * 1024];
__device__ __half g_peh[2048UL * 1024];
__device__ __half g_wth[3072UL * 1024], g_wtl[3072UL * 1024];  // W_tok^T
__device__ __half g_wph[2048UL * 1024], g_wpl[2048UL * 1024];  // W_pos^T
__device__ __half g_qh[32UL * 2048 * 128], g_ql[32UL * 2048 * 128];
__device__ __half g_kh[32UL * 2048 * 128];
__device__ __half g_vh[32UL * 64 * 2048];   // V^T per z, hi only

// ---------------------------------------------------------------------------
__device__ __forceinline__ void mma16816(float c[4], const uint32_t a[4],
                                         const uint32_t b[2]) {
    asm volatile(
        "mma.sync.aligned.m16n8k16.row.col.f32.f16.f16.f32 "
        "{%0,%1,%2,%3}, {%4,%5,%6,%7}, {%8,%9}, {%0,%1,%2,%3};\n"
        : "+f"(c[0]), "+f"(c[1]), "+f"(c[2]), "+f"(c[3])
        : "r"(a[0]), "r"(a[1]), "r"(a[2]), "r"(a[3]), "r"(b[0]), "r"(b[1]));
}
__device__ __forceinline__ uint32_t sptr(const void* p) {
    return (uint32_t)__cvta_generic_to_shared(p);
}
__device__ __forceinline__ void ldsm4(uint32_t r[4], const __half* p) {
    asm volatile("ldmatrix.sync.aligned.m8n8.x4.shared.b16 {%0,%1,%2,%3}, [%4];\n"
                 : "=r"(r[0]), "=r"(r[1]), "=r"(r[2]), "=r"(r[3]) : "r"(sptr(p)));
}
__device__ __forceinline__ void cpa16(__half* dst, const __half* src) {
    asm volatile("cp.async.cg.shared.global [%0], [%1], 16;\n"
                 :: "r"(sptr(dst)), "l"(src));
}
#define CP_COMMIT() asm volatile("cp.async.commit_group;\n")
#define CP_WAIT1() asm volatile("cp.async.wait_group 1;\n")
#define CP_WAIT0() asm volatile("cp.async.wait_group 0;\n")
__device__ __forceinline__ void split1(float v, __half& h, __half& l) {
    h = __float2half_rn(v);
    l = __float2half_rn(v - __half2float(h));
}

// ---------------------------------------------------------------------------
// fused: pack x -> xh and pos_embed -> peh (fp16 hi only)
// ---------------------------------------------------------------------------
constexpr int N4X = 4096 * 1024 / 4;   // 1048576
constexpr int N4P = 2048 * 1024 / 4;   // 524288
__global__ void pack_all_h(const float* __restrict__ x,
                           const float* __restrict__ pe) {
    int i = blockIdx.x * blockDim.x + threadIdx.x;
    if (i >= N4X + N4P) return;
    const float* src;
    __half* dst;
    int j;
    if (i < N4X) { src = x;  dst = g_xh;  j = i; }
    else         { src = pe; dst = g_peh; j = i - N4X; }
    float4 v = ((const float4*)src)[j];
    ((__half2*)dst)[2 * j]     = __floats2half2_rn(v.x, v.y);
    ((__half2*)dst)[2 * j + 1] = __floats2half2_rn(v.z, v.w);
}

// ---------------------------------------------------------------------------
// fused pack+transpose+split for both weights: src [1024][N] -> dst [N][1024]
// grid.x: 0..95 -> W_tok (N=3072), 96..159 -> W_pos (N=2048); grid.y = k/32
// ---------------------------------------------------------------------------
__global__ void __launch_bounds__(256) pack_splitT_all(
    const float* __restrict__ wt, const float* __restrict__ wp) {
    __shared__ float tile[32][33];
    const float* src;
    __half *hi, *lo;
    int N, bx = blockIdx.x;
    if (bx < 96) { src = wt; hi = g_wth; lo = g_wtl; N = 3072; }
    else         { src = wp; hi = g_wph; lo = g_wpl; N = 2048; bx -= 96; }
    int n0 = bx * 32, k0 = blockIdx.y * 32;
    int tx = threadIdx.x, ty = threadIdx.y;
#pragma unroll
    for (int t = 0; t < 4; t++)
        tile[ty + t * 8][tx] = src[(size_t)(k0 + ty + t * 8) * N + n0 + tx];
    __syncthreads();
#pragma unroll
    for (int t = 0; t < 4; t++) {
        int n = n0 + ty + t * 8;
        float v = tile[tx][ty + t * 8];
        __half h, l;
        split1(v, h, l);
        hi[(size_t)n * 1024 + k0 + tx] = h;
        lo[(size_t)n * 1024 + k0 + tx] = l;
    }
}

// ---------------------------------------------------------------------------
// fused: build Q (split, pre-scaled by 1/sqrt(128)) / K (hi) / V^T (hi) + bias LUT
// ---------------------------------------------------------------------------
constexpr int NQK = 32 * 2048 * 32;   // 2097152
constexpr int NV  = 32 * 64 * 512;    // 1048576
constexpr int NB  = 16 * 4096;        // 65536
__global__ void pack_qkv(const float* __restrict__ tok, const float* __restrict__ pos,
                         const float* __restrict__ bias_table) {
    int i = blockIdx.x * blockDim.x + threadIdx.x;
    if (i < NQK) {
        int d = (i & 31) * 4, s = (i >> 5) & 2047, z = i >> 16;
        int b = z >> 4, h = z & 15;
        const float* qsrc;
        const float* ksrc;
        if (d < 64) {
            qsrc = &tok[(size_t)(b * 2048 + s) * 3072 + 1024 + h * 64 + d];
            ksrc = &tok[(size_t)(b * 2048 + s) * 3072 + h * 64 + d];
        } else {
            qsrc = &pos[(size_t)s * 2048 + 1024 + h * 64 + (d - 64)];
            ksrc = &pos[(size_t)s * 2048 + h * 64 + (d - 64)];
        }
        float4 qv = *(const float4*)qsrc;
        float4 kv = *(const float4*)ksrc;
        size_t o = ((size_t)z * 2048 + s) * 128 + d;
        __half h0, h1, h2, h3, l0, l1, l2, l3;
        split1(qv.x * INV_SCALE, h0, l0); split1(qv.y * INV_SCALE, h1, l1);
        split1(qv.z * INV_SCALE, h2, l2); split1(qv.w * INV_SCALE, h3, l3);
        *(__half2*)&g_qh[o] = __halves2half2(h0, h1);
        *(__half2*)&g_qh[o + 2] = __halves2half2(h2, h3);
        *(__half2*)&g_ql[o] = __halves2half2(l0, l1);
        *(__half2*)&g_ql[o + 2] = __halves2half2(l2, l3);
        *(__half2*)&g_kh[o]     = __floats2half2_rn(kv.x, kv.y);
        *(__half2*)&g_kh[o + 2] = __floats2half2_rn(kv.z, kv.w);
    } else if (i < NQK + NV) {
        int j = i - NQK;
        int s = (j & 511) * 4, dh = (j >> 9) & 63, z = j >> 15;
        int b = z >> 4, h = z & 15;
        size_t o = ((size_t)z * 64 + dh) * 2048 + s;
#pragma unroll
        for (int t = 0; t < 4; t++) {
            float v = tok[(size_t)(b * 2048 + s + t) * 3072 + 2048 + h * 64 + dh];
            g_vh[o + t] = __float2half_rn(v);
        }
    } else if (i < NQK + NV + NB) {
        int j = i - NQK - NV;
        int h = j >> 12, dd = j & 4095;
        int n = -(dd - 2047);
        int ret = 0;
        if (n < 0) { ret = 16; n = -n; }
        int bucket;
        if (n < 8) bucket = n;
        else {
            float v = logf((float)n / 8.0f) / logf(16.0f) * 8.0f;
            int vi = 8 + (int)v;
            bucket = vi < 15 ? vi : 15;
        }
        g_bias[j] = bias_table[(bucket + ret + 2048) * 16 + h];
    }
}

// ---------------------------------------------------------------------------
// 2-term GEMM: C[M][N] = Ah[M][K] @ (Bh + Bl)^T  (B given as [N][K] split).
// 128x128 tile, 8 warps, 3-stage cp.async pipeline, 1 sync per k-step.
// ---------------------------------------------------------------------------
constexpr int HG_STG = 128 * 24;            // halves per array per stage
constexpr int HG_STAGE = 3 * HG_STG;        // Ah, Bh, Bl
constexpr int HG_SMEM = 3 * HG_STAGE * 2;   // bytes = 55296

__global__ void __launch_bounds__(256) hgemm_split(
    const __half* __restrict__ Ah,
    const __half* __restrict__ Bh, const __half* __restrict__ Bl,
    float* __restrict__ C, int M, int N, int K)
{
    extern __shared__ __half smg[];
    const int tid = threadIdx.x, wid = tid >> 5, lane = tid & 31;
    const int wm = wid & 1, wn = wid >> 1;
    const int bm = blockIdx.y * 128, bn = blockIdx.x * 128;
    const int lr = tid >> 1, lc = (tid & 1) * 8;
    const __half* pAh = Ah + (size_t)(bm + lr) * K + lc;
    const __half* pBh = Bh + (size_t)(bn + lr) * K + lc;
    const __half* pBl = Bl + (size_t)(bn + lr) * K + lc;
    const int soff = lr * 24 + lc;
    const int aoff = (lane & 15) * 24 + (lane >> 4) * 8;
    const int boff = ((lane & 7) + ((lane >> 4) << 3)) * 24 + ((lane >> 3) & 1) * 8;
    const int NK = K / 16;
    float acc[4][4][4] = {};

#pragma unroll
    for (int s = 0; s < 2; s++) {
        __half* st = smg + s * HG_STAGE;
        cpa16(st + soff, pAh + s * 16);
        cpa16(st + HG_STG + soff, pBh + s * 16);
        cpa16(st + 2 * HG_STG + soff, pBl + s * 16);
        CP_COMMIT();
    }
    CP_WAIT1();
    __syncthreads();

    for (int kt = 0; kt < NK; kt++) {
        const __half* st = smg + (kt % 3) * HG_STAGE;
        uint32_t afh[4][4], bfh[4][2], bfl[4][2];
#pragma unroll
        for (int i = 0; i < 4; i++)
            ldsm4(afh[i], st + (wm * 64 + i * 16) * 24 + aoff);
#pragma unroll
        for (int j2 = 0; j2 < 2; j2++) {
            uint32_t t4[4];
            ldsm4(t4, st + HG_STG + (wn * 32 + j2 * 16) * 24 + boff);
            bfh[2 * j2][0] = t4[0]; bfh[2 * j2][1] = t4[1];
            bfh[2 * j2 + 1][0] = t4[2]; bfh[2 * j2 + 1][1] = t4[3];
            ldsm4(t4, st + 2 * HG_STG + (wn * 32 + j2 * 16) * 24 + boff);
            bfl[2 * j2][0] = t4[0]; bfl[2 * j2][1] = t4[1];
            bfl[2 * j2 + 1][0] = t4[2]; bfl[2 * j2 + 1][1] = t4[3];
        }
#pragma unroll
        for (int i = 0; i < 4; i++)
#pragma unroll
            for (int j = 0; j < 4; j++) {
                mma16816(acc[i][j], afh[i], bfh[j]);
                mma16816(acc[i][j], afh[i], bfl[j]);
            }
        if (kt + 2 < NK) {
            __half* nt = smg + ((kt + 2) % 3) * HG_STAGE;
            int ko = (kt + 2) * 16;
            cpa16(nt + soff, pAh + ko);
            cpa16(nt + HG_STG + soff, pBh + ko);
            cpa16(nt + 2 * HG_STG + soff, pBl + ko);
            CP_COMMIT();
            CP_WAIT1();
        } else {
            CP_WAIT0();
        }
        __syncthreads();
    }
#pragma unroll
    for (int i = 0; i < 4; i++)
#pragma unroll
        for (int j = 0; j < 4; j++) {
            int r = bm + wm * 64 + i * 16 + (lane >> 2);
            int c = bn + wn * 32 + j * 8 + (lane & 3) * 2;
            *(float2*)&C[(size_t)r * N + c] = make_float2(acc[i][j][0], acc[i][j][1]);
            *(float2*)&C[(size_t)(r + 8) * N + c] = make_float2(acc[i][j][2], acc[i][j][3]);
        }
}

// ---------------------------------------------------------------------------
// fused flash attention: 2-term QK (pre-scaled Q), single-term PV,
// QK(it+1) before softmax(it), 4-stage cp.async K/V pipeline.
// block = (q-tile 128, z), 8 warps.
// ---------------------------------------------------------------------------
#define QSTR 136
#define VSTR 72
constexpr int O_QH = 0;
constexpr int O_QL = 128 * QSTR;                 // 17408
constexpr int O_K  = 2 * 128 * QSTR;             // 34816
constexpr int KHL  = 64 * QSTR;                  // 8704 (hi only)
constexpr int O_V  = O_K + 4 * KHL;              // 69632
constexpr int VHL  = 64 * VSTR;                  // 4608 (hi only)
constexpr int ATT_SMEM = (O_V + 4 * VHL) * 2;    // 176128 bytes

__global__ void __launch_bounds__(256) attn_kernel(
    const __half* __restrict__ qh, const __half* __restrict__ ql,
    const __half* __restrict__ kh, const __half* __restrict__ vh,
    const float* __restrict__ biasd, float* __restrict__ out)
{
    extern __shared__ __half smh[];
    const int z = blockIdx.y, b = z >> 4, h = z & 15;
    const int q0 = blockIdx.x * 128;
    const int tid = threadIdx.x, wid = tid >> 5, lane = tid & 31;
    const int lr4 = lane >> 2, lc2 = (lane & 3) * 2;
    const float* bd = biasd + h * 4096;
    const size_t zq = (size_t)z * 2048 * 128;
    const size_t zv = (size_t)z * 64 * 2048;
    const int mrow = wid * 16;
    const int aoffQ = (lane & 15) * QSTR + (lane >> 4) * 8;
    const int boffK = ((lane & 7) + ((lane >> 4) << 3)) * QSTR + ((lane >> 3) & 1) * 8;
    const int boffV = ((lane & 7) + ((lane >> 4) << 3)) * VSTR + ((lane >> 3) & 1) * 8;

    auto PREFETCH = [&](int t) {
        __half* bK = smh + O_K + (t & 3) * KHL;
        __half* bV = smh + O_V + (t & 3) * VHL;
        const int k0 = t * 64;
#pragma unroll
        for (int tt = 0; tt < 4; tt++) {
            int i = tid + tt * 256, r = i >> 4, c = (i & 15) * 8;
            cpa16(bK + r * QSTR + c, kh + zq + (size_t)(k0 + r) * 128 + c);
        }
#pragma unroll
        for (int tt = 0; tt < 2; tt++) {
            int i = tid + tt * 256, d = i >> 3, c = (i & 7) * 8;
            cpa16(bV + d * VSTR + c, vh + zv + (size_t)d * 2048 + k0 + c);
        }
        CP_COMMIT();
    };

    // group 0: Q + K/V tile0 ; group 1: tile1 ; group 2: tile2
#pragma unroll
    for (int t = 0; t < 8; t++) {
        int i = tid + t * 256, r = i >> 4, c = (i & 15) * 8;
        cpa16(smh + O_QH + r * QSTR + c, qh + zq + (size_t)(q0 + r) * 128 + c);
        cpa16(smh + O_QL + r * QSTR + c, ql + zq + (size_t)(q0 + r) * 128 + c);
    }
    {
        __half* bK = smh + O_K;
        __half* bV = smh + O_V;
#pragma unroll
        for (int tt = 0; tt < 4; tt++) {
            int i = tid + tt * 256, r = i >> 4, c = (i & 15) * 8;
            cpa16(bK + r * QSTR + c, kh + zq + (size_t)r * 128 + c);
        }
#pragma unroll
        for (int tt = 0; tt < 2; tt++) {
            int i = tid + tt * 256, d = i >> 3, c = (i & 7) * 8;
            cpa16(bV + d * VSTR + c, vh + zv + (size_t)d * 2048 + c);
        }
        CP_COMMIT();
    }
    PREFETCH(1);
    PREFETCH(2);
    CP_WAIT1();          // Q + tiles 0,1 arrived
    __syncthreads();

    // hoist Q fragments (tile-invariant)
    uint32_t qfh[8][4], qfl[8][4];
#pragma unroll
    for (int kd = 0; kd < 8; kd++) {
        ldsm4(qfh[kd], smh + O_QH + mrow * QSTR + kd * 16 + aoffQ);
        ldsm4(qfl[kd], smh + O_QL + mrow * QSTR + kd * 16 + aoffQ);
    }

    float m0 = -INFINITY, m1 = -INFINITY, L0 = 0.f, L1 = 0.f;
    float of[8][4] = {};
    float sfA[8][4], sfB[8][4];

    auto QK = [&](int t, float (&sf)[8][4]) {
        const __half* bK = smh + O_K + (t & 3) * KHL;
#pragma unroll
        for (int nf = 0; nf < 8; nf++)
#pragma unroll
            for (int c = 0; c < 4; c++) sf[nf][c] = 0.f;
#pragma unroll
        for (int kd = 0; kd < 8; kd++) {
#pragma unroll
            for (int np = 0; np < 4; np++) {
                uint32_t b4[4];
                ldsm4(b4, bK + (np * 16) * QSTR + kd * 16 + boffK);
                mma16816(sf[2 * np],     qfh[kd], b4);
                mma16816(sf[2 * np],     qfl[kd], b4);
                mma16816(sf[2 * np + 1], qfh[kd], b4 + 2);
                mma16816(sf[2 * np + 1], qfl[kd], b4 + 2);
            }
        }
    };

    auto SOFTPV = [&](int it, float (&sf)[8][4]) {
        const int k0 = it * 64;
        const __half* bV = smh + O_V + (it & 3) * VHL;
        const int r0 = q0 + mrow + lr4;
        float lm0 = -INFINITY, lm1 = -INFINITY;
#pragma unroll
        for (int nf = 0; nf < 8; nf++) {
            int c = k0 + nf * 8 + lc2;
            sf[nf][0] += bd[c - r0 + 2047];
            sf[nf][1] += bd[c + 1 - r0 + 2047];
            sf[nf][2] += bd[c - (r0 + 8) + 2047];
            sf[nf][3] += bd[c + 1 - (r0 + 8) + 2047];
            lm0 = fmaxf(lm0, fmaxf(sf[nf][0], sf[nf][1]));
            lm1 = fmaxf(lm1, fmaxf(sf[nf][2], sf[nf][3]));
        }
        lm0 = fmaxf(lm0, __shfl_xor_sync(0xffffffffu, lm0, 1));
        lm0 = fmaxf(lm0, __shfl_xor_sync(0xffffffffu, lm0, 2));
        lm1 = fmaxf(lm1, __shfl_xor_sync(0xffffffffu, lm1, 1));
        lm1 = fmaxf(lm1, __shfl_xor_sync(0xffffffffu, lm1, 2));
        float mn0 = fmaxf(m0, lm0), mn1 = fmaxf(m1, lm1);
        float corr0 = __expf(m0 - mn0), corr1 = __expf(m1 - mn1);
        float rs0 = 0.f, rs1 = 0.f;
        uint32_t ap[4][4];
#pragma unroll
        for (int nf = 0; nf < 8; nf++) {
            float p0 = __expf(sf[nf][0] - mn0), p1 = __expf(sf[nf][1] - mn0);
            float p2 = __expf(sf[nf][2] - mn1), p3 = __expf(sf[nf][3] - mn1);
            rs0 += p0 + p1; rs1 += p2 + p3;
            __half2 h01 = __floats2half2_rn(p0, p1);
            __half2 h23 = __floats2half2_rn(p2, p3);
            int kf = nf >> 1, off = (nf & 1) * 2;
            ap[kf][off] = *(uint32_t*)&h01;
            ap[kf][off + 1] = *(uint32_t*)&h23;
        }
        rs0 += __shfl_xor_sync(0xffffffffu, rs0, 1);
        rs0 += __shfl_xor_sync(0xffffffffu, rs0, 2);
        rs1 += __shfl_xor_sync(0xffffffffu, rs1, 1);
        rs1 += __shfl_xor_sync(0xffffffffu, rs1, 2);
        L0 = L0 * corr0 + rs0;
        L1 = L1 * corr1 + rs1;
        m0 = mn0; m1 = mn1;
#pragma unroll
        for (int nf = 0; nf < 8; nf++) {
            of[nf][0] *= corr0; of[nf][1] *= corr0;
            of[nf][2] *= corr1; of[nf][3] *= corr1;
        }
#pragma unroll
        for (int kf = 0; kf < 4; kf++)
#pragma unroll
            for (int np = 0; np < 4; np++) {
                uint32_t b4[4];
                ldsm4(b4, bV + (np * 16) * VSTR + kf * 16 + boffV);
                mma16816(of[2 * np],     ap[kf], b4);
                mma16816(of[2 * np + 1], ap[kf], b4 + 2);
            }
    };

    auto PIPE = [&](int it) {
        if (it + 3 < 32) {
            PREFETCH(it + 3);
            CP_WAIT1();      // tile it+2 arrived
        } else {
            CP_WAIT0();
        }
        __syncthreads();
    };

    QK(0, sfA);
    for (int it = 0; it < 32; it += 2) {
        if (it + 1 < 32) QK(it + 1, sfB);
        SOFTPV(it, sfA);
        PIPE(it);
        if (it + 2 < 32) QK(it + 2, sfA);
        SOFTPV(it + 1, sfB);
        PIPE(it + 1);
    }

    float inv0 = 1.f / L0, inv1 = 1.f / L1;
    const int r0 = q0 + mrow + lr4;
    const size_t ob = (size_t)b * 2048 * 1024 + h * 64;
#pragma unroll
    for (int nf = 0; nf < 8; nf++) {
        int c = nf * 8 + lc2;
        *(float2*)&out[ob + (size_t)r0 * 1024 + c] =
            make_float2(of[nf][0] * inv0, of[nf][1] * inv0);
        *(float2*)&out[ob + (size_t)(r0 + 8) * 1024 + c] =
            make_float2(of[nf][2] * inv1, of[nf][3] * inv1);
    }
}

// ---------------------------------------------------------------------------
extern "C" void kernel_launch(void* const* d_in, const int* in_sizes, int n_in,
                              void* d_out, int out_size)
{
    const float* x          = (const float*)d_in[0];
    const float* pos_embed  = (const float*)d_in[1];
    const float* W_pos_kq   = (const float*)d_in[2];
    const float* W_tok_kqv  = (const float*)d_in[3];
    const float* bias_table = (const float*)d_in[4];
    float* out = (float*)d_out;

    float *tok, *pos, *biasd;
    __half *xh, *peh, *wth, *wtl, *wph, *wpl;
    __half *qh, *ql, *kh, *vh;
    cudaGetSymbolAddress((void**)&tok, g_tok);
    cudaGetSymbolAddress((void**)&pos, g_pos);
    cudaGetSymbolAddress((void**)&biasd, g_bias);
    cudaGetSymbolAddress((void**)&xh, g_xh);
    cudaGetSymbolAddress((void**)&peh, g_peh);
    cudaGetSymbolAddress((void**)&wth, g_wth); cudaGetSymbolAddress((void**)&wtl, g_wtl);
    cudaGetSymbolAddress((void**)&wph, g_wph); cudaGetSymbolAddress((void**)&wpl, g_wpl);
    cudaGetSymbolAddress((void**)&qh, g_qh);   cudaGetSymbolAddress((void**)&ql, g_ql);
    cudaGetSymbolAddress((void**)&kh, g_kh);
    cudaGetSymbolAddress((void**)&vh, g_vh);

    cudaFuncSetAttribute(attn_kernel,
                         cudaFuncAttributeMaxDynamicSharedMemorySize, ATT_SMEM);
    cudaFuncSetAttribute(hgemm_split,
                         cudaFuncAttributeMaxDynamicSharedMemorySize, HG_SMEM);

    // launch 1: pack x + pos_embed to fp16
    pack_all_h<<<(N4X + N4P + 255) / 256, 256>>>(x, pos_embed);
    // launch 2: pack+transpose+split both weights
    pack_splitT_all<<<dim3(160, 32), dim3(32, 8)>>>(W_tok_kqv, W_pos_kq);
    // launches 3-4: projection GEMMs
    hgemm_split<<<dim3(3072 / 128, 4096 / 128), 256, HG_SMEM>>>(
        xh, wth, wtl, tok, 4096, 3072, 1024);
    hgemm_split<<<dim3(2048 / 128, 2048 / 128), 256, HG_SMEM>>>(
        peh, wph, wpl, pos, 2048, 2048, 1024);
    // launch 5: fused Q/K/V pack + bias LUT
    pack_qkv<<<(NQK + NV + NB + 255) / 256, 256>>>(tok, pos, bias_table);
    // launch 6: attention (profiled by ncu -s 5 -c 1)
    attn_kernel<<<dim3(16, 32), 256, ATT_SMEM>>>(qh, ql, kh, vh, biasd, out);
}

// round 9
// speedup vs baseline: 5.1354x; 1.0890x over previous
#include <cuda_runtime.h>
#include <cuda_fp16.h>
#include <math.h>
#include <stdint.h>

#define INV_SCALE 0.08838834764831845f  // 1/sqrt(128)

// ------------------------- static scratch (no cudaMalloc) -------------------
__device__ float  g_bias[16 * 4096];
__device__ float  g_tok[4096UL * 3072];     // [B*S][3D]
__device__ float  g_pos[2048UL * 2048];     // [S][2D]
__device__ __half g_xh[4096UL * 1024];
__device__ __half g_peh[2048UL * 1024];
__device__ __half g_wth[3072UL * 1024], g_wtl[3072UL * 1024];  // W_tok^T
__device__ __half g_wph[2048UL * 1024], g_wpl[2048UL * 1024];  // W_pos^T
__device__ __half g_qh[32UL * 2048 * 128], g_ql[32UL * 2048 * 128];
__device__ __half g_kh[32UL * 2048 * 128];
__device__ __half g_vh[32UL * 64 * 2048];   // V^T per z, hi only

// ---------------------------------------------------------------------------
__device__ __forceinline__ void mma16816(float c[4], const uint32_t a[4],
                                         const uint32_t b[2]) {
    asm volatile(
        "mma.sync.aligned.m16n8k16.row.col.f32.f16.f16.f32 "
        "{%0,%1,%2,%3}, {%4,%5,%6,%7}, {%8,%9}, {%0,%1,%2,%3};\n"
        : "+f"(c[0]), "+f"(c[1]), "+f"(c[2]), "+f"(c[3])
        : "r"(a[0]), "r"(a[1]), "r"(a[2]), "r"(a[3]), "r"(b[0]), "r"(b[1]));
}
__device__ __forceinline__ uint32_t sptr(const void* p) {
    return (uint32_t)__cvta_generic_to_shared(p);
}
__device__ __forceinline__ void ldsm4(uint32_t r[4], const __half* p) {
    asm volatile("ldmatrix.sync.aligned.m8n8.x4.shared.b16 {%0,%1,%2,%3}, [%4];\n"
                 : "=r"(r[0]), "=r"(r[1]), "=r"(r[2]), "=r"(r[3]) : "r"(sptr(p)));
}
__device__ __forceinline__ void cpa16(__half* dst, const __half* src) {
    asm volatile("cp.async.cg.shared.global [%0], [%1], 16;\n"
                 :: "r"(sptr(dst)), "l"(src));
}
#define CP_COMMIT() asm volatile("cp.async.commit_group;\n")
#define CP_WAIT1() asm volatile("cp.async.wait_group 1;\n")
#define CP_WAIT0() asm volatile("cp.async.wait_group 0;\n")
__device__ __forceinline__ void split1(float v, __half& h, __half& l) {
    h = __float2half_rn(v);
    l = __float2half_rn(v - __half2float(h));
}

// ---------------------------------------------------------------------------
// fused: pack x -> xh and pos_embed -> peh (fp16 hi only)
// ---------------------------------------------------------------------------
constexpr int N4X = 4096 * 1024 / 4;   // 1048576
constexpr int N4P = 2048 * 1024 / 4;   // 524288
__global__ void pack_all_h(const float* __restrict__ x,
                           const float* __restrict__ pe) {
    int i = blockIdx.x * blockDim.x + threadIdx.x;
    if (i >= N4X + N4P) return;
    const float* src;
    __half* dst;
    int j;
    if (i < N4X) { src = x;  dst = g_xh;  j = i; }
    else         { src = pe; dst = g_peh; j = i - N4X; }
    float4 v = ((const float4*)src)[j];
    ((__half2*)dst)[2 * j]     = __floats2half2_rn(v.x, v.y);
    ((__half2*)dst)[2 * j + 1] = __floats2half2_rn(v.z, v.w);
}

// ---------------------------------------------------------------------------
// fused pack+transpose+split for both weights: src [1024][N] -> dst [N][1024]
// ---------------------------------------------------------------------------
__global__ void __launch_bounds__(256) pack_splitT_all(
    const float* __restrict__ wt, const float* __restrict__ wp) {
    __shared__ float tile[32][33];
    const float* src;
    __half *hi, *lo;
    int N, bx = blockIdx.x;
    if (bx < 96) { src = wt; hi = g_wth; lo = g_wtl; N = 3072; }
    else         { src = wp; hi = g_wph; lo = g_wpl; N = 2048; bx -= 96; }
    int n0 = bx * 32, k0 = blockIdx.y * 32;
    int tx = threadIdx.x, ty = threadIdx.y;
#pragma unroll
    for (int t = 0; t < 4; t++)
        tile[ty + t * 8][tx] = src[(size_t)(k0 + ty + t * 8) * N + n0 + tx];
    __syncthreads();
#pragma unroll
    for (int t = 0; t < 4; t++) {
        int n = n0 + ty + t * 8;
        float v = tile[tx][ty + t * 8];
        __half h, l;
        split1(v, h, l);
        hi[(size_t)n * 1024 + k0 + tx] = h;
        lo[(size_t)n * 1024 + k0 + tx] = l;
    }
}

// ---------------------------------------------------------------------------
// fused: build Q (split, pre-scaled) / K (hi) / V^T (hi) + bias LUT
// ---------------------------------------------------------------------------
constexpr int NQK = 32 * 2048 * 32;   // 2097152
constexpr int NV  = 32 * 64 * 512;    // 1048576
constexpr int NB  = 16 * 4096;        // 65536
__global__ void pack_qkv(const float* __restrict__ tok, const float* __restrict__ pos,
                         const float* __restrict__ bias_table) {
    int i = blockIdx.x * blockDim.x + threadIdx.x;
    if (i < NQK) {
        int d = (i & 31) * 4, s = (i >> 5) & 2047, z = i >> 16;
        int b = z >> 4, h = z & 15;
        const float* qsrc;
        const float* ksrc;
        if (d < 64) {
            qsrc = &tok[(size_t)(b * 2048 + s) * 3072 + 1024 + h * 64 + d];
            ksrc = &tok[(size_t)(b * 2048 + s) * 3072 + h * 64 + d];
        } else {
            qsrc = &pos[(size_t)s * 2048 + 1024 + h * 64 + (d - 64)];
            ksrc = &pos[(size_t)s * 2048 + h * 64 + (d - 64)];
        }
        float4 qv = *(const float4*)qsrc;
        float4 kv = *(const float4*)ksrc;
        size_t o = ((size_t)z * 2048 + s) * 128 + d;
        __half h0, h1, h2, h3, l0, l1, l2, l3;
        split1(qv.x * INV_SCALE, h0, l0); split1(qv.y * INV_SCALE, h1, l1);
        split1(qv.z * INV_SCALE, h2, l2); split1(qv.w * INV_SCALE, h3, l3);
        *(__half2*)&g_qh[o] = __halves2half2(h0, h1);
        *(__half2*)&g_qh[o + 2] = __halves2half2(h2, h3);
        *(__half2*)&g_ql[o] = __halves2half2(l0, l1);
        *(__half2*)&g_ql[o + 2] = __halves2half2(l2, l3);
        *(__half2*)&g_kh[o]     = __floats2half2_rn(kv.x, kv.y);
        *(__half2*)&g_kh[o + 2] = __floats2half2_rn(kv.z, kv.w);
    } else if (i < NQK + NV) {
        int j = i - NQK;
        int s = (j & 511) * 4, dh = (j >> 9) & 63, z = j >> 15;
        int b = z >> 4, h = z & 15;
        size_t o = ((size_t)z * 64 + dh) * 2048 + s;
#pragma unroll
        for (int t = 0; t < 4; t++) {
            float v = tok[(size_t)(b * 2048 + s + t) * 3072 + 2048 + h * 64 + dh];
            g_vh[o + t] = __float2half_rn(v);
        }
    } else if (i < NQK + NV + NB) {
        int j = i - NQK - NV;
        int h = j >> 12, dd = j & 4095;
        int n = -(dd - 2047);
        int ret = 0;
        if (n < 0) { ret = 16; n = -n; }
        int bucket;
        if (n < 8) bucket = n;
        else {
            float v = logf((float)n / 8.0f) / logf(16.0f) * 8.0f;
            int vi = 8 + (int)v;
            bucket = vi < 15 ? vi : 15;
        }
        g_bias[j] = bias_table[(bucket + ret + 2048) * 16 + h];
    }
}

// ---------------------------------------------------------------------------
// merged 2-term GEMM (both projections in ONE launch):
// blocks [0,768): tok = xh @ (wth+wtl)^T   (M=4096, N=3072)
// blocks [768,1024): pos = peh @ (wph+wpl)^T (M=2048, N=2048)
// 128x128 tile, 8 warps, k-step 32, 3-stage cp.async, 2 CTAs/SM.
// ---------------------------------------------------------------------------
constexpr int HSTR = 40;                        // halves per stage row
constexpr int HG_STG = 128 * HSTR;              // 5120 halves per array
constexpr int HG_STAGE = 3 * HG_STG;            // A, Bh, Bl
constexpr int HG_SMEM = 3 * HG_STAGE * 2;       // 92160 bytes

__global__ void __launch_bounds__(256, 2) hgemm2(
    const __half* __restrict__ At, const __half* __restrict__ Bht,
    const __half* __restrict__ Blt, float* __restrict__ Ct,
    const __half* __restrict__ Ap, const __half* __restrict__ Bhp,
    const __half* __restrict__ Blp, float* __restrict__ Cp)
{
    extern __shared__ __half smg[];
    const int tid = threadIdx.x, wid = tid >> 5, lane = tid & 31;
    const int wm = wid & 1, wn = wid >> 1;
    const __half *A, *Bh, *Bl;
    float* C;
    int N, bx, by;
    {
        int bid = blockIdx.x;
        if (bid < 768) { A = At; Bh = Bht; Bl = Blt; C = Ct; N = 3072;
                         bx = bid % 24; by = bid / 24; }
        else { bid -= 768; A = Ap; Bh = Bhp; Bl = Blp; C = Cp; N = 2048;
               bx = bid % 16; by = bid / 16; }
    }
    const int bm = by * 128, bn = bx * 128;
    // loader: 512 granules of 16B per array; thread covers 2 rows x 4 granules
    const int lrow = tid >> 2, lgc = (tid & 3) * 8;   // row 0..63 pairs
    const __half* pA0 = A + (size_t)(bm + lrow) * 1024 + lgc;
    const __half* pA1 = A + (size_t)(bm + lrow + 64) * 1024 + lgc;
    const __half* pBh0 = Bh + (size_t)(bn + lrow) * 1024 + lgc;
    const __half* pBh1 = Bh + (size_t)(bn + lrow + 64) * 1024 + lgc;
    const __half* pBl0 = Bl + (size_t)(bn + lrow) * 1024 + lgc;
    const __half* pBl1 = Bl + (size_t)(bn + lrow + 64) * 1024 + lgc;
    const int so0 = lrow * HSTR + lgc, so1 = (lrow + 64) * HSTR + lgc;
    const int aoff = (lane & 15) * HSTR + (lane >> 4) * 8;
    const int boff = ((lane & 7) + ((lane >> 4) << 3)) * HSTR + ((lane >> 3) & 1) * 8;
    float acc[4][4][4] = {};

    auto LOAD = [&](int c) {
        __half* st = smg + (c % 3) * HG_STAGE;
        const int k0 = c * 32;
        cpa16(st + so0, pA0 + k0);
        cpa16(st + so1, pA1 + k0);
        cpa16(st + HG_STG + so0, pBh0 + k0);
        cpa16(st + HG_STG + so1, pBh1 + k0);
        cpa16(st + 2 * HG_STG + so0, pBl0 + k0);
        cpa16(st + 2 * HG_STG + so1, pBl1 + k0);
        CP_COMMIT();
    };

    LOAD(0);
    LOAD(1);
    CP_WAIT1();
    __syncthreads();

    for (int kt = 0; kt < 32; kt++) {
        const __half* st = smg + (kt % 3) * HG_STAGE;
#pragma unroll
        for (int kd = 0; kd < 2; kd++) {
            uint32_t af[4][4], bfh[4][2], bfl[4][2];
#pragma unroll
            for (int i = 0; i < 4; i++)
                ldsm4(af[i], st + (wm * 64 + i * 16) * HSTR + kd * 16 + aoff);
#pragma unroll
            for (int j2 = 0; j2 < 2; j2++) {
                uint32_t t4[4];
                ldsm4(t4, st + HG_STG + (wn * 32 + j2 * 16) * HSTR + kd * 16 + boff);
                bfh[2 * j2][0] = t4[0]; bfh[2 * j2][1] = t4[1];
                bfh[2 * j2 + 1][0] = t4[2]; bfh[2 * j2 + 1][1] = t4[3];
                ldsm4(t4, st + 2 * HG_STG + (wn * 32 + j2 * 16) * HSTR + kd * 16 + boff);
                bfl[2 * j2][0] = t4[0]; bfl[2 * j2][1] = t4[1];
                bfl[2 * j2 + 1][0] = t4[2]; bfl[2 * j2 + 1][1] = t4[3];
            }
#pragma unroll
            for (int i = 0; i < 4; i++)
#pragma unroll
                for (int j = 0; j < 4; j++) {
                    mma16816(acc[i][j], af[i], bfh[j]);
                    mma16816(acc[i][j], af[i], bfl[j]);
                }
        }
        if (kt + 2 < 32) {
            LOAD(kt + 2);
            CP_WAIT1();
        } else {
            CP_WAIT0();
        }
        __syncthreads();
    }
#pragma unroll
    for (int i = 0; i < 4; i++)
#pragma unroll
        for (int j = 0; j < 4; j++) {
            int r = bm + wm * 64 + i * 16 + (lane >> 2);
            int c = bn + wn * 32 + j * 8 + (lane & 3) * 2;
            *(float2*)&C[(size_t)r * N + c] = make_float2(acc[i][j][0], acc[i][j][1]);
            *(float2*)&C[(size_t)(r + 8) * N + c] = make_float2(acc[i][j][2], acc[i][j][3]);
        }
}

// ---------------------------------------------------------------------------
// fused flash attention (round-6 proven version): 2-term QK, 1-term PV,
// QK(it+1) before softmax(it), 4-stage cp.async K/V pipeline.
// ---------------------------------------------------------------------------
#define QSTR 136
#define VSTR 72
constexpr int O_QH = 0;
constexpr int O_QL = 128 * QSTR;
constexpr int O_K  = 2 * 128 * QSTR;
constexpr int KHL  = 64 * QSTR;
constexpr int O_V  = O_K + 4 * KHL;
constexpr int VHL  = 64 * VSTR;
constexpr int ATT_SMEM = (O_V + 4 * VHL) * 2;    // 176128 bytes

__global__ void __launch_bounds__(256) attn_kernel(
    const __half* __restrict__ qh, const __half* __restrict__ ql,
    const __half* __restrict__ kh, const __half* __restrict__ vh,
    const float* __restrict__ biasd, float* __restrict__ out)
{
    extern __shared__ __half smh[];
    const int z = blockIdx.y, b = z >> 4, h = z & 15;
    const int q0 = blockIdx.x * 128;
    const int tid = threadIdx.x, wid = tid >> 5, lane = tid & 31;
    const int lr4 = lane >> 2, lc2 = (lane & 3) * 2;
    const float* bd = biasd + h * 4096;
    const size_t zq = (size_t)z * 2048 * 128;
    const size_t zv = (size_t)z * 64 * 2048;
    const int mrow = wid * 16;
    const int aoffQ = (lane & 15) * QSTR + (lane >> 4) * 8;
    const int boffK = ((lane & 7) + ((lane >> 4) << 3)) * QSTR + ((lane >> 3) & 1) * 8;
    const int boffV = ((lane & 7) + ((lane >> 4) << 3)) * VSTR + ((lane >> 3) & 1) * 8;

    auto PREFETCH = [&](int t) {
        __half* bK = smh + O_K + (t & 3) * KHL;
        __half* bV = smh + O_V + (t & 3) * VHL;
        const int k0 = t * 64;
#pragma unroll
        for (int tt = 0; tt < 4; tt++) {
            int i = tid + tt * 256, r = i >> 4, c = (i & 15) * 8;
            cpa16(bK + r * QSTR + c, kh + zq + (size_t)(k0 + r) * 128 + c);
        }
#pragma unroll
        for (int tt = 0; tt < 2; tt++) {
            int i = tid + tt * 256, d = i >> 3, c = (i & 7) * 8;
            cpa16(bV + d * VSTR + c, vh + zv + (size_t)d * 2048 + k0 + c);
        }
        CP_COMMIT();
    };

#pragma unroll
    for (int t = 0; t < 8; t++) {
        int i = tid + t * 256, r = i >> 4, c = (i & 15) * 8;
        cpa16(smh + O_QH + r * QSTR + c, qh + zq + (size_t)(q0 + r) * 128 + c);
        cpa16(smh + O_QL + r * QSTR + c, ql + zq + (size_t)(q0 + r) * 128 + c);
    }
    {
        __half* bK = smh + O_K;
        __half* bV = smh + O_V;
#pragma unroll
        for (int tt = 0; tt < 4; tt++) {
            int i = tid + tt * 256, r = i >> 4, c = (i & 15) * 8;
            cpa16(bK + r * QSTR + c, kh + zq + (size_t)r * 128 + c);
        }
#pragma unroll
        for (int tt = 0; tt < 2; tt++) {
            int i = tid + tt * 256, d = i >> 3, c = (i & 7) * 8;
            cpa16(bV + d * VSTR + c, vh + zv + (size_t)d * 2048 + c);
        }
        CP_COMMIT();
    }
    PREFETCH(1);
    PREFETCH(2);
    CP_WAIT1();
    __syncthreads();

    uint32_t qfh[8][4], qfl[8][4];
#pragma unroll
    for (int kd = 0; kd < 8; kd++) {
        ldsm4(qfh[kd], smh + O_QH + mrow * QSTR + kd * 16 + aoffQ);
        ldsm4(qfl[kd], smh + O_QL + mrow * QSTR + kd * 16 + aoffQ);
    }

    float m0 = -INFINITY, m1 = -INFINITY, L0 = 0.f, L1 = 0.f;
    float of[8][4] = {};
    float sfA[8][4], sfB[8][4];

    auto QK = [&](int t, float (&sf)[8][4]) {
        const __half* bK = smh + O_K + (t & 3) * KHL;
#pragma unroll
        for (int nf = 0; nf < 8; nf++)
#pragma unroll
            for (int c = 0; c < 4; c++) sf[nf][c] = 0.f;
#pragma unroll
        for (int kd = 0; kd < 8; kd++) {
#pragma unroll
            for (int np = 0; np < 4; np++) {
                uint32_t b4[4];
                ldsm4(b4, bK + (np * 16) * QSTR + kd * 16 + boffK);
                mma16816(sf[2 * np],     qfh[kd], b4);
                mma16816(sf[2 * np],     qfl[kd], b4);
                mma16816(sf[2 * np + 1], qfh[kd], b4 + 2);
                mma16816(sf[2 * np + 1], qfl[kd], b4 + 2);
            }
        }
    };

    auto SOFTPV = [&](int it, float (&sf)[8][4]) {
        const int k0 = it * 64;
        const __half* bV = smh + O_V + (it & 3) * VHL;
        const int r0 = q0 + mrow + lr4;
        float lm0 = -INFINITY, lm1 = -INFINITY;
#pragma unroll
        for (int nf = 0; nf < 8; nf++) {
            int c = k0 + nf * 8 + lc2;
            sf[nf][0] += bd[c - r0 + 2047];
            sf[nf][1] += bd[c + 1 - r0 + 2047];
            sf[nf][2] += bd[c - (r0 + 8) + 2047];
            sf[nf][3] += bd[c + 1 - (r0 + 8) + 2047];
            lm0 = fmaxf(lm0, fmaxf(sf[nf][0], sf[nf][1]));
            lm1 = fmaxf(lm1, fmaxf(sf[nf][2], sf[nf][3]));
        }
        lm0 = fmaxf(lm0, __shfl_xor_sync(0xffffffffu, lm0, 1));
        lm0 = fmaxf(lm0, __shfl_xor_sync(0xffffffffu, lm0, 2));
        lm1 = fmaxf(lm1, __shfl_xor_sync(0xffffffffu, lm1, 1));
        lm1 = fmaxf(lm1, __shfl_xor_sync(0xffffffffu, lm1, 2));
        float mn0 = fmaxf(m0, lm0), mn1 = fmaxf(m1, lm1);
        float corr0 = __expf(m0 - mn0), corr1 = __expf(m1 - mn1);
        float rs0 = 0.f, rs1 = 0.f;
        uint32_t ap[4][4];
#pragma unroll
        for (int nf = 0; nf < 8; nf++) {
            float p0 = __expf(sf[nf][0] - mn0), p1 = __expf(sf[nf][1] - mn0);
            float p2 = __expf(sf[nf][2] - mn1), p3 = __expf(sf[nf][3] - mn1);
            rs0 += p0 + p1; rs1 += p2 + p3;
            __half2 h01 = __floats2half2_rn(p0, p1);
            __half2 h23 = __floats2half2_rn(p2, p3);
            int kf = nf >> 1, off = (nf & 1) * 2;
            ap[kf][off] = *(uint32_t*)&h01;
            ap[kf][off + 1] = *(uint32_t*)&h23;
        }
        rs0 += __shfl_xor_sync(0xffffffffu, rs0, 1);
        rs0 += __shfl_xor_sync(0xffffffffu, rs0, 2);
        rs1 += __shfl_xor_sync(0xffffffffu, rs1, 1);
        rs1 += __shfl_xor_sync(0xffffffffu, rs1, 2);
        L0 = L0 * corr0 + rs0;
        L1 = L1 * corr1 + rs1;
        m0 = mn0; m1 = mn1;
#pragma unroll
        for (int nf = 0; nf < 8; nf++) {
            of[nf][0] *= corr0; of[nf][1] *= corr0;
            of[nf][2] *= corr1; of[nf][3] *= corr1;
        }
#pragma unroll
        for (int kf = 0; kf < 4; kf++)
#pragma unroll
            for (int np = 0; np < 4; np++) {
                uint32_t b4[4];
                ldsm4(b4, bV + (np * 16) * VSTR + kf * 16 + boffV);
                mma16816(of[2 * np],     ap[kf], b4);
                mma16816(of[2 * np + 1], ap[kf], b4 + 2);
            }
    };

    auto PIPE = [&](int it) {
        if (it + 3 < 32) {
            PREFETCH(it + 3);
            CP_WAIT1();
        } else {
            CP_WAIT0();
        }
        __syncthreads();
    };

    QK(0, sfA);
    for (int it = 0; it < 32; it += 2) {
        if (it + 1 < 32) QK(it + 1, sfB);
        SOFTPV(it, sfA);
        PIPE(it);
        if (it + 2 < 32) QK(it + 2, sfA);
        SOFTPV(it + 1, sfB);
        PIPE(it + 1);
    }

    float inv0 = 1.f / L0, inv1 = 1.f / L1;
    const int r0 = q0 + mrow + lr4;
    const size_t ob = (size_t)b * 2048 * 1024 + h * 64;
#pragma unroll
    for (int nf = 0; nf < 8; nf++) {
        int c = nf * 8 + lc2;
        *(float2*)&out[ob + (size_t)r0 * 1024 + c] =
            make_float2(of[nf][0] * inv0, of[nf][1] * inv0);
        *(float2*)&out[ob + (size_t)(r0 + 8) * 1024 + c] =
            make_float2(of[nf][2] * inv1, of[nf][3] * inv1);
    }
}

// ---------------------------------------------------------------------------
extern "C" void kernel_launch(void* const* d_in, const int* in_sizes, int n_in,
                              void* d_out, int out_size)
{
    const float* x          = (const float*)d_in[0];
    const float* pos_embed  = (const float*)d_in[1];
    const float* W_pos_kq   = (const float*)d_in[2];
    const float* W_tok_kqv  = (const float*)d_in[3];
    const float* bias_table = (const float*)d_in[4];
    float* out = (float*)d_out;

    float *tok, *pos, *biasd;
    __half *xh, *peh, *wth, *wtl, *wph, *wpl;
    __half *qh, *ql, *kh, *vh;
    cudaGetSymbolAddress((void**)&tok, g_tok);
    cudaGetSymbolAddress((void**)&pos, g_pos);
    cudaGetSymbolAddress((void**)&biasd, g_bias);
    cudaGetSymbolAddress((void**)&xh, g_xh);
    cudaGetSymbolAddress((void**)&peh, g_peh);
    cudaGetSymbolAddress((void**)&wth, g_wth); cudaGetSymbolAddress((void**)&wtl, g_wtl);
    cudaGetSymbolAddress((void**)&wph, g_wph); cudaGetSymbolAddress((void**)&wpl, g_wpl);
    cudaGetSymbolAddress((void**)&qh, g_qh);   cudaGetSymbolAddress((void**)&ql, g_ql);
    cudaGetSymbolAddress((void**)&kh, g_kh);
    cudaGetSymbolAddress((void**)&vh, g_vh);

    cudaFuncSetAttribute(attn_kernel,
                         cudaFuncAttributeMaxDynamicSharedMemorySize, ATT_SMEM);
    cudaFuncSetAttribute(hgemm2,
                         cudaFuncAttributeMaxDynamicSharedMemorySize, HG_SMEM);

    pack_all_h<<<(N4X + N4P + 255) / 256, 256>>>(x, pos_embed);
    pack_splitT_all<<<dim3(160, 32), dim3(32, 8)>>>(W_tok_kqv, W_pos_kq);
    // both projection GEMMs in one launch
    hgemm2<<<1024, 256, HG_SMEM>>>(xh, wth, wtl, tok, peh, wph, wpl, pos);
    pack_qkv<<<(NQK + NV + NB + 255) / 256, 256>>>(tok, pos, bias_table);
    attn_kernel<<<dim3(16, 32), 256, ATT_SMEM>>>(qh, ql, kh, vh, biasd, out);
}

// round 10
// speedup vs baseline: 5.4381x; 1.0589x over previous
#include <cuda_runtime.h>
#include <cuda_fp16.h>
#include <math.h>
#include <stdint.h>

#define INV_SCALE 0.08838834764831845f  // 1/sqrt(128)

// ------------------------- static scratch (no cudaMalloc) -------------------
__device__ float  g_bias[16 * 4096];
__device__ __half g_xh[4096UL * 1024];
__device__ __half g_peh[2048UL * 1024];
__device__ __half g_wth[3072UL * 1024], g_wtl[3072UL * 1024];  // W_tok^T
__device__ __half g_wph[2048UL * 1024], g_wpl[2048UL * 1024];  // W_pos^T
__device__ __half g_qh[32UL * 2048 * 128], g_ql[32UL * 2048 * 128];
__device__ __half g_kh[32UL * 2048 * 128];
__device__ __half g_vh[32UL * 2048 * 64];   // V per z: [s][64] natural layout

// ---------------------------------------------------------------------------
__device__ __forceinline__ void mma16816(float c[4], const uint32_t a[4],
                                         const uint32_t b[2]) {
    asm volatile(
        "mma.sync.aligned.m16n8k16.row.col.f32.f16.f16.f32 "
        "{%0,%1,%2,%3}, {%4,%5,%6,%7}, {%8,%9}, {%0,%1,%2,%3};\n"
        : "+f"(c[0]), "+f"(c[1]), "+f"(c[2]), "+f"(c[3])
        : "r"(a[0]), "r"(a[1]), "r"(a[2]), "r"(a[3]), "r"(b[0]), "r"(b[1]));
}
__device__ __forceinline__ uint32_t sptr(const void* p) {
    return (uint32_t)__cvta_generic_to_shared(p);
}
__device__ __forceinline__ void ldsm4(uint32_t r[4], const __half* p) {
    asm volatile("ldmatrix.sync.aligned.m8n8.x4.shared.b16 {%0,%1,%2,%3}, [%4];\n"
                 : "=r"(r[0]), "=r"(r[1]), "=r"(r[2]), "=r"(r[3]) : "r"(sptr(p)));
}
__device__ __forceinline__ void ldsm4t(uint32_t r[4], const __half* p) {
    asm volatile("ldmatrix.sync.aligned.m8n8.x4.trans.shared.b16 {%0,%1,%2,%3}, [%4];\n"
                 : "=r"(r[0]), "=r"(r[1]), "=r"(r[2]), "=r"(r[3]) : "r"(sptr(p)));
}
__device__ __forceinline__ void cpa16(__half* dst, const __half* src) {
    asm volatile("cp.async.cg.shared.global [%0], [%1], 16;\n"
                 :: "r"(sptr(dst)), "l"(src));
}
#define CP_COMMIT() asm volatile("cp.async.commit_group;\n")
#define CP_WAIT1() asm volatile("cp.async.wait_group 1;\n")
#define CP_WAIT0() asm volatile("cp.async.wait_group 0;\n")
__device__ __forceinline__ void split1(float v, __half& h, __half& l) {
    h = __float2half_rn(v);
    l = __float2half_rn(v - __half2float(h));
}

// ---------------------------------------------------------------------------
// fused: pack x -> xh, pos_embed -> peh (fp16 hi only), and T5 bias LUT
// ---------------------------------------------------------------------------
constexpr int N4X = 4096 * 1024 / 4;   // 1048576
constexpr int N4P = 2048 * 1024 / 4;   // 524288
constexpr int NB  = 16 * 4096;         // 65536
__global__ void pack_all_h(const float* __restrict__ x,
                           const float* __restrict__ pe,
                           const float* __restrict__ bias_table) {
    int i = blockIdx.x * blockDim.x + threadIdx.x;
    if (i < N4X + N4P) {
        const float* src;
        __half* dst;
        int j;
        if (i < N4X) { src = x;  dst = g_xh;  j = i; }
        else         { src = pe; dst = g_peh; j = i - N4X; }
        float4 v = ((const float4*)src)[j];
        ((__half2*)dst)[2 * j]     = __floats2half2_rn(v.x, v.y);
        ((__half2*)dst)[2 * j + 1] = __floats2half2_rn(v.z, v.w);
    } else if (i < N4X + N4P + NB) {
        int j = i - N4X - N4P;
        int h = j >> 12, dd = j & 4095;
        int n = -(dd - 2047);
        int ret = 0;
        if (n < 0) { ret = 16; n = -n; }
        int bucket;
        if (n < 8) bucket = n;
        else {
            float v = logf((float)n / 8.0f) / logf(16.0f) * 8.0f;
            int vi = 8 + (int)v;
            bucket = vi < 15 ? vi : 15;
        }
        g_bias[j] = bias_table[(bucket + ret + 2048) * 16 + h];
    }
}

// ---------------------------------------------------------------------------
// fused pack+transpose+split for both weights: src [1024][N] -> dst [N][1024]
// ---------------------------------------------------------------------------
__global__ void __launch_bounds__(256) pack_splitT_all(
    const float* __restrict__ wt, const float* __restrict__ wp) {
    __shared__ float tile[32][33];
    const float* src;
    __half *hi, *lo;
    int N, bx = blockIdx.x;
    if (bx < 96) { src = wt; hi = g_wth; lo = g_wtl; N = 3072; }
    else         { src = wp; hi = g_wph; lo = g_wpl; N = 2048; bx -= 96; }
    int n0 = bx * 32, k0 = blockIdx.y * 32;
    int tx = threadIdx.x, ty = threadIdx.y;
#pragma unroll
    for (int t = 0; t < 4; t++)
        tile[ty + t * 8][tx] = src[(size_t)(k0 + ty + t * 8) * N + n0 + tx];
    __syncthreads();
#pragma unroll
    for (int t = 0; t < 4; t++) {
        int n = n0 + ty + t * 8;
        float v = tile[tx][ty + t * 8];
        __half h, l;
        split1(v, h, l);
        hi[(size_t)n * 1024 + k0 + tx] = h;
        lo[(size_t)n * 1024 + k0 + tx] = l;
    }
}

// ---------------------------------------------------------------------------
// merged 2-term GEMM with FUSED Q/K/V epilogue (no fp32 intermediate):
// blocks [0,768): tok proj (M=4096, N=3072): key->kh[:, :64], query->qh/ql,
//                 value->vh [z][s][64]
// blocks [768,1024): pos proj (M=2048, N=2048): -> kh/qh/ql [:, 64:128], both b
// 128x128 tile, 8 warps, k-step 32, 3-stage cp.async, 2 CTAs/SM.
// ---------------------------------------------------------------------------
constexpr int HSTR = 40;
constexpr int HG_STG = 128 * HSTR;
constexpr int HG_STAGE = 3 * HG_STG;
constexpr int HG_SMEM = 3 * HG_STAGE * 2;       // 92160 bytes

__global__ void __launch_bounds__(256, 2) hgemm2(
    const __half* __restrict__ At, const __half* __restrict__ Bht,
    const __half* __restrict__ Blt,
    const __half* __restrict__ Ap, const __half* __restrict__ Bhp,
    const __half* __restrict__ Blp)
{
    extern __shared__ __half smg[];
    const int tid = threadIdx.x, wid = tid >> 5, lane = tid & 31;
    const int wm = wid & 1, wn = wid >> 1;
    const __half *A, *Bh, *Bl;
    int bx, by, isTok;
    {
        int bid = blockIdx.x;
        if (bid < 768) { A = At; Bh = Bht; Bl = Blt; isTok = 1;
                         bx = bid % 24; by = bid / 24; }
        else { bid -= 768; A = Ap; Bh = Bhp; Bl = Blp; isTok = 0;
               bx = bid % 16; by = bid / 16; }
    }
    const int bm = by * 128, bn = bx * 128;
    const int lrow = tid >> 2, lgc = (tid & 3) * 8;
    const __half* pA0 = A + (size_t)(bm + lrow) * 1024 + lgc;
    const __half* pA1 = A + (size_t)(bm + lrow + 64) * 1024 + lgc;
    const __half* pBh0 = Bh + (size_t)(bn + lrow) * 1024 + lgc;
    const __half* pBh1 = Bh + (size_t)(bn + lrow + 64) * 1024 + lgc;
    const __half* pBl0 = Bl + (size_t)(bn + lrow) * 1024 + lgc;
    const __half* pBl1 = Bl + (size_t)(bn + lrow + 64) * 1024 + lgc;
    const int so0 = lrow * HSTR + lgc, so1 = (lrow + 64) * HSTR + lgc;
    const int aoff = (lane & 15) * HSTR + (lane >> 4) * 8;
    const int boff = ((lane & 7) + ((lane >> 4) << 3)) * HSTR + ((lane >> 3) & 1) * 8;
    float acc[4][4][4] = {};

    auto LOAD = [&](int c) {
        __half* st = smg + (c % 3) * HG_STAGE;
        const int k0 = c * 32;
        cpa16(st + so0, pA0 + k0);
        cpa16(st + so1, pA1 + k0);
        cpa16(st + HG_STG + so0, pBh0 + k0);
        cpa16(st + HG_STG + so1, pBh1 + k0);
        cpa16(st + 2 * HG_STG + so0, pBl0 + k0);
        cpa16(st + 2 * HG_STG + so1, pBl1 + k0);
        CP_COMMIT();
    };

    LOAD(0);
    LOAD(1);
    CP_WAIT1();
    __syncthreads();

    for (int kt = 0; kt < 32; kt++) {
        const __half* st = smg + (kt % 3) * HG_STAGE;
#pragma unroll
        for (int kd = 0; kd < 2; kd++) {
            uint32_t af[4][4], bfh[4][2], bfl[4][2];
#pragma unroll
            for (int i = 0; i < 4; i++)
                ldsm4(af[i], st + (wm * 64 + i * 16) * HSTR + kd * 16 + aoff);
#pragma unroll
            for (int j2 = 0; j2 < 2; j2++) {
                uint32_t t4[4];
                ldsm4(t4, st + HG_STG + (wn * 32 + j2 * 16) * HSTR + kd * 16 + boff);
                bfh[2 * j2][0] = t4[0]; bfh[2 * j2][1] = t4[1];
                bfh[2 * j2 + 1][0] = t4[2]; bfh[2 * j2 + 1][1] = t4[3];
                ldsm4(t4, st + 2 * HG_STG + (wn * 32 + j2 * 16) * HSTR + kd * 16 + boff);
                bfl[2 * j2][0] = t4[0]; bfl[2 * j2][1] = t4[1];
                bfl[2 * j2 + 1][0] = t4[2]; bfl[2 * j2 + 1][1] = t4[3];
            }
#pragma unroll
            for (int i = 0; i < 4; i++)
#pragma unroll
                for (int j = 0; j < 4; j++) {
                    mma16816(acc[i][j], af[i], bfh[j]);
                    mma16816(acc[i][j], af[i], bfl[j]);
                }
        }
        if (kt + 2 < 32) {
            LOAD(kt + 2);
            CP_WAIT1();
        } else {
            CP_WAIT0();
        }
        __syncthreads();
    }

    // ---- fused epilogue: write Q/K/V directly in attention layout ----
    if (isTok) {
#pragma unroll
        for (int i = 0; i < 4; i++) {
            int r = bm + wm * 64 + i * 16 + (lane >> 2);
            int bb = r >> 11, s = r & 2047;
#pragma unroll
            for (int j = 0; j < 4; j++) {
                int c = bn + wn * 32 + j * 8 + (lane & 3) * 2;
                int region = c >> 10, col = c & 1023;
                int h = col >> 6, dh = col & 63;
                size_t zs = (size_t)(bb * 16 + h) * 2048;
                if (region == 0) {
                    *(__half2*)&g_kh[(zs + s) * 128 + dh] =
                        __floats2half2_rn(acc[i][j][0], acc[i][j][1]);
                    *(__half2*)&g_kh[(zs + s + 8) * 128 + dh] =
                        __floats2half2_rn(acc[i][j][2], acc[i][j][3]);
                } else if (region == 1) {
                    __half h0, l0, h1, l1, h2, l2, h3, l3;
                    split1(acc[i][j][0] * INV_SCALE, h0, l0);
                    split1(acc[i][j][1] * INV_SCALE, h1, l1);
                    split1(acc[i][j][2] * INV_SCALE, h2, l2);
                    split1(acc[i][j][3] * INV_SCALE, h3, l3);
                    *(__half2*)&g_qh[(zs + s) * 128 + dh]     = __halves2half2(h0, h1);
                    *(__half2*)&g_ql[(zs + s) * 128 + dh]     = __halves2half2(l0, l1);
                    *(__half2*)&g_qh[(zs + s + 8) * 128 + dh] = __halves2half2(h2, h3);
                    *(__half2*)&g_ql[(zs + s + 8) * 128 + dh] = __halves2half2(l2, l3);
                } else {
                    *(__half2*)&g_vh[(zs + s) * 64 + dh] =
                        __floats2half2_rn(acc[i][j][0], acc[i][j][1]);
                    *(__half2*)&g_vh[(zs + s + 8) * 64 + dh] =
                        __floats2half2_rn(acc[i][j][2], acc[i][j][3]);
                }
            }
        }
    } else {
#pragma unroll
        for (int i = 0; i < 4; i++) {
            int s = bm + wm * 64 + i * 16 + (lane >> 2);
#pragma unroll
            for (int j = 0; j < 4; j++) {
                int c = bn + wn * 32 + j * 8 + (lane & 3) * 2;
                int region = c >> 10, col = c & 1023;
                int h = col >> 6, dh = 64 + (col & 63);
                if (region == 0) {
                    __half2 v01 = __floats2half2_rn(acc[i][j][0], acc[i][j][1]);
                    __half2 v23 = __floats2half2_rn(acc[i][j][2], acc[i][j][3]);
#pragma unroll
                    for (int bb = 0; bb < 2; bb++) {
                        size_t zs = (size_t)(bb * 16 + h) * 2048;
                        *(__half2*)&g_kh[(zs + s) * 128 + dh]     = v01;
                        *(__half2*)&g_kh[(zs + s + 8) * 128 + dh] = v23;
                    }
                } else {
                    __half h0, l0, h1, l1, h2, l2, h3, l3;
                    split1(acc[i][j][0] * INV_SCALE, h0, l0);
                    split1(acc[i][j][1] * INV_SCALE, h1, l1);
                    split1(acc[i][j][2] * INV_SCALE, h2, l2);
                    split1(acc[i][j][3] * INV_SCALE, h3, l3);
                    __half2 qh01 = __halves2half2(h0, h1), ql01 = __halves2half2(l0, l1);
                    __half2 qh23 = __halves2half2(h2, h3), ql23 = __halves2half2(l2, l3);
#pragma unroll
                    for (int bb = 0; bb < 2; bb++) {
                        size_t zs = (size_t)(bb * 16 + h) * 2048;
                        *(__half2*)&g_qh[(zs + s) * 128 + dh]     = qh01;
                        *(__half2*)&g_ql[(zs + s) * 128 + dh]     = ql01;
                        *(__half2*)&g_qh[(zs + s + 8) * 128 + dh] = qh23;
                        *(__half2*)&g_ql[(zs + s + 8) * 128 + dh] = ql23;
                    }
                }
            }
        }
    }
}

// ---------------------------------------------------------------------------
// fused flash attention: 2-term QK (pre-scaled Q), 1-term PV with V in
// natural [s][64] layout via ldmatrix.trans. QK(it+1) before softmax(it),
// 4-stage cp.async K/V pipeline. block = (q-tile 128, z), 8 warps.
// ---------------------------------------------------------------------------
#define QSTR 136
#define VSTR 72
constexpr int O_QH = 0;
constexpr int O_QL = 128 * QSTR;
constexpr int O_K  = 2 * 128 * QSTR;
constexpr int KHL  = 64 * QSTR;
constexpr int O_V  = O_K + 4 * KHL;
constexpr int VHL  = 64 * VSTR;
constexpr int ATT_SMEM = (O_V + 4 * VHL) * 2;    // 176128 bytes

__global__ void __launch_bounds__(256) attn_kernel(
    const __half* __restrict__ qh, const __half* __restrict__ ql,
    const __half* __restrict__ kh, const __half* __restrict__ vh,
    const float* __restrict__ biasd, float* __restrict__ out)
{
    extern __shared__ __half smh[];
    const int z = blockIdx.y, b = z >> 4, h = z & 15;
    const int q0 = blockIdx.x * 128;
    const int tid = threadIdx.x, wid = tid >> 5, lane = tid & 31;
    const int lr4 = lane >> 2, lc2 = (lane & 3) * 2;
    const float* bd = biasd + h * 4096;
    const size_t zq = (size_t)z * 2048 * 128;
    const size_t zv = (size_t)z * 2048 * 64;
    const int mrow = wid * 16;
    const int aoffQ = (lane & 15) * QSTR + (lane >> 4) * 8;
    const int boffK = ((lane & 7) + ((lane >> 4) << 3)) * QSTR + ((lane >> 3) & 1) * 8;
    // trans-ldmatrix offsets for V [s][64]: row = (l&7) + ((l>>3)&1)*8 (k),
    // col = (l>>4)*8 (n)
    const int boffVt = ((lane & 7) + ((lane >> 3) & 1) * 8) * VSTR + (lane >> 4) * 8;

    auto PREFETCH = [&](int t) {
        __half* bK = smh + O_K + (t & 3) * KHL;
        __half* bV = smh + O_V + (t & 3) * VHL;
        const int k0 = t * 64;
#pragma unroll
        for (int tt = 0; tt < 4; tt++) {
            int i = tid + tt * 256, r = i >> 4, c = (i & 15) * 8;
            cpa16(bK + r * QSTR + c, kh + zq + (size_t)(k0 + r) * 128 + c);
        }
#pragma unroll
        for (int tt = 0; tt < 2; tt++) {
            int i = tid + tt * 256, r = i >> 3, c = (i & 7) * 8;
            cpa16(bV + r * VSTR + c, vh + zv + (size_t)(k0 + r) * 64 + c);
        }
        CP_COMMIT();
    };

#pragma unroll
    for (int t = 0; t < 8; t++) {
        int i = tid + t * 256, r = i >> 4, c = (i & 15) * 8;
        cpa16(smh + O_QH + r * QSTR + c, qh + zq + (size_t)(q0 + r) * 128 + c);
        cpa16(smh + O_QL + r * QSTR + c, ql + zq + (size_t)(q0 + r) * 128 + c);
    }
    {
        __half* bK = smh + O_K;
        __half* bV = smh + O_V;
#pragma unroll
        for (int tt = 0; tt < 4; tt++) {
            int i = tid + tt * 256, r = i >> 4, c = (i & 15) * 8;
            cpa16(bK + r * QSTR + c, kh + zq + (size_t)r * 128 + c);
        }
#pragma unroll
        for (int tt = 0; tt < 2; tt++) {
            int i = tid + tt * 256, r = i >> 3, c = (i & 7) * 8;
            cpa16(bV + r * VSTR + c, vh + zv + (size_t)r * 64 + c);
        }
        CP_COMMIT();
    }
    PREFETCH(1);
    PREFETCH(2);
    CP_WAIT1();
    __syncthreads();

    uint32_t qfh[8][4], qfl[8][4];
#pragma unroll
    for (int kd = 0; kd < 8; kd++) {
        ldsm4(qfh[kd], smh + O_QH + mrow * QSTR + kd * 16 + aoffQ);
        ldsm4(qfl[kd], smh + O_QL + mrow * QSTR + kd * 16 + aoffQ);
    }

    float m0 = -INFINITY, m1 = -INFINITY, L0 = 0.f, L1 = 0.f;
    float of[8][4] = {};
    float sfA[8][4], sfB[8][4];

    auto QK = [&](int t, float (&sf)[8][4]) {
        const __half* bK = smh + O_K + (t & 3) * KHL;
#pragma unroll
        for (int nf = 0; nf < 8; nf++)
#pragma unroll
            for (int c = 0; c < 4; c++) sf[nf][c] = 0.f;
#pragma unroll
        for (int kd = 0; kd < 8; kd++) {
#pragma unroll
            for (int np = 0; np < 4; np++) {
                uint32_t b4[4];
                ldsm4(b4, bK + (np * 16) * QSTR + kd * 16 + boffK);
                mma16816(sf[2 * np],     qfh[kd], b4);
                mma16816(sf[2 * np],     qfl[kd], b4);
                mma16816(sf[2 * np + 1], qfh[kd], b4 + 2);
                mma16816(sf[2 * np + 1], qfl[kd], b4 + 2);
            }
        }
    };

    auto SOFTPV = [&](int it, float (&sf)[8][4]) {
        const int k0 = it * 64;
        const __half* bV = smh + O_V + (it & 3) * VHL;
        const int r0 = q0 + mrow + lr4;
        float lm0 = -INFINITY, lm1 = -INFINITY;
#pragma unroll
        for (int nf = 0; nf < 8; nf++) {
            int c = k0 + nf * 8 + lc2;
            sf[nf][0] += bd[c - r0 + 2047];
            sf[nf][1] += bd[c + 1 - r0 + 2047];
            sf[nf][2] += bd[c - (r0 + 8) + 2047];
            sf[nf][3] += bd[c + 1 - (r0 + 8) + 2047];
            lm0 = fmaxf(lm0, fmaxf(sf[nf][0], sf[nf][1]));
            lm1 = fmaxf(lm1, fmaxf(sf[nf][2], sf[nf][3]));
        }
        lm0 = fmaxf(lm0, __shfl_xor_sync(0xffffffffu, lm0, 1));
        lm0 = fmaxf(lm0, __shfl_xor_sync(0xffffffffu, lm0, 2));
        lm1 = fmaxf(lm1, __shfl_xor_sync(0xffffffffu, lm1, 1));
        lm1 = fmaxf(lm1, __shfl_xor_sync(0xffffffffu, lm1, 2));
        float mn0 = fmaxf(m0, lm0), mn1 = fmaxf(m1, lm1);
        float corr0 = __expf(m0 - mn0), corr1 = __expf(m1 - mn1);
        float rs0 = 0.f, rs1 = 0.f;
        uint32_t ap[4][4];
#pragma unroll
        for (int nf = 0; nf < 8; nf++) {
            float p0 = __expf(sf[nf][0] - mn0), p1 = __expf(sf[nf][1] - mn0);
            float p2 = __expf(sf[nf][2] - mn1), p3 = __expf(sf[nf][3] - mn1);
            rs0 += p0 + p1; rs1 += p2 + p3;
            __half2 h01 = __floats2half2_rn(p0, p1);
            __half2 h23 = __floats2half2_rn(p2, p3);
            int kf = nf >> 1, off = (nf & 1) * 2;
            ap[kf][off] = *(uint32_t*)&h01;
            ap[kf][off + 1] = *(uint32_t*)&h23;
        }
        rs0 += __shfl_xor_sync(0xffffffffu, rs0, 1);
        rs0 += __shfl_xor_sync(0xffffffffu, rs0, 2);
        rs1 += __shfl_xor_sync(0xffffffffu, rs1, 1);
        rs1 += __shfl_xor_sync(0xffffffffu, rs1, 2);
        L0 = L0 * corr0 + rs0;
        L1 = L1 * corr1 + rs1;
        m0 = mn0; m1 = mn1;
#pragma unroll
        for (int nf = 0; nf < 8; nf++) {
            of[nf][0] *= corr0; of[nf][1] *= corr0;
            of[nf][2] *= corr1; of[nf][3] *= corr1;
        }
#pragma unroll
        for (int kf = 0; kf < 4; kf++)
#pragma unroll
            for (int np = 0; np < 4; np++) {
                uint32_t b4[4];
                ldsm4t(b4, bV + (kf * 16) * VSTR + np * 16 + boffVt);
                mma16816(of[2 * np],     ap[kf], b4);
                mma16816(of[2 * np + 1], ap[kf], b4 + 2);
            }
    };

    auto PIPE = [&](int it) {
        if (it + 3 < 32) {
            PREFETCH(it + 3);
            CP_WAIT1();
        } else {
            CP_WAIT0();
        }
        __syncthreads();
    };

    QK(0, sfA);
    for (int it = 0; it < 32; it += 2) {
        if (it + 1 < 32) QK(it + 1, sfB);
        SOFTPV(it, sfA);
        PIPE(it);
        if (it + 2 < 32) QK(it + 2, sfA);
        SOFTPV(it + 1, sfB);
        PIPE(it + 1);
    }

    float inv0 = 1.f / L0, inv1 = 1.f / L1;
    const int r0 = q0 + mrow + lr4;
    const size_t ob = (size_t)b * 2048 * 1024 + h * 64;
#pragma unroll
    for (int nf = 0; nf < 8; nf++) {
        int c = nf * 8 + lc2;
        *(float2*)&out[ob + (size_t)r0 * 1024 + c] =
            make_float2(of[nf][0] * inv0, of[nf][1] * inv0);
        *(float2*)&out[ob + (size_t)(r0 + 8) * 1024 + c] =
            make_float2(of[nf][2] * inv1, of[nf][3] * inv1);
    }
}

// ---------------------------------------------------------------------------
extern "C" void kernel_launch(void* const* d_in, const int* in_sizes, int n_in,
                              void* d_out, int out_size)
{
    const float* x          = (const float*)d_in[0];
    const float* pos_embed  = (const float*)d_in[1];
    const float* W_pos_kq   = (const float*)d_in[2];
    const float* W_tok_kqv  = (const float*)d_in[3];
    const float* bias_table = (const float*)d_in[4];
    float* out = (float*)d_out;

    float* biasd;
    __half *xh, *peh, *wth, *wtl, *wph, *wpl;
    __half *qh, *ql, *kh, *vh;
    cudaGetSymbolAddress((void**)&biasd, g_bias);
    cudaGetSymbolAddress((void**)&xh, g_xh);
    cudaGetSymbolAddress((void**)&peh, g_peh);
    cudaGetSymbolAddress((void**)&wth, g_wth); cudaGetSymbolAddress((void**)&wtl, g_wtl);
    cudaGetSymbolAddress((void**)&wph, g_wph); cudaGetSymbolAddress((void**)&wpl, g_wpl);
    cudaGetSymbolAddress((void**)&qh, g_qh);   cudaGetSymbolAddress((void**)&ql, g_ql);
    cudaGetSymbolAddress((void**)&kh, g_kh);
    cudaGetSymbolAddress((void**)&vh, g_vh);

    cudaFuncSetAttribute(attn_kernel,
                         cudaFuncAttributeMaxDynamicSharedMemorySize, ATT_SMEM);
    cudaFuncSetAttribute(hgemm2,
                         cudaFuncAttributeMaxDynamicSharedMemorySize, HG_SMEM);

    pack_all_h<<<(N4X + N4P + NB + 255) / 256, 256>>>(x, pos_embed, bias_table);
    pack_splitT_all<<<dim3(160, 32), dim3(32, 8)>>>(W_tok_kqv, W_pos_kq);
    // both projection GEMMs + fused Q/K/V pack in one launch
    hgemm2<<<1024, 256, HG_SMEM>>>(xh, wth, wtl, peh, wph, wpl);
    attn_kernel<<<dim3(16, 32), 256, ATT_SMEM>>>(qh, ql, kh, vh, biasd, out);
}

// round 11
// speedup vs baseline: 6.2588x; 1.1509x over previous
#include <cuda_runtime.h>
#include <cuda_fp16.h>
#include <math.h>
#include <stdint.h>

#define INV_SCALE 0.08838834764831845f  // 1/sqrt(128)

// ------------------------- static scratch (no cudaMalloc) -------------------
__device__ float  g_bias[16 * 4096];
__device__ __half g_xh[4096UL * 1024];
__device__ __half g_peh[2048UL * 1024];
__device__ __half g_wth[3072UL * 1024], g_wtl[3072UL * 1024];  // W_tok^T
__device__ __half g_wph[2048UL * 1024], g_wpl[2048UL * 1024];  // W_pos^T
__device__ __half g_qh[32UL * 2048 * 128];
__device__ __half g_kh[32UL * 2048 * 128];
__device__ __half g_vh[32UL * 2048 * 64];   // V per z: [s][64] natural layout

// ---------------------------------------------------------------------------
__device__ __forceinline__ void mma16816(float c[4], const uint32_t a[4],
                                         const uint32_t b[2]) {
    asm volatile(
        "mma.sync.aligned.m16n8k16.row.col.f32.f16.f16.f32 "
        "{%0,%1,%2,%3}, {%4,%5,%6,%7}, {%8,%9}, {%0,%1,%2,%3};\n"
        : "+f"(c[0]), "+f"(c[1]), "+f"(c[2]), "+f"(c[3])
        : "r"(a[0]), "r"(a[1]), "r"(a[2]), "r"(a[3]), "r"(b[0]), "r"(b[1]));
}
__device__ __forceinline__ uint32_t sptr(const void* p) {
    return (uint32_t)__cvta_generic_to_shared(p);
}
__device__ __forceinline__ void ldsm4(uint32_t r[4], const __half* p) {
    asm volatile("ldmatrix.sync.aligned.m8n8.x4.shared.b16 {%0,%1,%2,%3}, [%4];\n"
                 : "=r"(r[0]), "=r"(r[1]), "=r"(r[2]), "=r"(r[3]) : "r"(sptr(p)));
}
__device__ __forceinline__ void ldsm4t(uint32_t r[4], const __half* p) {
    asm volatile("ldmatrix.sync.aligned.m8n8.x4.trans.shared.b16 {%0,%1,%2,%3}, [%4];\n"
                 : "=r"(r[0]), "=r"(r[1]), "=r"(r[2]), "=r"(r[3]) : "r"(sptr(p)));
}
__device__ __forceinline__ void cpa16(__half* dst, const __half* src) {
    asm volatile("cp.async.cg.shared.global [%0], [%1], 16;\n"
                 :: "r"(sptr(dst)), "l"(src));
}
#define CP_COMMIT() asm volatile("cp.async.commit_group;\n")
#define CP_WAIT1() asm volatile("cp.async.wait_group 1;\n")
#define CP_WAIT0() asm volatile("cp.async.wait_group 0;\n")
__device__ __forceinline__ void split1(float v, __half& h, __half& l) {
    h = __float2half_rn(v);
    l = __float2half_rn(v - __half2float(h));
}

// ---------------------------------------------------------------------------
// fused: pack x -> xh, pos_embed -> peh (fp16 hi only), and T5 bias LUT
// ---------------------------------------------------------------------------
constexpr int N4X = 4096 * 1024 / 4;   // 1048576
constexpr int N4P = 2048 * 1024 / 4;   // 524288
constexpr int NB  = 16 * 4096;         // 65536
__global__ void pack_all_h(const float* __restrict__ x,
                           const float* __restrict__ pe,
                           const float* __restrict__ bias_table) {
    int i = blockIdx.x * blockDim.x + threadIdx.x;
    if (i < N4X + N4P) {
        const float* src;
        __half* dst;
        int j;
        if (i < N4X) { src = x;  dst = g_xh;  j = i; }
        else         { src = pe; dst = g_peh; j = i - N4X; }
        float4 v = ((const float4*)src)[j];
        ((__half2*)dst)[2 * j]     = __floats2half2_rn(v.x, v.y);
        ((__half2*)dst)[2 * j + 1] = __floats2half2_rn(v.z, v.w);
    } else if (i < N4X + N4P + NB) {
        int j = i - N4X - N4P;
        int h = j >> 12, dd = j & 4095;
        int n = -(dd - 2047);
        int ret = 0;
        if (n < 0) { ret = 16; n = -n; }
        int bucket;
        if (n < 8) bucket = n;
        else {
            float v = logf((float)n / 8.0f) / logf(16.0f) * 8.0f;
            int vi = 8 + (int)v;
            bucket = vi < 15 ? vi : 15;
        }
        g_bias[j] = bias_table[(bucket + ret + 2048) * 16 + h];
    }
}

// ---------------------------------------------------------------------------
// fused pack+transpose+split for both weights: src [1024][N] -> dst [N][1024]
// ---------------------------------------------------------------------------
__global__ void __launch_bounds__(256) pack_splitT_all(
    const float* __restrict__ wt, const float* __restrict__ wp) {
    __shared__ float tile[32][33];
    const float* src;
    __half *hi, *lo;
    int N, bx = blockIdx.x;
    if (bx < 96) { src = wt; hi = g_wth; lo = g_wtl; N = 3072; }
    else         { src = wp; hi = g_wph; lo = g_wpl; N = 2048; bx -= 96; }
    int n0 = bx * 32, k0 = blockIdx.y * 32;
    int tx = threadIdx.x, ty = threadIdx.y;
#pragma unroll
    for (int t = 0; t < 4; t++)
        tile[ty + t * 8][tx] = src[(size_t)(k0 + ty + t * 8) * N + n0 + tx];
    __syncthreads();
#pragma unroll
    for (int t = 0; t < 4; t++) {
        int n = n0 + ty + t * 8;
        float v = tile[tx][ty + t * 8];
        __half h, l;
        split1(v, h, l);
        hi[(size_t)n * 1024 + k0 + tx] = h;
        lo[(size_t)n * 1024 + k0 + tx] = l;
    }
}

// ---------------------------------------------------------------------------
// merged 2-term GEMM with FUSED Q/K/V epilogue (no fp32 intermediate):
// blocks [0,768): tok proj: key->kh[:, :64], query->qh (scaled), value->vh
// blocks [768,1024): pos proj: -> kh/qh [:, 64:128], duplicated to both b
// 128x128 tile, 8 warps, k-step 32, 3-stage cp.async, 2 CTAs/SM.
// ---------------------------------------------------------------------------
constexpr int HSTR = 40;
constexpr int HG_STG = 128 * HSTR;
constexpr int HG_STAGE = 3 * HG_STG;
constexpr int HG_SMEM = 3 * HG_STAGE * 2;       // 92160 bytes

__global__ void __launch_bounds__(256, 2) hgemm2(
    const __half* __restrict__ At, const __half* __restrict__ Bht,
    const __half* __restrict__ Blt,
    const __half* __restrict__ Ap, const __half* __restrict__ Bhp,
    const __half* __restrict__ Blp)
{
    extern __shared__ __half smg[];
    const int tid = threadIdx.x, wid = tid >> 5, lane = tid & 31;
    const int wm = wid & 1, wn = wid >> 1;
    const __half *A, *Bh, *Bl;
    int bx, by, isTok;
    {
        int bid = blockIdx.x;
        if (bid < 768) { A = At; Bh = Bht; Bl = Blt; isTok = 1;
                         bx = bid % 24; by = bid / 24; }
        else { bid -= 768; A = Ap; Bh = Bhp; Bl = Blp; isTok = 0;
               bx = bid % 16; by = bid / 16; }
    }
    const int bm = by * 128, bn = bx * 128;
    const int lrow = tid >> 2, lgc = (tid & 3) * 8;
    const __half* pA0 = A + (size_t)(bm + lrow) * 1024 + lgc;
    const __half* pA1 = A + (size_t)(bm + lrow + 64) * 1024 + lgc;
    const __half* pBh0 = Bh + (size_t)(bn + lrow) * 1024 + lgc;
    const __half* pBh1 = Bh + (size_t)(bn + lrow + 64) * 1024 + lgc;
    const __half* pBl0 = Bl + (size_t)(bn + lrow) * 1024 + lgc;
    const __half* pBl1 = Bl + (size_t)(bn + lrow + 64) * 1024 + lgc;
    const int so0 = lrow * HSTR + lgc, so1 = (lrow + 64) * HSTR + lgc;
    const int aoff = (lane & 15) * HSTR + (lane >> 4) * 8;
    const int boff = ((lane & 7) + ((lane >> 4) << 3)) * HSTR + ((lane >> 3) & 1) * 8;
    float acc[4][4][4] = {};

    auto LOAD = [&](int c) {
        __half* st = smg + (c % 3) * HG_STAGE;
        const int k0 = c * 32;
        cpa16(st + so0, pA0 + k0);
        cpa16(st + so1, pA1 + k0);
        cpa16(st + HG_STG + so0, pBh0 + k0);
        cpa16(st + HG_STG + so1, pBh1 + k0);
        cpa16(st + 2 * HG_STG + so0, pBl0 + k0);
        cpa16(st + 2 * HG_STG + so1, pBl1 + k0);
        CP_COMMIT();
    };

    LOAD(0);
    LOAD(1);
    CP_WAIT1();
    __syncthreads();

    for (int kt = 0; kt < 32; kt++) {
        const __half* st = smg + (kt % 3) * HG_STAGE;
#pragma unroll
        for (int kd = 0; kd < 2; kd++) {
            uint32_t af[4][4], bfh[4][2], bfl[4][2];
#pragma unroll
            for (int i = 0; i < 4; i++)
                ldsm4(af[i], st + (wm * 64 + i * 16) * HSTR + kd * 16 + aoff);
#pragma unroll
            for (int j2 = 0; j2 < 2; j2++) {
                uint32_t t4[4];
                ldsm4(t4, st + HG_STG + (wn * 32 + j2 * 16) * HSTR + kd * 16 + boff);
                bfh[2 * j2][0] = t4[0]; bfh[2 * j2][1] = t4[1];
                bfh[2 * j2 + 1][0] = t4[2]; bfh[2 * j2 + 1][1] = t4[3];
                ldsm4(t4, st + 2 * HG_STG + (wn * 32 + j2 * 16) * HSTR + kd * 16 + boff);
                bfl[2 * j2][0] = t4[0]; bfl[2 * j2][1] = t4[1];
                bfl[2 * j2 + 1][0] = t4[2]; bfl[2 * j2 + 1][1] = t4[3];
            }
#pragma unroll
            for (int i = 0; i < 4; i++)
#pragma unroll
                for (int j = 0; j < 4; j++) {
                    mma16816(acc[i][j], af[i], bfh[j]);
                    mma16816(acc[i][j], af[i], bfl[j]);
                }
        }
        if (kt + 2 < 32) {
            LOAD(kt + 2);
            CP_WAIT1();
        } else {
            CP_WAIT0();
        }
        __syncthreads();
    }

    // ---- fused epilogue: write Q/K/V directly in attention layout ----
    if (isTok) {
#pragma unroll
        for (int i = 0; i < 4; i++) {
            int r = bm + wm * 64 + i * 16 + (lane >> 2);
            int bb = r >> 11, s = r & 2047;
#pragma unroll
            for (int j = 0; j < 4; j++) {
                int c = bn + wn * 32 + j * 8 + (lane & 3) * 2;
                int region = c >> 10, col = c & 1023;
                int h = col >> 6, dh = col & 63;
                size_t zs = (size_t)(bb * 16 + h) * 2048;
                if (region == 0) {
                    *(__half2*)&g_kh[(zs + s) * 128 + dh] =
                        __floats2half2_rn(acc[i][j][0], acc[i][j][1]);
                    *(__half2*)&g_kh[(zs + s + 8) * 128 + dh] =
                        __floats2half2_rn(acc[i][j][2], acc[i][j][3]);
                } else if (region == 1) {
                    *(__half2*)&g_qh[(zs + s) * 128 + dh] = __floats2half2_rn(
                        acc[i][j][0] * INV_SCALE, acc[i][j][1] * INV_SCALE);
                    *(__half2*)&g_qh[(zs + s + 8) * 128 + dh] = __floats2half2_rn(
                        acc[i][j][2] * INV_SCALE, acc[i][j][3] * INV_SCALE);
                } else {
                    *(__half2*)&g_vh[(zs + s) * 64 + dh] =
                        __floats2half2_rn(acc[i][j][0], acc[i][j][1]);
                    *(__half2*)&g_vh[(zs + s + 8) * 64 + dh] =
                        __floats2half2_rn(acc[i][j][2], acc[i][j][3]);
                }
            }
        }
    } else {
#pragma unroll
        for (int i = 0; i < 4; i++) {
            int s = bm + wm * 64 + i * 16 + (lane >> 2);
#pragma unroll
            for (int j = 0; j < 4; j++) {
                int c = bn + wn * 32 + j * 8 + (lane & 3) * 2;
                int region = c >> 10, col = c & 1023;
                int h = col >> 6, dh = 64 + (col & 63);
                if (region == 0) {
                    __half2 v01 = __floats2half2_rn(acc[i][j][0], acc[i][j][1]);
                    __half2 v23 = __floats2half2_rn(acc[i][j][2], acc[i][j][3]);
#pragma unroll
                    for (int bb = 0; bb < 2; bb++) {
                        size_t zs = (size_t)(bb * 16 + h) * 2048;
                        *(__half2*)&g_kh[(zs + s) * 128 + dh]     = v01;
                        *(__half2*)&g_kh[(zs + s + 8) * 128 + dh] = v23;
                    }
                } else {
                    __half2 q01 = __floats2half2_rn(acc[i][j][0] * INV_SCALE,
                                                    acc[i][j][1] * INV_SCALE);
                    __half2 q23 = __floats2half2_rn(acc[i][j][2] * INV_SCALE,
                                                    acc[i][j][3] * INV_SCALE);
#pragma unroll
                    for (int bb = 0; bb < 2; bb++) {
                        size_t zs = (size_t)(bb * 16 + h) * 2048;
                        *(__half2*)&g_qh[(zs + s) * 128 + dh]     = q01;
                        *(__half2*)&g_qh[(zs + s + 8) * 128 + dh] = q23;
                    }
                }
            }
        }
    }
}

// ---------------------------------------------------------------------------
// fused flash attention: 1-term QK (pre-scaled Q), 1-term PV with V in
// natural [s][64] layout via ldmatrix.trans. QK(it+1) before softmax(it),
// 4-stage cp.async K/V pipeline. block = (q-tile 128, z), 8 warps.
// ---------------------------------------------------------------------------
#define QSTR 136
#define VSTR 72
constexpr int O_QH = 0;
constexpr int O_K  = 128 * QSTR;
constexpr int KHL  = 64 * QSTR;
constexpr int O_V  = O_K + 4 * KHL;
constexpr int VHL  = 64 * VSTR;
constexpr int ATT_SMEM = (O_V + 4 * VHL) * 2;    // 141312 bytes

__global__ void __launch_bounds__(256) attn_kernel(
    const __half* __restrict__ qh,
    const __half* __restrict__ kh, const __half* __restrict__ vh,
    const float* __restrict__ biasd, float* __restrict__ out)
{
    extern __shared__ __half smh[];
    const int z = blockIdx.y, b = z >> 4, h = z & 15;
    const int q0 = blockIdx.x * 128;
    const int tid = threadIdx.x, wid = tid >> 5, lane = tid & 31;
    const int lr4 = lane >> 2, lc2 = (lane & 3) * 2;
    const float* bd = biasd + h * 4096;
    const size_t zq = (size_t)z * 2048 * 128;
    const size_t zv = (size_t)z * 2048 * 64;
    const int mrow = wid * 16;
    const int aoffQ = (lane & 15) * QSTR + (lane >> 4) * 8;
    const int boffK = ((lane & 7) + ((lane >> 4) << 3)) * QSTR + ((lane >> 3) & 1) * 8;
    const int boffVt = ((lane & 7) + ((lane >> 3) & 1) * 8) * VSTR + (lane >> 4) * 8;

    auto PREFETCH = [&](int t) {
        __half* bK = smh + O_K + (t & 3) * KHL;
        __half* bV = smh + O_V + (t & 3) * VHL;
        const int k0 = t * 64;
#pragma unroll
        for (int tt = 0; tt < 4; tt++) {
            int i = tid + tt * 256, r = i >> 4, c = (i & 15) * 8;
            cpa16(bK + r * QSTR + c, kh + zq + (size_t)(k0 + r) * 128 + c);
        }
#pragma unroll
        for (int tt = 0; tt < 2; tt++) {
            int i = tid + tt * 256, r = i >> 3, c = (i & 7) * 8;
            cpa16(bV + r * VSTR + c, vh + zv + (size_t)(k0 + r) * 64 + c);
        }
        CP_COMMIT();
    };

#pragma unroll
    for (int t = 0; t < 4; t++) {
        int i = tid + t * 256, r = i >> 3, c = (i & 7) * 16;
        cpa16(smh + O_QH + r * QSTR + c, qh + zq + (size_t)(q0 + r) * 128 + c);
        cpa16(smh + O_QH + r * QSTR + c + 8, qh + zq + (size_t)(q0 + r) * 128 + c + 8);
    }
    {
        __half* bK = smh + O_K;
        __half* bV = smh + O_V;
#pragma unroll
        for (int tt = 0; tt < 4; tt++) {
            int i = tid + tt * 256, r = i >> 4, c = (i & 15) * 8;
            cpa16(bK + r * QSTR + c, kh + zq + (size_t)r * 128 + c);
        }
#pragma unroll
        for (int tt = 0; tt < 2; tt++) {
            int i = tid + tt * 256, r = i >> 3, c = (i & 7) * 8;
            cpa16(bV + r * VSTR + c, vh + zv + (size_t)r * 64 + c);
        }
        CP_COMMIT();
    }
    PREFETCH(1);
    PREFETCH(2);
    CP_WAIT1();
    __syncthreads();

    uint32_t qfh[8][4];
#pragma unroll
    for (int kd = 0; kd < 8; kd++)
        ldsm4(qfh[kd], smh + O_QH + mrow * QSTR + kd * 16 + aoffQ);

    float m0 = -INFINITY, m1 = -INFINITY, L0 = 0.f, L1 = 0.f;
    float of[8][4] = {};
    float sfA[8][4], sfB[8][4];

    auto QK = [&](int t, float (&sf)[8][4]) {
        const __half* bK = smh + O_K + (t & 3) * KHL;
#pragma unroll
        for (int nf = 0; nf < 8; nf++)
#pragma unroll
            for (int c = 0; c < 4; c++) sf[nf][c] = 0.f;
#pragma unroll
        for (int kd = 0; kd < 8; kd++) {
#pragma unroll
            for (int np = 0; np < 4; np++) {
                uint32_t b4[4];
                ldsm4(b4, bK + (np * 16) * QSTR + kd * 16 + boffK);
                mma16816(sf[2 * np],     qfh[kd], b4);
                mma16816(sf[2 * np + 1], qfh[kd], b4 + 2);
            }
        }
    };

    auto SOFTPV = [&](int it, float (&sf)[8][4]) {
        const int k0 = it * 64;
        const __half* bV = smh + O_V + (it & 3) * VHL;
        const int r0 = q0 + mrow + lr4;
        float lm0 = -INFINITY, lm1 = -INFINITY;
#pragma unroll
        for (int nf = 0; nf < 8; nf++) {
            int c = k0 + nf * 8 + lc2;
            sf[nf][0] += bd[c - r0 + 2047];
            sf[nf][1] += bd[c + 1 - r0 + 2047];
            sf[nf][2] += bd[c - (r0 + 8) + 2047];
            sf[nf][3] += bd[c + 1 - (r0 + 8) + 2047];
            lm0 = fmaxf(lm0, fmaxf(sf[nf][0], sf[nf][1]));
            lm1 = fmaxf(lm1, fmaxf(sf[nf][2], sf[nf][3]));
        }
        lm0 = fmaxf(lm0, __shfl_xor_sync(0xffffffffu, lm0, 1));
        lm0 = fmaxf(lm0, __shfl_xor_sync(0xffffffffu, lm0, 2));
        lm1 = fmaxf(lm1, __shfl_xor_sync(0xffffffffu, lm1, 1));
        lm1 = fmaxf(lm1, __shfl_xor_sync(0xffffffffu, lm1, 2));
        float mn0 = fmaxf(m0, lm0), mn1 = fmaxf(m1, lm1);
        float corr0 = __expf(m0 - mn0), corr1 = __expf(m1 - mn1);
        float rs0 = 0.f, rs1 = 0.f;
        uint32_t ap[4][4];
#pragma unroll
        for (int nf = 0; nf < 8; nf++) {
            float p0 = __expf(sf[nf][0] - mn0), p1 = __expf(sf[nf][1] - mn0);
            float p2 = __expf(sf[nf][2] - mn1), p3 = __expf(sf[nf][3] - mn1);
            rs0 += p0 + p1; rs1 += p2 + p3;
            __half2 h01 = __floats2half2_rn(p0, p1);
            __half2 h23 = __floats2half2_rn(p2, p3);
            int kf = nf >> 1, off = (nf & 1) * 2;
            ap[kf][off] = *(uint32_t*)&h01;
            ap[kf][off + 1] = *(uint32_t*)&h23;
        }
        rs0 += __shfl_xor_sync(0xffffffffu, rs0, 1);
        rs0 += __shfl_xor_sync(0xffffffffu, rs0, 2);
        rs1 += __shfl_xor_sync(0xffffffffu, rs1, 1);
        rs1 += __shfl_xor_sync(0xffffffffu, rs1, 2);
        L0 = L0 * corr0 + rs0;
        L1 = L1 * corr1 + rs1;
        m0 = mn0; m1 = mn1;
#pragma unroll
        for (int nf = 0; nf < 8; nf++) {
            of[nf][0] *= corr0; of[nf][1] *= corr0;
            of[nf][2] *= corr1; of[nf][3] *= corr1;
        }
#pragma unroll
        for (int kf = 0; kf < 4; kf++)
#pragma unroll
            for (int np = 0; np < 4; np++) {
                uint32_t b4[4];
                ldsm4t(b4, bV + (kf * 16) * VSTR + np * 16 + boffVt);
                mma16816(of[2 * np],     ap[kf], b4);
                mma16816(of[2 * np + 1], ap[kf], b4 + 2);
            }
    };

    auto PIPE = [&](int it) {
        if (it + 3 < 32) {
            PREFETCH(it + 3);
            CP_WAIT1();
        } else {
            CP_WAIT0();
        }
        __syncthreads();
    };

    QK(0, sfA);
    for (int it = 0; it < 32; it += 2) {
        if (it + 1 < 32) QK(it + 1, sfB);
        SOFTPV(it, sfA);
        PIPE(it);
        if (it + 2 < 32) QK(it + 2, sfA);
        SOFTPV(it + 1, sfB);
        PIPE(it + 1);
    }

    float inv0 = 1.f / L0, inv1 = 1.f / L1;
    const int r0 = q0 + mrow + lr4;
    const size_t ob = (size_t)b * 2048 * 1024 + h * 64;
#pragma unroll
    for (int nf = 0; nf < 8; nf++) {
        int c = nf * 8 + lc2;
        *(float2*)&out[ob + (size_t)r0 * 1024 + c] =
            make_float2(of[nf][0] * inv0, of[nf][1] * inv0);
        *(float2*)&out[ob + (size_t)(r0 + 8) * 1024 + c] =
            make_float2(of[nf][2] * inv1, of[nf][3] * inv1);
    }
}

// ---------------------------------------------------------------------------
extern "C" void kernel_launch(void* const* d_in, const int* in_sizes, int n_in,
                              void* d_out, int out_size)
{
    const float* x          = (const float*)d_in[0];
    const float* pos_embed  = (const float*)d_in[1];
    const float* W_pos_kq   = (const float*)d_in[2];
    const float* W_tok_kqv  = (const float*)d_in[3];
    const float* bias_table = (const float*)d_in[4];
    float* out = (float*)d_out;

    float* biasd;
    __half *xh, *peh, *wth, *wtl, *wph, *wpl;
    __half *qh, *kh, *vh;
    cudaGetSymbolAddress((void**)&biasd, g_bias);
    cudaGetSymbolAddress((void**)&xh, g_xh);
    cudaGetSymbolAddress((void**)&peh, g_peh);
    cudaGetSymbolAddress((void**)&wth, g_wth); cudaGetSymbolAddress((void**)&wtl, g_wtl);
    cudaGetSymbolAddress((void**)&wph, g_wph); cudaGetSymbolAddress((void**)&wpl, g_wpl);
    cudaGetSymbolAddress((void**)&qh, g_qh);
    cudaGetSymbolAddress((void**)&kh, g_kh);
    cudaGetSymbolAddress((void**)&vh, g_vh);

    cudaFuncSetAttribute(attn_kernel,
                         cudaFuncAttributeMaxDynamicSharedMemorySize, ATT_SMEM);
    cudaFuncSetAttribute(hgemm2,
                         cudaFuncAttributeMaxDynamicSharedMemorySize, HG_SMEM);

    pack_all_h<<<(N4X + N4P + NB + 255) / 256, 256>>>(x, pos_embed, bias_table);
    pack_splitT_all<<<dim3(160, 32), dim3(32, 8)>>>(W_tok_kqv, W_pos_kq);
    hgemm2<<<1024, 256, HG_SMEM>>>(xh, wth, wtl, peh, wph, wpl);
    attn_kernel<<<dim3(16, 32), 256, ATT_SMEM>>>(qh, kh, vh, biasd, out);
}

// round 12
// speedup vs baseline: 6.7870x; 1.0844x over previous
#include <cuda_runtime.h>
#include <cuda_fp16.h>
#include <math.h>
#include <stdint.h>

#define INV_SCALE 0.08838834764831845f  // 1/sqrt(128)

// ------------------------- static scratch (no cudaMalloc) -------------------
__device__ float  g_bias[16 * 4096];
__device__ __half g_xh[4096UL * 1024];
__device__ __half g_peh[2048UL * 1024];
__device__ __half g_wth[3072UL * 1024], g_wtl[3072UL * 1024];  // W_tok^T
__device__ __half g_wph[2048UL * 1024], g_wpl[2048UL * 1024];  // W_pos^T
__device__ __half g_qh[32UL * 2048 * 128];
__device__ __half g_kh[32UL * 2048 * 128];
__device__ __half g_vh[32UL * 2048 * 64];   // V per z: [s][64] natural layout

// ---------------------------------------------------------------------------
__device__ __forceinline__ void mma16816(float c[4], const uint32_t a[4],
                                         const uint32_t b[2]) {
    asm volatile(
        "mma.sync.aligned.m16n8k16.row.col.f32.f16.f16.f32 "
        "{%0,%1,%2,%3}, {%4,%5,%6,%7}, {%8,%9}, {%0,%1,%2,%3};\n"
        : "+f"(c[0]), "+f"(c[1]), "+f"(c[2]), "+f"(c[3])
        : "r"(a[0]), "r"(a[1]), "r"(a[2]), "r"(a[3]), "r"(b[0]), "r"(b[1]));
}
__device__ __forceinline__ uint32_t sptr(const void* p) {
    return (uint32_t)__cvta_generic_to_shared(p);
}
__device__ __forceinline__ void ldsm4(uint32_t r[4], const __half* p) {
    asm volatile("ldmatrix.sync.aligned.m8n8.x4.shared.b16 {%0,%1,%2,%3}, [%4];\n"
                 : "=r"(r[0]), "=r"(r[1]), "=r"(r[2]), "=r"(r[3]) : "r"(sptr(p)));
}
__device__ __forceinline__ void ldsm4t(uint32_t r[4], const __half* p) {
    asm volatile("ldmatrix.sync.aligned.m8n8.x4.trans.shared.b16 {%0,%1,%2,%3}, [%4];\n"
                 : "=r"(r[0]), "=r"(r[1]), "=r"(r[2]), "=r"(r[3]) : "r"(sptr(p)));
}
__device__ __forceinline__ void cpa16(__half* dst, const __half* src) {
    asm volatile("cp.async.cg.shared.global [%0], [%1], 16;\n"
                 :: "r"(sptr(dst)), "l"(src));
}
#define CP_COMMIT() asm volatile("cp.async.commit_group;\n")
#define CP_WAIT1() asm volatile("cp.async.wait_group 1;\n")
#define CP_WAIT0() asm volatile("cp.async.wait_group 0;\n")
__device__ __forceinline__ void split1(float v, __half& h, __half& l) {
    h = __float2half_rn(v);
    l = __float2half_rn(v - __half2float(h));
}

// ---------------------------------------------------------------------------
// fused: pack x -> xh, pos_embed -> peh (fp16 hi only), and T5 bias LUT
// ---------------------------------------------------------------------------
constexpr int N4X = 4096 * 1024 / 4;   // 1048576
constexpr int N4P = 2048 * 1024 / 4;   // 524288
constexpr int NB  = 16 * 4096;         // 65536
__global__ void pack_all_h(const float* __restrict__ x,
                           const float* __restrict__ pe,
                           const float* __restrict__ bias_table) {
    int i = blockIdx.x * blockDim.x + threadIdx.x;
    if (i < N4X + N4P) {
        const float* src;
        __half* dst;
        int j;
        if (i < N4X) { src = x;  dst = g_xh;  j = i; }
        else         { src = pe; dst = g_peh; j = i - N4X; }
        float4 v = ((const float4*)src)[j];
        ((__half2*)dst)[2 * j]     = __floats2half2_rn(v.x, v.y);
        ((__half2*)dst)[2 * j + 1] = __floats2half2_rn(v.z, v.w);
    } else if (i < N4X + N4P + NB) {
        int j = i - N4X - N4P;
        int h = j >> 12, dd = j & 4095;
        int n = -(dd - 2047);
        int ret = 0;
        if (n < 0) { ret = 16; n = -n; }
        int bucket;
        if (n < 8) bucket = n;
        else {
            float v = logf((float)n / 8.0f) / logf(16.0f) * 8.0f;
            int vi = 8 + (int)v;
            bucket = vi < 15 ? vi : 15;
        }
        g_bias[j] = bias_table[(bucket + ret + 2048) * 16 + h];
    }
}

// ---------------------------------------------------------------------------
// fused pack+transpose+split for both weights: src [1024][N] -> dst [N][1024]
// ---------------------------------------------------------------------------
__global__ void __launch_bounds__(256) pack_splitT_all(
    const float* __restrict__ wt, const float* __restrict__ wp) {
    __shared__ float tile[32][33];
    const float* src;
    __half *hi, *lo;
    int N, bx = blockIdx.x;
    if (bx < 96) { src = wt; hi = g_wth; lo = g_wtl; N = 3072; }
    else         { src = wp; hi = g_wph; lo = g_wpl; N = 2048; bx -= 96; }
    int n0 = bx * 32, k0 = blockIdx.y * 32;
    int tx = threadIdx.x, ty = threadIdx.y;
#pragma unroll
    for (int t = 0; t < 4; t++)
        tile[ty + t * 8][tx] = src[(size_t)(k0 + ty + t * 8) * N + n0 + tx];
    __syncthreads();
#pragma unroll
    for (int t = 0; t < 4; t++) {
        int n = n0 + ty + t * 8;
        float v = tile[tx][ty + t * 8];
        __half h, l;
        split1(v, h, l);
        hi[(size_t)n * 1024 + k0 + tx] = h;
        lo[(size_t)n * 1024 + k0 + tx] = l;
    }
}

// ---------------------------------------------------------------------------
// merged 2-term GEMM with FUSED Q/K/V epilogue (no fp32 intermediate):
// blocks [0,768): tok proj: key->kh[:, :64], query->qh (scaled), value->vh
// blocks [768,1024): pos proj: -> kh/qh [:, 64:128], duplicated to both b
// 128x128 tile, 8 warps, k-step 32, 3-stage cp.async, 2 CTAs/SM.
// ---------------------------------------------------------------------------
constexpr int HSTR = 40;
constexpr int HG_STG = 128 * HSTR;
constexpr int HG_STAGE = 3 * HG_STG;
constexpr int HG_SMEM = 3 * HG_STAGE * 2;       // 92160 bytes

__global__ void __launch_bounds__(256, 2) hgemm2(
    const __half* __restrict__ At, const __half* __restrict__ Bht,
    const __half* __restrict__ Blt,
    const __half* __restrict__ Ap, const __half* __restrict__ Bhp,
    const __half* __restrict__ Blp)
{
    extern __shared__ __half smg[];
    const int tid = threadIdx.x, wid = tid >> 5, lane = tid & 31;
    const int wm = wid & 1, wn = wid >> 1;
    const __half *A, *Bh, *Bl;
    int bx, by, isTok;
    {
        int bid = blockIdx.x;
        if (bid < 768) { A = At; Bh = Bht; Bl = Blt; isTok = 1;
                         bx = bid % 24; by = bid / 24; }
        else { bid -= 768; A = Ap; Bh = Bhp; Bl = Blp; isTok = 0;
               bx = bid % 16; by = bid / 16; }
    }
    const int bm = by * 128, bn = bx * 128;
    const int lrow = tid >> 2, lgc = (tid & 3) * 8;
    const __half* pA0 = A + (size_t)(bm + lrow) * 1024 + lgc;
    const __half* pA1 = A + (size_t)(bm + lrow + 64) * 1024 + lgc;
    const __half* pBh0 = Bh + (size_t)(bn + lrow) * 1024 + lgc;
    const __half* pBh1 = Bh + (size_t)(bn + lrow + 64) * 1024 + lgc;
    const __half* pBl0 = Bl + (size_t)(bn + lrow) * 1024 + lgc;
    const __half* pBl1 = Bl + (size_t)(bn + lrow + 64) * 1024 + lgc;
    const int so0 = lrow * HSTR + lgc, so1 = (lrow + 64) * HSTR + lgc;
    const int aoff = (lane & 15) * HSTR + (lane >> 4) * 8;
    const int boff = ((lane & 7) + ((lane >> 4) << 3)) * HSTR + ((lane >> 3) & 1) * 8;
    float acc[4][4][4] = {};

    auto LOAD = [&](int c) {
        __half* st = smg + (c % 3) * HG_STAGE;
        const int k0 = c * 32;
        cpa16(st + so0, pA0 + k0);
        cpa16(st + so1, pA1 + k0);
        cpa16(st + HG_STG + so0, pBh0 + k0);
        cpa16(st + HG_STG + so1, pBh1 + k0);
        cpa16(st + 2 * HG_STG + so0, pBl0 + k0);
        cpa16(st + 2 * HG_STG + so1, pBl1 + k0);
        CP_COMMIT();
    };

    LOAD(0);
    LOAD(1);
    CP_WAIT1();
    __syncthreads();

    for (int kt = 0; kt < 32; kt++) {
        const __half* st = smg + (kt % 3) * HG_STAGE;
#pragma unroll
        for (int kd = 0; kd < 2; kd++) {
            uint32_t af[4][4], bfh[4][2], bfl[4][2];
#pragma unroll
            for (int i = 0; i < 4; i++)
                ldsm4(af[i], st + (wm * 64 + i * 16) * HSTR + kd * 16 + aoff);
#pragma unroll
            for (int j2 = 0; j2 < 2; j2++) {
                uint32_t t4[4];
                ldsm4(t4, st + HG_STG + (wn * 32 + j2 * 16) * HSTR + kd * 16 + boff);
                bfh[2 * j2][0] = t4[0]; bfh[2 * j2][1] = t4[1];
                bfh[2 * j2 + 1][0] = t4[2]; bfh[2 * j2 + 1][1] = t4[3];
                ldsm4(t4, st + 2 * HG_STG + (wn * 32 + j2 * 16) * HSTR + kd * 16 + boff);
                bfl[2 * j2][0] = t4[0]; bfl[2 * j2][1] = t4[1];
                bfl[2 * j2 + 1][0] = t4[2]; bfl[2 * j2 + 1][1] = t4[3];
            }
#pragma unroll
            for (int i = 0; i < 4; i++)
#pragma unroll
                for (int j = 0; j < 4; j++) {
                    mma16816(acc[i][j], af[i], bfh[j]);
                    mma16816(acc[i][j], af[i], bfl[j]);
                }
        }
        if (kt + 2 < 32) {
            LOAD(kt + 2);
            CP_WAIT1();
        } else {
            CP_WAIT0();
        }
        __syncthreads();
    }

    // ---- fused epilogue: write Q/K/V directly in attention layout ----
    if (isTok) {
#pragma unroll
        for (int i = 0; i < 4; i++) {
            int r = bm + wm * 64 + i * 16 + (lane >> 2);
            int bb = r >> 11, s = r & 2047;
#pragma unroll
            for (int j = 0; j < 4; j++) {
                int c = bn + wn * 32 + j * 8 + (lane & 3) * 2;
                int region = c >> 10, col = c & 1023;
                int h = col >> 6, dh = col & 63;
                size_t zs = (size_t)(bb * 16 + h) * 2048;
                if (region == 0) {
                    *(__half2*)&g_kh[(zs + s) * 128 + dh] =
                        __floats2half2_rn(acc[i][j][0], acc[i][j][1]);
                    *(__half2*)&g_kh[(zs + s + 8) * 128 + dh] =
                        __floats2half2_rn(acc[i][j][2], acc[i][j][3]);
                } else if (region == 1) {
                    *(__half2*)&g_qh[(zs + s) * 128 + dh] = __floats2half2_rn(
                        acc[i][j][0] * INV_SCALE, acc[i][j][1] * INV_SCALE);
                    *(__half2*)&g_qh[(zs + s + 8) * 128 + dh] = __floats2half2_rn(
                        acc[i][j][2] * INV_SCALE, acc[i][j][3] * INV_SCALE);
                } else {
                    *(__half2*)&g_vh[(zs + s) * 64 + dh] =
                        __floats2half2_rn(acc[i][j][0], acc[i][j][1]);
                    *(__half2*)&g_vh[(zs + s + 8) * 64 + dh] =
                        __floats2half2_rn(acc[i][j][2], acc[i][j][3]);
                }
            }
        }
    } else {
#pragma unroll
        for (int i = 0; i < 4; i++) {
            int s = bm + wm * 64 + i * 16 + (lane >> 2);
#pragma unroll
            for (int j = 0; j < 4; j++) {
                int c = bn + wn * 32 + j * 8 + (lane & 3) * 2;
                int region = c >> 10, col = c & 1023;
                int h = col >> 6, dh = 64 + (col & 63);
                if (region == 0) {
                    __half2 v01 = __floats2half2_rn(acc[i][j][0], acc[i][j][1]);
                    __half2 v23 = __floats2half2_rn(acc[i][j][2], acc[i][j][3]);
#pragma unroll
                    for (int bb = 0; bb < 2; bb++) {
                        size_t zs = (size_t)(bb * 16 + h) * 2048;
                        *(__half2*)&g_kh[(zs + s) * 128 + dh]     = v01;
                        *(__half2*)&g_kh[(zs + s + 8) * 128 + dh] = v23;
                    }
                } else {
                    __half2 q01 = __floats2half2_rn(acc[i][j][0] * INV_SCALE,
                                                    acc[i][j][1] * INV_SCALE);
                    __half2 q23 = __floats2half2_rn(acc[i][j][2] * INV_SCALE,
                                                    acc[i][j][3] * INV_SCALE);
#pragma unroll
                    for (int bb = 0; bb < 2; bb++) {
                        size_t zs = (size_t)(bb * 16 + h) * 2048;
                        *(__half2*)&g_qh[(zs + s) * 128 + dh]     = q01;
                        *(__half2*)&g_qh[(zs + s + 8) * 128 + dh] = q23;
                    }
                }
            }
        }
    }
}

// ---------------------------------------------------------------------------
// fused flash attention: 1-term QK (pre-scaled Q), 1-term PV, V natural
// layout via ldmatrix.trans. 3-stage cp.async K/V pipeline, sequential
// QK->softmax->PV per tile, 2 CTAs/SM for cross-CTA latency hiding.
// block = (q-tile 128, z), 8 warps.
// ---------------------------------------------------------------------------
#define QSTR 136
#define VSTR 72
constexpr int O_QH = 0;
constexpr int O_K  = 128 * QSTR;
constexpr int KHL  = 64 * QSTR;
constexpr int O_V  = O_K + 3 * KHL;
constexpr int VHL  = 64 * VSTR;
constexpr int ATT_SMEM = (O_V + 3 * VHL) * 2;    // 114688 bytes

__global__ void __launch_bounds__(256, 2) attn_kernel(
    const __half* __restrict__ qh,
    const __half* __restrict__ kh, const __half* __restrict__ vh,
    const float* __restrict__ biasd, float* __restrict__ out)
{
    extern __shared__ __half smh[];
    const int z = blockIdx.y, b = z >> 4, h = z & 15;
    const int q0 = blockIdx.x * 128;
    const int tid = threadIdx.x, wid = tid >> 5, lane = tid & 31;
    const int lr4 = lane >> 2, lc2 = (lane & 3) * 2;
    const float* bd = biasd + h * 4096;
    const size_t zq = (size_t)z * 2048 * 128;
    const size_t zv = (size_t)z * 2048 * 64;
    const int mrow = wid * 16;
    const int aoffQ = (lane & 15) * QSTR + (lane >> 4) * 8;
    const int boffK = ((lane & 7) + ((lane >> 4) << 3)) * QSTR + ((lane >> 3) & 1) * 8;
    const int boffVt = ((lane & 7) + ((lane >> 3) & 1) * 8) * VSTR + (lane >> 4) * 8;

    auto PREFETCH = [&](int t) {
        __half* bK = smh + O_K + (t % 3) * KHL;
        __half* bV = smh + O_V + (t % 3) * VHL;
        const int k0 = t * 64;
#pragma unroll
        for (int tt = 0; tt < 4; tt++) {
            int i = tid + tt * 256, r = i >> 4, c = (i & 15) * 8;
            cpa16(bK + r * QSTR + c, kh + zq + (size_t)(k0 + r) * 128 + c);
        }
#pragma unroll
        for (int tt = 0; tt < 2; tt++) {
            int i = tid + tt * 256, r = i >> 3, c = (i & 7) * 8;
            cpa16(bV + r * VSTR + c, vh + zv + (size_t)(k0 + r) * 64 + c);
        }
        CP_COMMIT();
    };

    // group 0: Q + K/V tile0 ; group 1: tile1
#pragma unroll
    for (int t = 0; t < 4; t++) {
        int i = tid + t * 256, r = i >> 3, c = (i & 7) * 16;
        cpa16(smh + O_QH + r * QSTR + c, qh + zq + (size_t)(q0 + r) * 128 + c);
        cpa16(smh + O_QH + r * QSTR + c + 8, qh + zq + (size_t)(q0 + r) * 128 + c + 8);
    }
    {
        __half* bK = smh + O_K;
        __half* bV = smh + O_V;
#pragma unroll
        for (int tt = 0; tt < 4; tt++) {
            int i = tid + tt * 256, r = i >> 4, c = (i & 15) * 8;
            cpa16(bK + r * QSTR + c, kh + zq + (size_t)r * 128 + c);
        }
#pragma unroll
        for (int tt = 0; tt < 2; tt++) {
            int i = tid + tt * 256, r = i >> 3, c = (i & 7) * 8;
            cpa16(bV + r * VSTR + c, vh + zv + (size_t)r * 64 + c);
        }
        CP_COMMIT();
    }
    PREFETCH(1);
    CP_WAIT1();          // Q + tile0 arrived
    __syncthreads();

    uint32_t qfh[8][4];
#pragma unroll
    for (int kd = 0; kd < 8; kd++)
        ldsm4(qfh[kd], smh + O_QH + mrow * QSTR + kd * 16 + aoffQ);

    float m0 = -INFINITY, m1 = -INFINITY, L0 = 0.f, L1 = 0.f;
    float of[8][4] = {};

    for (int it = 0; it < 32; it++) {
        const int k0 = it * 64, stg = it % 3;
        const __half* bK = smh + O_K + stg * KHL;
        const __half* bV = smh + O_V + stg * VHL;

        // S = Q K^T
        float sf[8][4] = {};
#pragma unroll
        for (int kd = 0; kd < 8; kd++) {
#pragma unroll
            for (int np = 0; np < 4; np++) {
                uint32_t b4[4];
                ldsm4(b4, bK + (np * 16) * QSTR + kd * 16 + boffK);
                mma16816(sf[2 * np],     qfh[kd], b4);
                mma16816(sf[2 * np + 1], qfh[kd], b4 + 2);
            }
        }

        // bias + online softmax
        const int r0 = q0 + mrow + lr4;
        float lm0 = -INFINITY, lm1 = -INFINITY;
#pragma unroll
        for (int nf = 0; nf < 8; nf++) {
            int c = k0 + nf * 8 + lc2;
            sf[nf][0] += bd[c - r0 + 2047];
            sf[nf][1] += bd[c + 1 - r0 + 2047];
            sf[nf][2] += bd[c - (r0 + 8) + 2047];
            sf[nf][3] += bd[c + 1 - (r0 + 8) + 2047];
            lm0 = fmaxf(lm0, fmaxf(sf[nf][0], sf[nf][1]));
            lm1 = fmaxf(lm1, fmaxf(sf[nf][2], sf[nf][3]));
        }
        lm0 = fmaxf(lm0, __shfl_xor_sync(0xffffffffu, lm0, 1));
        lm0 = fmaxf(lm0, __shfl_xor_sync(0xffffffffu, lm0, 2));
        lm1 = fmaxf(lm1, __shfl_xor_sync(0xffffffffu, lm1, 1));
        lm1 = fmaxf(lm1, __shfl_xor_sync(0xffffffffu, lm1, 2));
        float mn0 = fmaxf(m0, lm0), mn1 = fmaxf(m1, lm1);
        float corr0 = __expf(m0 - mn0), corr1 = __expf(m1 - mn1);
        float rs0 = 0.f, rs1 = 0.f;
        uint32_t ap[4][4];
#pragma unroll
        for (int nf = 0; nf < 8; nf++) {
            float p0 = __expf(sf[nf][0] - mn0), p1 = __expf(sf[nf][1] - mn0);
            float p2 = __expf(sf[nf][2] - mn1), p3 = __expf(sf[nf][3] - mn1);
            rs0 += p0 + p1; rs1 += p2 + p3;
            __half2 h01 = __floats2half2_rn(p0, p1);
            __half2 h23 = __floats2half2_rn(p2, p3);
            int kf = nf >> 1, off = (nf & 1) * 2;
            ap[kf][off] = *(uint32_t*)&h01;
            ap[kf][off + 1] = *(uint32_t*)&h23;
        }
        rs0 += __shfl_xor_sync(0xffffffffu, rs0, 1);
        rs0 += __shfl_xor_sync(0xffffffffu, rs0, 2);
        rs1 += __shfl_xor_sync(0xffffffffu, rs1, 1);
        rs1 += __shfl_xor_sync(0xffffffffu, rs1, 2);
        L0 = L0 * corr0 + rs0;
        L1 = L1 * corr1 + rs1;
        m0 = mn0; m1 = mn1;
#pragma unroll
        for (int nf = 0; nf < 8; nf++) {
            of[nf][0] *= corr0; of[nf][1] *= corr0;
            of[nf][2] *= corr1; of[nf][3] *= corr1;
        }
        // O += P V
#pragma unroll
        for (int kf = 0; kf < 4; kf++)
#pragma unroll
            for (int np = 0; np < 4; np++) {
                uint32_t b4[4];
                ldsm4t(b4, bV + (kf * 16) * VSTR + np * 16 + boffVt);
                mma16816(of[2 * np],     ap[kf], b4);
                mma16816(of[2 * np + 1], ap[kf], b4 + 2);
            }

        if (it + 2 < 32) {
            PREFETCH(it + 2);
            CP_WAIT1();
        } else {
            CP_WAIT0();
        }
        __syncthreads();
    }

    float inv0 = 1.f / L0, inv1 = 1.f / L1;
    const int r0 = q0 + mrow + lr4;
    const size_t ob = (size_t)b * 2048 * 1024 + h * 64;
#pragma unroll
    for (int nf = 0; nf < 8; nf++) {
        int c = nf * 8 + lc2;
        *(float2*)&out[ob + (size_t)r0 * 1024 + c] =
            make_float2(of[nf][0] * inv0, of[nf][1] * inv0);
        *(float2*)&out[ob + (size_t)(r0 + 8) * 1024 + c] =
            make_float2(of[nf][2] * inv1, of[nf][3] * inv1);
    }
}

// ---------------------------------------------------------------------------
extern "C" void kernel_launch(void* const* d_in, const int* in_sizes, int n_in,
                              void* d_out, int out_size)
{
    const float* x          = (const float*)d_in[0];
    const float* pos_embed  = (const float*)d_in[1];
    const float* W_pos_kq   = (const float*)d_in[2];
    const float* W_tok_kqv  = (const float*)d_in[3];
    const float* bias_table = (const float*)d_in[4];
    float* out = (float*)d_out;

    float* biasd;
    __half *xh, *peh, *wth, *wtl, *wph, *wpl;
    __half *qh, *kh, *vh;
    cudaGetSymbolAddress((void**)&biasd, g_bias);
    cudaGetSymbolAddress((void**)&xh, g_xh);
    cudaGetSymbolAddress((void**)&peh, g_peh);
    cudaGetSymbolAddress((void**)&wth, g_wth); cudaGetSymbolAddress((void**)&wtl, g_wtl);
    cudaGetSymbolAddress((void**)&wph, g_wph); cudaGetSymbolAddress((void**)&wpl, g_wpl);
    cudaGetSymbolAddress((void**)&qh, g_qh);
    cudaGetSymbolAddress((void**)&kh, g_kh);
    cudaGetSymbolAddress((void**)&vh, g_vh);

    cudaFuncSetAttribute(attn_kernel,
                         cudaFuncAttributeMaxDynamicSharedMemorySize, ATT_SMEM);
    cudaFuncSetAttribute(hgemm2,
                         cudaFuncAttributeMaxDynamicSharedMemorySize, HG_SMEM);

    pack_all_h<<<(N4X + N4P + NB + 255) / 256, 256>>>(x, pos_embed, bias_table);
    pack_splitT_all<<<dim3(160, 32), dim3(32, 8)>>>(W_tok_kqv, W_pos_kq);
    hgemm2<<<1024, 256, HG_SMEM>>>(xh, wth, wtl, peh, wph, wpl);
    attn_kernel<<<dim3(16, 32), 256, ATT_SMEM>>>(qh, kh, vh, biasd, out);
}